// round 1
// baseline (speedup 1.0000x reference)
#include <cuda_runtime.h>
#include <math.h>

#define LL   2048
#define DD   2048
#define HH   16
#define DKK  1024
#define DVV  2048
#define HDKK 64
#define HDVV 128

// ---------------- scratch (device globals; no allocation allowed) ----------
__device__ float g_xc[LL*DD];    // conv+silu output
__device__ float g_q [LL*DKK];   // silu(xc@Wq), then roped
__device__ float g_k [LL*DKK];   // xc@Wk, then roped
__device__ float g_v [LL*DVV];
__device__ float g_gt[LL*DVV];   // gate projection
__device__ float g_o [LL*DVV];   // attention output, (l, h*128+j) layout
__device__ float g_y [LL*DVV];   // silu(g)*LN(o)
__device__ float g_coef[HH*LL];  // score_max/count * HDK^-0.5
__device__ int   g_rsel[HH*LL];  // selected expert per (h,l)

__device__ __forceinline__ float silu_f(float z) { return z / (1.f + expf(-z)); }

// ---------------- stage 1: shifted conv + silu -----------------------------
__global__ void conv_silu_kernel(const float* __restrict__ x,
                                 const float* __restrict__ cw) {
    int idx = blockIdx.x * blockDim.x + threadIdx.x;  // over L*D
    if (idx >= LL*DD) return;
    int d = idx & (DD-1);
    int l = idx >> 11;
    float prev = (l == 0) ? 0.f : x[idx - DD];
    float z = prev * cw[2*d] + x[idx] * cw[2*d + 1];
    g_xc[idx] = silu_f(z);
}

// ---------------- SGEMM: C = A(MxK) @ B(KxN), row-major, optional silu -----
template<bool SILU>
__global__ void sgemm_kernel(const float* __restrict__ A,
                             const float* __restrict__ B,
                             float* __restrict__ C,
                             int M, int N, int K) {
    __shared__ float As[8][128];
    __shared__ float Bs[8][128];
    int tid = threadIdx.x;                  // 256 threads
    int bm = blockIdx.y * 128, bn = blockIdx.x * 128;
    int tx = tid & 15, ty = tid >> 4;       // 16x16 thread grid, 8x8 per thread

    float acc[8][8];
    #pragma unroll
    for (int i = 0; i < 8; i++)
        #pragma unroll
        for (int j = 0; j < 8; j++) acc[i][j] = 0.f;

    int a_row = tid >> 1;                   // 0..127
    int a_col = (tid & 1) * 4;              // 0 or 4
    int b_row = tid >> 5;                   // 0..7
    int b_col = (tid & 31) * 4;             // 0..124

    const float* Ab = A + (size_t)bm * K;
    const float* Bb = B + bn;

    for (int k0 = 0; k0 < K; k0 += 8) {
        float4 av = *(const float4*)(Ab + (size_t)a_row * K + k0 + a_col);
        As[a_col + 0][a_row] = av.x;
        As[a_col + 1][a_row] = av.y;
        As[a_col + 2][a_row] = av.z;
        As[a_col + 3][a_row] = av.w;
        float4 bv = *(const float4*)(Bb + (size_t)(k0 + b_row) * N + b_col);
        *(float4*)&Bs[b_row][b_col] = bv;
        __syncthreads();
        #pragma unroll
        for (int kk = 0; kk < 8; kk++) {
            float ar[8], br[8];
            #pragma unroll
            for (int i = 0; i < 8; i++) ar[i] = As[kk][ty * 8 + i];
            #pragma unroll
            for (int j = 0; j < 8; j++) br[j] = Bs[kk][tx * 8 + j];
            #pragma unroll
            for (int i = 0; i < 8; i++)
                #pragma unroll
                for (int j = 0; j < 8; j++)
                    acc[i][j] += ar[i] * br[j];
        }
        __syncthreads();
    }

    #pragma unroll
    for (int i = 0; i < 8; i++) {
        int r = bm + ty * 8 + i;
        #pragma unroll
        for (int j = 0; j < 8; j++) {
            int c = bn + tx * 8 + j;
            float v = acc[i][j];
            if (SILU) v = silu_f(v);
            C[(size_t)r * N + c] = v;
        }
    }
}

// ---------------- stage 3: RoPE on q and k (in place) ----------------------
__global__ void rope_kernel() {
    int idx = blockIdx.x * blockDim.x + threadIdx.x;   // L*H*32
    if (idx >= LL * HH * 32) return;
    int i  = idx & 31;
    int lh = idx >> 5;
    int h  = lh & (HH-1);
    int l  = lh >> 4;
    // inv_freq[i] = BASE^(-(2i)/HDK) = 10000^(-i/32)
    float invf = powf(10000.f, -(float)i / 32.f);
    float ang = (float)l * invf;
    float c = cosf(ang), s = sinf(ang);
    int base = l * DKK + h * HDKK;
    float q1 = g_q[base + i], q2 = g_q[base + 32 + i];
    g_q[base + i]      = q1 * c - q2 * s;
    g_q[base + 32 + i] = q2 * c + q1 * s;
    float k1 = g_k[base + i], k2 = g_k[base + 32 + i];
    g_k[base + i]      = k1 * c - k2 * s;
    g_k[base + 32 + i] = k2 * c + k1 * s;
}

// ---------------- stage 4: router + sequential count scan ------------------
__global__ void router_kernel(const float* __restrict__ rw) {
    int h = blockIdx.x;                    // 16 blocks, 256 threads
    __shared__ float s_score[LL];
    __shared__ int   s_sel[LL];
    for (int l = threadIdx.x; l < LL; l += blockDim.x) {
        const float* vrow = g_v + (size_t)l * DVV + h * HDVV;
        float z0 = 0.f, z1 = 0.f;
        #pragma unroll 4
        for (int d = 0; d < HDVV; d++) {
            float vv = vrow[d];
            z0 += vv * rw[(h * HDVV + d) * 2 + 0];
            z1 += vv * rw[(h * HDVV + d) * 2 + 1];
        }
        int sel = (z1 > z0) ? 1 : 0;
        float m = fmaxf(z0, z1);
        float e0 = expf(z0 - m), e1 = expf(z1 - m);
        s_sel[l]   = sel;
        s_score[l] = ((sel == 0) ? e0 : e1) / (e0 + e1);
    }
    __syncthreads();
    if (threadIdx.x == 0) {
        int c0 = 0, c1 = 0;
        const float scale = 0.125f;   // HDK^{-1/2}
        for (int l = 0; l < LL; l++) {
            int sel = s_sel[l];
            int cnt;
            if (sel == 0) { c0++; cnt = c0; } else { c1++; cnt = c1; }
            g_rsel[h * LL + l] = sel;
            g_coef[h * LL + l] = s_score[l] / (float)cnt * scale;
        }
    }
}

// ---------------- stage 5: attention (no softmax, expert-gated) ------------
// grid (L/64, H), 256 threads, dynamic smem
#define QS_STRIDE 68
#define ATTN_SMEM_FLOATS (3*64*QS_STRIDE + 64*128 + 64 + 2*64)
#define ATTN_SMEM_BYTES  (ATTN_SMEM_FLOATS * 4)

__global__ void attn_kernel() {
    extern __shared__ float sm[];
    float* Qs     = sm;                       // [64][68]
    float* Ks     = Qs + 64 * QS_STRIDE;      // [64][68]
    float* Ss     = Ks + 64 * QS_STRIDE;      // [64][68]
    float* Vs     = Ss + 64 * QS_STRIDE;      // [64][128]
    float* coef_r = Vs + 64 * 128;            // [64]
    int*   rsel_r = (int*)(coef_r + 64);      // [64]
    int*   rsel_c = rsel_r + 64;              // [64]

    int h  = blockIdx.y;
    int l0 = blockIdx.x * 64;
    int tid = threadIdx.x;

    // load Q tile + row metadata
    for (int t = tid; t < 64 * 64; t += 256) {
        int i = t >> 6, j = t & 63;
        Qs[i * QS_STRIDE + j] = g_q[(size_t)(l0 + i) * DKK + h * HDKK + j];
    }
    if (tid < 64) {
        rsel_r[tid] = g_rsel[h * LL + l0 + tid];
        coef_r[tid] = g_coef[h * LL + l0 + tid];
    }

    float Oacc[32];
    #pragma unroll
    for (int i = 0; i < 32; i++) Oacc[i] = 0.f;
    int oty = tid >> 5;       // 0..7 (warp id)
    int otx = tid & 31;       // lane

    int sty = tid >> 4, stx = tid & 15;

    for (int m0 = 0; m0 <= l0; m0 += 64) {
        __syncthreads();
        for (int t = tid; t < 64 * 64; t += 256) {
            int i = t >> 6, j = t & 63;
            Ks[i * QS_STRIDE + j] = g_k[(size_t)(m0 + i) * DKK + h * HDKK + j];
        }
        for (int t = tid; t < 64 * 128; t += 256) {
            int i = t >> 7, j = t & 127;
            Vs[i * 128 + j] = g_v[(size_t)(m0 + i) * DVV + h * HDVV + j];
        }
        if (tid < 64) rsel_c[tid] = g_rsel[h * LL + m0 + tid];
        __syncthreads();

        // S tile: 64x64, each thread 4 rows x 4 cols
        #pragma unroll
        for (int ii = 0; ii < 4; ii++) {
            int i  = sty + ii * 16;
            int gl = l0 + i;
            const float4* q4 = (const float4*)(Qs + i * QS_STRIDE);
            #pragma unroll
            for (int jj = 0; jj < 4; jj++) {
                int j  = stx * 4 + jj;
                int gm = m0 + j;
                float s = 0.f;
                if (gm <= gl && rsel_c[j] == rsel_r[i]) {
                    const float4* k4 = (const float4*)(Ks + j * QS_STRIDE);
                    float acc = 0.f;
                    #pragma unroll
                    for (int kk = 0; kk < 16; kk++) {
                        float4 a = q4[kk], b = k4[kk];
                        acc += a.x*b.x + a.y*b.y + a.z*b.z + a.w*b.w;
                    }
                    s = acc * coef_r[i];
                }
                Ss[i * QS_STRIDE + j] = s;
            }
        }
        __syncthreads();

        // O += S @ V : thread owns rows oty*8..+7, cols otx*4..+3
        #pragma unroll
        for (int kk = 0; kk < 64; kk++) {
            float4 vv = *(const float4*)(Vs + kk * 128 + otx * 4);
            #pragma unroll
            for (int i = 0; i < 8; i++) {
                float sv = Ss[(oty * 8 + i) * QS_STRIDE + kk];
                Oacc[i * 4 + 0] += sv * vv.x;
                Oacc[i * 4 + 1] += sv * vv.y;
                Oacc[i * 4 + 2] += sv * vv.z;
                Oacc[i * 4 + 3] += sv * vv.w;
            }
        }
    }

    // store O in (l, h*128+j) layout
    #pragma unroll
    for (int i = 0; i < 8; i++) {
        int gl = l0 + oty * 8 + i;
        float4 o4 = make_float4(Oacc[i*4+0], Oacc[i*4+1], Oacc[i*4+2], Oacc[i*4+3]);
        *(float4*)(g_o + (size_t)gl * DVV + h * HDVV + otx * 4) = o4;
    }
}

// ---------------- stage 6: LayerNorm(128) * silu(gate) ---------------------
__global__ void ln_gate_kernel() {
    int h = blockIdx.x;
    int l = blockIdx.y;
    int j = threadIdx.x;    // 128
    size_t base = (size_t)l * DVV + h * HDVV;
    float o = g_o[base + j];
    float sum = o, sumsq = o * o;
    #pragma unroll
    for (int off = 16; off; off >>= 1) {
        sum   += __shfl_down_sync(0xffffffffu, sum,   off);
        sumsq += __shfl_down_sync(0xffffffffu, sumsq, off);
    }
    __shared__ float s1[4], s2[4];
    if ((j & 31) == 0) { s1[j >> 5] = sum; s2[j >> 5] = sumsq; }
    __syncthreads();
    float tot   = s1[0] + s1[1] + s1[2] + s1[3];
    float totsq = s2[0] + s2[1] + s2[2] + s2[3];
    float mu  = tot * (1.f / 128.f);
    float var = totsq * (1.f / 128.f) - mu * mu;
    float inv = rsqrtf(var + 1e-5f);
    float gt  = g_gt[base + j];
    g_y[base + j] = silu_f(gt) * (o - mu) * inv;
}

// ---------------- launch ----------------------------------------------------
extern "C" void kernel_launch(void* const* d_in, const int* in_sizes, int n_in,
                              void* d_out, int out_size) {
    const float* x    = (const float*)d_in[0];
    const float* cw   = (const float*)d_in[1];
    const float* Wq   = (const float*)d_in[2];
    const float* Wk   = (const float*)d_in[3];
    const float* Wv   = (const float*)d_in[4];
    const float* Wg   = (const float*)d_in[5];
    const float* rw   = (const float*)d_in[6];
    const float* Wout = (const float*)d_in[7];
    float* out = (float*)d_out;

    float *p_xc, *p_q, *p_k, *p_v, *p_gt, *p_y;
    cudaGetSymbolAddress((void**)&p_xc, g_xc);
    cudaGetSymbolAddress((void**)&p_q,  g_q);
    cudaGetSymbolAddress((void**)&p_k,  g_k);
    cudaGetSymbolAddress((void**)&p_v,  g_v);
    cudaGetSymbolAddress((void**)&p_gt, g_gt);
    cudaGetSymbolAddress((void**)&p_y,  g_y);

    cudaFuncSetAttribute(attn_kernel,
                         cudaFuncAttributeMaxDynamicSharedMemorySize,
                         ATTN_SMEM_BYTES);

    conv_silu_kernel<<<(LL*DD)/256, 256>>>(x, cw);

    sgemm_kernel<true ><<<dim3(DKK/128, LL/128), 256>>>(p_xc, Wq, p_q,  LL, DKK, DD);
    sgemm_kernel<false><<<dim3(DKK/128, LL/128), 256>>>(p_xc, Wk, p_k,  LL, DKK, DD);
    sgemm_kernel<false><<<dim3(DVV/128, LL/128), 256>>>(p_xc, Wv, p_v,  LL, DVV, DD);
    sgemm_kernel<false><<<dim3(DVV/128, LL/128), 256>>>(p_xc, Wg, p_gt, LL, DVV, DD);

    rope_kernel<<<(LL*HH*32)/256, 256>>>();
    router_kernel<<<HH, 256>>>(rw);

    attn_kernel<<<dim3(LL/64, HH), 256, ATTN_SMEM_BYTES>>>();

    ln_gate_kernel<<<dim3(HH, LL), 128>>>();

    sgemm_kernel<false><<<dim3(DD/128, LL/128), 256>>>(p_y, Wout, out, LL, DD, DD);
}

// round 3
// speedup vs baseline: 1.4366x; 1.4366x over previous
#include <cuda_runtime.h>
#include <math.h>

#define LL   2048
#define DD   2048
#define HH   16
#define DKK  1024
#define DVV  2048
#define HDKK 64
#define HDVV 128

// ---------------- scratch (device globals; no allocation allowed) ----------
__device__ float g_xc[LL*DD];    // conv+silu output
__device__ float g_q [LL*DKK];   // silu(xc@Wq), then roped
__device__ float g_k [LL*DKK];   // xc@Wk, then roped
__device__ float g_v [LL*DVV];
__device__ float g_gt[LL*DVV];   // gate projection
__device__ float g_o [LL*DVV];   // attention output, (l, h*128+j) layout
__device__ float g_y [LL*DVV];   // silu(g)*LN(o)
__device__ float g_coef[HH*LL];  // score_max/count * HDK^-0.5
__device__ int   g_rsel[HH*LL];  // selected expert per (h,l)

__device__ __forceinline__ float silu_f(float z) { return z / (1.f + expf(-z)); }

__device__ __forceinline__ unsigned f2tf(float f) {
    unsigned r;
    asm("cvt.rna.tf32.f32 %0, %1;" : "=r"(r) : "f"(f));
    return r;
}

__device__ __forceinline__ void mma8(float* c,
                                     unsigned a0, unsigned a1, unsigned a2, unsigned a3,
                                     unsigned b0, unsigned b1) {
    asm("mma.sync.aligned.m16n8k8.row.col.f32.tf32.tf32.f32 "
        "{%0,%1,%2,%3}, {%4,%5,%6,%7}, {%8,%9}, {%0,%1,%2,%3};"
        : "+f"(c[0]), "+f"(c[1]), "+f"(c[2]), "+f"(c[3])
        : "r"(a0), "r"(a1), "r"(a2), "r"(a3), "r"(b0), "r"(b1));
}

// ---------------- stage 1: shifted conv + silu -----------------------------
__global__ void conv_silu_kernel(const float* __restrict__ x,
                                 const float* __restrict__ cw) {
    int idx = blockIdx.x * blockDim.x + threadIdx.x;  // over L*D
    if (idx >= LL*DD) return;
    int d = idx & (DD-1);
    int l = idx >> 11;
    float prev = (l == 0) ? 0.f : x[idx - DD];
    float z = prev * cw[2*d] + x[idx] * cw[2*d + 1];
    g_xc[idx] = silu_f(z);
}

// ---------------- tensor-core GEMM: C = A(MxK) @ B(KxN), row-major ---------
// MODE 0: plain tf32 (one rounding).  MODE 1: 3xTF32 (fp32-grade accuracy).
// 256 threads, CTA tile 128x128, warp tile 64x32, K-tile 32.
#define AP 36
#define BP 132
#define SMEM_GEMM0 ((128*AP + 32*BP) * 4)
#define SMEM_GEMM1 (2 * SMEM_GEMM0)

template<int MODE, bool SILU>
__global__ void gemm_tc(const float* __restrict__ A,
                        const float* __restrict__ B,
                        float* __restrict__ C,
                        int M, int N, int K) {
    extern __shared__ float sm[];
    float* Ah = sm;                 // [128][AP]
    float* Bh = Ah + 128*AP;        // [32][BP]
    float* Al = Bh + 32*BP;         // MODE1 only
    float* Bl = Al + 128*AP;

    int tid = threadIdx.x, lane = tid & 31, warp = tid >> 5;
    int bm = blockIdx.y * 128, bn = blockIdx.x * 128;
    int wm = (warp >> 2) * 64, wn = (warp & 3) * 32;
    int g = lane >> 2, t = lane & 3;

    float acc[4][4][4];
    #pragma unroll
    for (int i = 0; i < 4; i++)
        #pragma unroll
        for (int j = 0; j < 4; j++)
            #pragma unroll
            for (int r = 0; r < 4; r++) acc[i][j][r] = 0.f;

    // global-load index maps (4 float4 each for A and B tiles)
    int ar[4], ac[4], br[4], bc[4];
    #pragma unroll
    for (int i = 0; i < 4; i++) {
        int idx = tid + i * 256;
        ar[i] = idx >> 3;  ac[i] = (idx & 7) * 4;    // A tile: 128 rows x 32 k
        br[i] = idx >> 5;  bc[i] = (idx & 31) * 4;   // B tile: 32 k x 128 cols
    }

    const float* Abase = A + (size_t)bm * K;
    const float* Bbase = B + bn;

    float4 pa[4], pb[4];
    #pragma unroll
    for (int i = 0; i < 4; i++) {
        pa[i] = *(const float4*)(Abase + (size_t)ar[i] * K + ac[i]);
        pb[i] = *(const float4*)(Bbase + (size_t)br[i] * N + bc[i]);
    }

    int nk = K >> 5;
    for (int kt = 0; kt < nk; kt++) {
        // store current tile to smem (converted)
        #pragma unroll
        for (int i = 0; i < 4; i++) {
            float va[4] = {pa[i].x, pa[i].y, pa[i].z, pa[i].w};
            float vb[4] = {pb[i].x, pb[i].y, pb[i].z, pb[i].w};
            #pragma unroll
            for (int j = 0; j < 4; j++) {
                float ahi = __uint_as_float(f2tf(va[j]));
                float bhi = __uint_as_float(f2tf(vb[j]));
                Ah[ar[i]*AP + ac[i] + j] = ahi;
                Bh[br[i]*BP + bc[i] + j] = bhi;
                if (MODE == 1) {
                    Al[ar[i]*AP + ac[i] + j] = __uint_as_float(f2tf(va[j] - ahi));
                    Bl[br[i]*BP + bc[i] + j] = __uint_as_float(f2tf(vb[j] - bhi));
                }
            }
        }
        __syncthreads();

        if (kt + 1 < nk) {
            int k0 = (kt + 1) * 32;
            #pragma unroll
            for (int i = 0; i < 4; i++) {
                pa[i] = *(const float4*)(Abase + (size_t)ar[i] * K + k0 + ac[i]);
                pb[i] = *(const float4*)(Bbase + (size_t)(k0 + br[i]) * N + bc[i]);
            }
        }

        #pragma unroll
        for (int ko = 0; ko < 32; ko += 8) {
            unsigned af[4][4], bf[4][2];
            #pragma unroll
            for (int fm = 0; fm < 4; fm++) {
                int r0 = wm + fm * 16 + g;
                af[fm][0] = __float_as_uint(Ah[ r0      * AP + ko + t]);
                af[fm][1] = __float_as_uint(Ah[(r0 + 8) * AP + ko + t]);
                af[fm][2] = __float_as_uint(Ah[ r0      * AP + ko + t + 4]);
                af[fm][3] = __float_as_uint(Ah[(r0 + 8) * AP + ko + t + 4]);
            }
            #pragma unroll
            for (int fn = 0; fn < 4; fn++) {
                int c0 = wn + fn * 8 + g;
                bf[fn][0] = __float_as_uint(Bh[(ko + t    ) * BP + c0]);
                bf[fn][1] = __float_as_uint(Bh[(ko + t + 4) * BP + c0]);
            }
            #pragma unroll
            for (int fm = 0; fm < 4; fm++)
                #pragma unroll
                for (int fn = 0; fn < 4; fn++)
                    mma8(acc[fm][fn], af[fm][0], af[fm][1], af[fm][2], af[fm][3],
                         bf[fn][0], bf[fn][1]);

            if (MODE == 1) {
                unsigned al[4][4], bl[4][2];
                #pragma unroll
                for (int fm = 0; fm < 4; fm++) {
                    int r0 = wm + fm * 16 + g;
                    al[fm][0] = __float_as_uint(Al[ r0      * AP + ko + t]);
                    al[fm][1] = __float_as_uint(Al[(r0 + 8) * AP + ko + t]);
                    al[fm][2] = __float_as_uint(Al[ r0      * AP + ko + t + 4]);
                    al[fm][3] = __float_as_uint(Al[(r0 + 8) * AP + ko + t + 4]);
                }
                #pragma unroll
                for (int fn = 0; fn < 4; fn++) {
                    int c0 = wn + fn * 8 + g;
                    bl[fn][0] = __float_as_uint(Bl[(ko + t    ) * BP + c0]);
                    bl[fn][1] = __float_as_uint(Bl[(ko + t + 4) * BP + c0]);
                }
                #pragma unroll
                for (int fm = 0; fm < 4; fm++)
                    #pragma unroll
                    for (int fn = 0; fn < 4; fn++) {
                        mma8(acc[fm][fn], af[fm][0], af[fm][1], af[fm][2], af[fm][3],
                             bl[fn][0], bl[fn][1]);
                        mma8(acc[fm][fn], al[fm][0], al[fm][1], al[fm][2], al[fm][3],
                             bf[fn][0], bf[fn][1]);
                    }
            }
        }
        __syncthreads();
    }

    // epilogue
    #pragma unroll
    for (int fm = 0; fm < 4; fm++) {
        int r0 = bm + wm + fm * 16 + g;
        #pragma unroll
        for (int fn = 0; fn < 4; fn++) {
            int c0 = bn + wn + fn * 8 + 2 * t;
            float v0 = acc[fm][fn][0], v1 = acc[fm][fn][1];
            float v2 = acc[fm][fn][2], v3 = acc[fm][fn][3];
            if (SILU) { v0 = silu_f(v0); v1 = silu_f(v1); v2 = silu_f(v2); v3 = silu_f(v3); }
            *(float2*)(C + (size_t)r0 * N + c0)       = make_float2(v0, v1);
            *(float2*)(C + (size_t)(r0 + 8) * N + c0) = make_float2(v2, v3);
        }
    }
}

// ---------------- stage 3: RoPE on q and k (in place) ----------------------
__global__ void rope_kernel() {
    int idx = blockIdx.x * blockDim.x + threadIdx.x;   // L*H*32
    if (idx >= LL * HH * 32) return;
    int i  = idx & 31;
    int lh = idx >> 5;
    int h  = lh & (HH-1);
    int l  = lh >> 4;
    float invf = powf(10000.f, -(float)i / 32.f);
    float ang = (float)l * invf;
    float c = cosf(ang), s = sinf(ang);
    int base = l * DKK + h * HDKK;
    float q1 = g_q[base + i], q2 = g_q[base + 32 + i];
    g_q[base + i]      = q1 * c - q2 * s;
    g_q[base + 32 + i] = q2 * c + q1 * s;
    float k1 = g_k[base + i], k2 = g_k[base + 32 + i];
    g_k[base + i]      = k1 * c - k2 * s;
    g_k[base + 32 + i] = k2 * c + k1 * s;
}

// ---------------- stage 4: router + sequential count scan ------------------
__global__ void router_kernel(const float* __restrict__ rw) {
    int h = blockIdx.x;                    // 16 blocks, 256 threads
    __shared__ float s_score[LL];
    __shared__ int   s_sel[LL];
    for (int l = threadIdx.x; l < LL; l += blockDim.x) {
        const float* vrow = g_v + (size_t)l * DVV + h * HDVV;
        float z0 = 0.f, z1 = 0.f;
        #pragma unroll 4
        for (int d = 0; d < HDVV; d++) {
            float vv = vrow[d];
            z0 += vv * rw[(h * HDVV + d) * 2 + 0];
            z1 += vv * rw[(h * HDVV + d) * 2 + 1];
        }
        int sel = (z1 > z0) ? 1 : 0;
        float m = fmaxf(z0, z1);
        float e0 = expf(z0 - m), e1 = expf(z1 - m);
        s_sel[l]   = sel;
        s_score[l] = ((sel == 0) ? e0 : e1) / (e0 + e1);
    }
    __syncthreads();
    if (threadIdx.x == 0) {
        int c0 = 0, c1 = 0;
        const float scale = 0.125f;   // HDK^{-1/2}
        for (int l = 0; l < LL; l++) {
            int sel = s_sel[l];
            int cnt;
            if (sel == 0) { c0++; cnt = c0; } else { c1++; cnt = c1; }
            g_rsel[h * LL + l] = sel;
            g_coef[h * LL + l] = s_score[l] / (float)cnt * scale;
        }
    }
}

// ---------------- stage 5: attention (no softmax, expert-gated) ------------
#define QS_STRIDE 68
#define ATTN_SMEM_FLOATS (3*64*QS_STRIDE + 64*128 + 64 + 2*64)
#define ATTN_SMEM_BYTES  (ATTN_SMEM_FLOATS * 4)

__global__ void attn_kernel() {
    extern __shared__ float smf[];
    float* Qs     = smf;                      // [64][68]
    float* Ks     = Qs + 64 * QS_STRIDE;      // [64][68]
    float* Ss     = Ks + 64 * QS_STRIDE;      // [64][68]
    float* Vs     = Ss + 64 * QS_STRIDE;      // [64][128]
    float* coef_r = Vs + 64 * 128;            // [64]
    int*   rsel_r = (int*)(coef_r + 64);      // [64]
    int*   rsel_c = rsel_r + 64;              // [64]

    int h  = blockIdx.y;
    int l0 = blockIdx.x * 64;
    int tid = threadIdx.x;

    for (int t = tid; t < 64 * 64; t += 256) {
        int i = t >> 6, j = t & 63;
        Qs[i * QS_STRIDE + j] = g_q[(size_t)(l0 + i) * DKK + h * HDKK + j];
    }
    if (tid < 64) {
        rsel_r[tid] = g_rsel[h * LL + l0 + tid];
        coef_r[tid] = g_coef[h * LL + l0 + tid];
    }

    float Oacc[32];
    #pragma unroll
    for (int i = 0; i < 32; i++) Oacc[i] = 0.f;
    int oty = tid >> 5;       // 0..7 (warp id)
    int otx = tid & 31;       // lane

    int sty = tid >> 4, stx = tid & 15;

    for (int m0 = 0; m0 <= l0; m0 += 64) {
        __syncthreads();
        for (int t = tid; t < 64 * 64; t += 256) {
            int i = t >> 6, j = t & 63;
            Ks[i * QS_STRIDE + j] = g_k[(size_t)(m0 + i) * DKK + h * HDKK + j];
        }
        for (int t = tid; t < 64 * 128; t += 256) {
            int i = t >> 7, j = t & 127;
            Vs[i * 128 + j] = g_v[(size_t)(m0 + i) * DVV + h * HDVV + j];
        }
        if (tid < 64) rsel_c[tid] = g_rsel[h * LL + m0 + tid];
        __syncthreads();

        #pragma unroll
        for (int ii = 0; ii < 4; ii++) {
            int i  = sty + ii * 16;
            int gl = l0 + i;
            const float4* q4 = (const float4*)(Qs + i * QS_STRIDE);
            #pragma unroll
            for (int jj = 0; jj < 4; jj++) {
                int j  = stx * 4 + jj;
                int gm = m0 + j;
                float s = 0.f;
                if (gm <= gl && rsel_c[j] == rsel_r[i]) {
                    const float4* k4 = (const float4*)(Ks + j * QS_STRIDE);
                    float a2 = 0.f;
                    #pragma unroll
                    for (int kk = 0; kk < 16; kk++) {
                        float4 a = q4[kk], b = k4[kk];
                        a2 += a.x*b.x + a.y*b.y + a.z*b.z + a.w*b.w;
                    }
                    s = a2 * coef_r[i];
                }
                Ss[i * QS_STRIDE + j] = s;
            }
        }
        __syncthreads();

        #pragma unroll
        for (int kk = 0; kk < 64; kk++) {
            float4 vv = *(const float4*)(Vs + kk * 128 + otx * 4);
            #pragma unroll
            for (int i = 0; i < 8; i++) {
                float sv = Ss[(oty * 8 + i) * QS_STRIDE + kk];
                Oacc[i * 4 + 0] += sv * vv.x;
                Oacc[i * 4 + 1] += sv * vv.y;
                Oacc[i * 4 + 2] += sv * vv.z;
                Oacc[i * 4 + 3] += sv * vv.w;
            }
        }
    }

    #pragma unroll
    for (int i = 0; i < 8; i++) {
        int gl = l0 + oty * 8 + i;
        float4 o4 = make_float4(Oacc[i*4+0], Oacc[i*4+1], Oacc[i*4+2], Oacc[i*4+3]);
        *(float4*)(g_o + (size_t)gl * DVV + h * HDVV + otx * 4) = o4;
    }
}

// ---------------- stage 6: LayerNorm(128) * silu(gate) ---------------------
__global__ void ln_gate_kernel() {
    int h = blockIdx.x;
    int l = blockIdx.y;
    int j = threadIdx.x;    // 128
    size_t base = (size_t)l * DVV + h * HDVV;
    float o = g_o[base + j];
    float sum = o, sumsq = o * o;
    #pragma unroll
    for (int off = 16; off; off >>= 1) {
        sum   += __shfl_down_sync(0xffffffffu, sum,   off);
        sumsq += __shfl_down_sync(0xffffffffu, sumsq, off);
    }
    __shared__ float s1[4], s2[4];
    if ((j & 31) == 0) { s1[j >> 5] = sum; s2[j >> 5] = sumsq; }
    __syncthreads();
    float tot   = s1[0] + s1[1] + s1[2] + s1[3];
    float totsq = s2[0] + s2[1] + s2[2] + s2[3];
    float mu  = tot * (1.f / 128.f);
    float var = totsq * (1.f / 128.f) - mu * mu;
    float inv = rsqrtf(var + 1e-5f);
    float gt  = g_gt[base + j];
    g_y[base + j] = silu_f(gt) * (o - mu) * inv;
}

// ---------------- launch ----------------------------------------------------
extern "C" void kernel_launch(void* const* d_in, const int* in_sizes, int n_in,
                              void* d_out, int out_size) {
    const float* x    = (const float*)d_in[0];
    const float* cw   = (const float*)d_in[1];
    const float* Wq   = (const float*)d_in[2];
    const float* Wk   = (const float*)d_in[3];
    const float* Wv   = (const float*)d_in[4];
    const float* Wg   = (const float*)d_in[5];
    const float* rw   = (const float*)d_in[6];
    const float* Wout = (const float*)d_in[7];
    float* out = (float*)d_out;

    float *p_xc, *p_q, *p_k, *p_v, *p_gt, *p_y;
    cudaGetSymbolAddress((void**)&p_xc, g_xc);
    cudaGetSymbolAddress((void**)&p_q,  g_q);
    cudaGetSymbolAddress((void**)&p_k,  g_k);
    cudaGetSymbolAddress((void**)&p_v,  g_v);
    cudaGetSymbolAddress((void**)&p_gt, g_gt);
    cudaGetSymbolAddress((void**)&p_y,  g_y);

    cudaFuncSetAttribute(attn_kernel,
                         cudaFuncAttributeMaxDynamicSharedMemorySize,
                         ATTN_SMEM_BYTES);
    cudaFuncSetAttribute(gemm_tc<0, true>,
                         cudaFuncAttributeMaxDynamicSharedMemorySize, SMEM_GEMM0);
    cudaFuncSetAttribute(gemm_tc<0, false>,
                         cudaFuncAttributeMaxDynamicSharedMemorySize, SMEM_GEMM0);
    cudaFuncSetAttribute(gemm_tc<1, false>,
                         cudaFuncAttributeMaxDynamicSharedMemorySize, SMEM_GEMM1);

    conv_silu_kernel<<<(LL*DD)/256, 256>>>(x, cw);

    gemm_tc<0, true ><<<dim3(DKK/128, LL/128), 256, SMEM_GEMM0>>>(p_xc, Wq, p_q,  LL, DKK, DD);
    gemm_tc<0, false><<<dim3(DKK/128, LL/128), 256, SMEM_GEMM0>>>(p_xc, Wk, p_k,  LL, DKK, DD);
    gemm_tc<1, false><<<dim3(DVV/128, LL/128), 256, SMEM_GEMM1>>>(p_xc, Wv, p_v,  LL, DVV, DD);
    gemm_tc<0, false><<<dim3(DVV/128, LL/128), 256, SMEM_GEMM0>>>(p_xc, Wg, p_gt, LL, DVV, DD);

    rope_kernel<<<(LL*HH*32)/256, 256>>>();
    router_kernel<<<HH, 256>>>(rw);

    attn_kernel<<<dim3(LL/64, HH), 256, ATTN_SMEM_BYTES>>>();

    ln_gate_kernel<<<dim3(HH, LL), 128>>>();

    gemm_tc<0, false><<<dim3(DD/128, LL/128), 256, SMEM_GEMM0>>>(p_y, Wout, out, LL, DD, DD);
}

// round 4
// speedup vs baseline: 2.0997x; 1.4616x over previous
#include <cuda_runtime.h>
#include <math.h>

#define LL   2048
#define DD   2048
#define HH   16
#define DKK  1024
#define DVV  2048
#define HDKK 64
#define HDVV 128

// ---------------- scratch (device globals; no allocation allowed) ----------
__device__ float g_xc[LL*DD];    // conv+silu output
__device__ float g_q [LL*DKK];   // silu(xc@Wq), then roped
__device__ float g_k [LL*DKK];   // xc@Wk, then roped
__device__ float g_v [LL*DVV];
__device__ float g_gt[LL*DVV];   // gate projection
__device__ float g_o [LL*DVV];   // attention output, (l, h*128+j) layout
__device__ float g_y [LL*DVV];   // silu(g)*LN(o)
__device__ float g_coef[HH*LL];  // score_max/count * HDK^-0.5
__device__ int   g_rsel[HH*LL];  // selected expert per (h,l)

__device__ __forceinline__ float silu_f(float z) { return z / (1.f + expf(-z)); }

__device__ __forceinline__ unsigned f2tf(float f) {
    unsigned r;
    asm("cvt.rna.tf32.f32 %0, %1;" : "=r"(r) : "f"(f));
    return r;
}

__device__ __forceinline__ void split_tf(float v, float& hi, float& lo) {
    hi = __uint_as_float(f2tf(v));
    lo = __uint_as_float(f2tf(v - hi));
}

__device__ __forceinline__ void mma8(float* c,
                                     unsigned a0, unsigned a1, unsigned a2, unsigned a3,
                                     unsigned b0, unsigned b1) {
    asm("mma.sync.aligned.m16n8k8.row.col.f32.tf32.tf32.f32 "
        "{%0,%1,%2,%3}, {%4,%5,%6,%7}, {%8,%9}, {%0,%1,%2,%3};"
        : "+f"(c[0]), "+f"(c[1]), "+f"(c[2]), "+f"(c[3])
        : "r"(a0), "r"(a1), "r"(a2), "r"(a3), "r"(b0), "r"(b1));
}

// ---------------- stage 1: shifted conv + silu -----------------------------
__global__ void conv_silu_kernel(const float* __restrict__ x,
                                 const float* __restrict__ cw) {
    int idx = blockIdx.x * blockDim.x + threadIdx.x;  // over L*D
    if (idx >= LL*DD) return;
    int d = idx & (DD-1);
    int l = idx >> 11;
    float prev = (l == 0) ? 0.f : x[idx - DD];
    float z = prev * cw[2*d] + x[idx] * cw[2*d + 1];
    g_xc[idx] = silu_f(z);
}

// ---------------- tensor-core GEMM: C = A(MxK) @ B(KxN), row-major ---------
// MODE 0: plain tf32.  MODE 1: 3xTF32 (fp32-grade accuracy).
#define AP 36
#define BP 132
#define SMEM_GEMM0 ((128*AP + 32*BP) * 4)
#define SMEM_GEMM1 (2 * SMEM_GEMM0)

template<int MODE, bool SILU>
__global__ void gemm_tc(const float* __restrict__ A,
                        const float* __restrict__ B,
                        float* __restrict__ C,
                        int M, int N, int K) {
    extern __shared__ float sm[];
    float* Ah = sm;                 // [128][AP]
    float* Bh = Ah + 128*AP;        // [32][BP]
    float* Al = Bh + 32*BP;         // MODE1 only
    float* Bl = Al + 128*AP;

    int tid = threadIdx.x, lane = tid & 31, warp = tid >> 5;
    int bm = blockIdx.y * 128, bn = blockIdx.x * 128;
    int wm = (warp >> 2) * 64, wn = (warp & 3) * 32;
    int g = lane >> 2, t = lane & 3;

    float acc[4][4][4];
    #pragma unroll
    for (int i = 0; i < 4; i++)
        #pragma unroll
        for (int j = 0; j < 4; j++)
            #pragma unroll
            for (int r = 0; r < 4; r++) acc[i][j][r] = 0.f;

    int ar[4], ac[4], br[4], bc[4];
    #pragma unroll
    for (int i = 0; i < 4; i++) {
        int idx = tid + i * 256;
        ar[i] = idx >> 3;  ac[i] = (idx & 7) * 4;
        br[i] = idx >> 5;  bc[i] = (idx & 31) * 4;
    }

    const float* Abase = A + (size_t)bm * K;
    const float* Bbase = B + bn;

    float4 pa[4], pb[4];
    #pragma unroll
    for (int i = 0; i < 4; i++) {
        pa[i] = *(const float4*)(Abase + (size_t)ar[i] * K + ac[i]);
        pb[i] = *(const float4*)(Bbase + (size_t)br[i] * N + bc[i]);
    }

    int nk = K >> 5;
    for (int kt = 0; kt < nk; kt++) {
        #pragma unroll
        for (int i = 0; i < 4; i++) {
            float va[4] = {pa[i].x, pa[i].y, pa[i].z, pa[i].w};
            float vb[4] = {pb[i].x, pb[i].y, pb[i].z, pb[i].w};
            #pragma unroll
            for (int j = 0; j < 4; j++) {
                float ahi = __uint_as_float(f2tf(va[j]));
                float bhi = __uint_as_float(f2tf(vb[j]));
                Ah[ar[i]*AP + ac[i] + j] = ahi;
                Bh[br[i]*BP + bc[i] + j] = bhi;
                if (MODE == 1) {
                    Al[ar[i]*AP + ac[i] + j] = __uint_as_float(f2tf(va[j] - ahi));
                    Bl[br[i]*BP + bc[i] + j] = __uint_as_float(f2tf(vb[j] - bhi));
                }
            }
        }
        __syncthreads();

        if (kt + 1 < nk) {
            int k0 = (kt + 1) * 32;
            #pragma unroll
            for (int i = 0; i < 4; i++) {
                pa[i] = *(const float4*)(Abase + (size_t)ar[i] * K + k0 + ac[i]);
                pb[i] = *(const float4*)(Bbase + (size_t)(k0 + br[i]) * N + bc[i]);
            }
        }

        #pragma unroll
        for (int ko = 0; ko < 32; ko += 8) {
            unsigned af[4][4], bf[4][2];
            #pragma unroll
            for (int fm = 0; fm < 4; fm++) {
                int r0 = wm + fm * 16 + g;
                af[fm][0] = __float_as_uint(Ah[ r0      * AP + ko + t]);
                af[fm][1] = __float_as_uint(Ah[(r0 + 8) * AP + ko + t]);
                af[fm][2] = __float_as_uint(Ah[ r0      * AP + ko + t + 4]);
                af[fm][3] = __float_as_uint(Ah[(r0 + 8) * AP + ko + t + 4]);
            }
            #pragma unroll
            for (int fn = 0; fn < 4; fn++) {
                int c0 = wn + fn * 8 + g;
                bf[fn][0] = __float_as_uint(Bh[(ko + t    ) * BP + c0]);
                bf[fn][1] = __float_as_uint(Bh[(ko + t + 4) * BP + c0]);
            }
            #pragma unroll
            for (int fm = 0; fm < 4; fm++)
                #pragma unroll
                for (int fn = 0; fn < 4; fn++)
                    mma8(acc[fm][fn], af[fm][0], af[fm][1], af[fm][2], af[fm][3],
                         bf[fn][0], bf[fn][1]);

            if (MODE == 1) {
                unsigned al[4][4], bl[4][2];
                #pragma unroll
                for (int fm = 0; fm < 4; fm++) {
                    int r0 = wm + fm * 16 + g;
                    al[fm][0] = __float_as_uint(Al[ r0      * AP + ko + t]);
                    al[fm][1] = __float_as_uint(Al[(r0 + 8) * AP + ko + t]);
                    al[fm][2] = __float_as_uint(Al[ r0      * AP + ko + t + 4]);
                    al[fm][3] = __float_as_uint(Al[(r0 + 8) * AP + ko + t + 4]);
                }
                #pragma unroll
                for (int fn = 0; fn < 4; fn++) {
                    int c0 = wn + fn * 8 + g;
                    bl[fn][0] = __float_as_uint(Bl[(ko + t    ) * BP + c0]);
                    bl[fn][1] = __float_as_uint(Bl[(ko + t + 4) * BP + c0]);
                }
                #pragma unroll
                for (int fm = 0; fm < 4; fm++)
                    #pragma unroll
                    for (int fn = 0; fn < 4; fn++) {
                        mma8(acc[fm][fn], af[fm][0], af[fm][1], af[fm][2], af[fm][3],
                             bl[fn][0], bl[fn][1]);
                        mma8(acc[fm][fn], al[fm][0], al[fm][1], al[fm][2], al[fm][3],
                             bf[fn][0], bf[fn][1]);
                    }
            }
        }
        __syncthreads();
    }

    #pragma unroll
    for (int fm = 0; fm < 4; fm++) {
        int r0 = bm + wm + fm * 16 + g;
        #pragma unroll
        for (int fn = 0; fn < 4; fn++) {
            int c0 = bn + wn + fn * 8 + 2 * t;
            float v0 = acc[fm][fn][0], v1 = acc[fm][fn][1];
            float v2 = acc[fm][fn][2], v3 = acc[fm][fn][3];
            if (SILU) { v0 = silu_f(v0); v1 = silu_f(v1); v2 = silu_f(v2); v3 = silu_f(v3); }
            *(float2*)(C + (size_t)r0 * N + c0)       = make_float2(v0, v1);
            *(float2*)(C + (size_t)(r0 + 8) * N + c0) = make_float2(v2, v3);
        }
    }
}

// ---------------- stage 3: RoPE on q and k (in place) ----------------------
__global__ void rope_kernel() {
    int idx = blockIdx.x * blockDim.x + threadIdx.x;   // L*H*32
    if (idx >= LL * HH * 32) return;
    int i  = idx & 31;
    int lh = idx >> 5;
    int h  = lh & (HH-1);
    int l  = lh >> 4;
    float invf = powf(10000.f, -(float)i / 32.f);
    float ang = (float)l * invf;
    float c = cosf(ang), s = sinf(ang);
    int base = l * DKK + h * HDKK;
    float q1 = g_q[base + i], q2 = g_q[base + 32 + i];
    g_q[base + i]      = q1 * c - q2 * s;
    g_q[base + 32 + i] = q2 * c + q1 * s;
    float k1 = g_k[base + i], k2 = g_k[base + 32 + i];
    g_k[base + i]      = k1 * c - k2 * s;
    g_k[base + 32 + i] = k2 * c + k1 * s;
}

// ---------------- stage 4: router + sequential count scan ------------------
__global__ void router_kernel(const float* __restrict__ rw) {
    int h = blockIdx.x;                    // 16 blocks, 256 threads
    __shared__ float s_score[LL];
    __shared__ int   s_sel[LL];
    for (int l = threadIdx.x; l < LL; l += blockDim.x) {
        const float* vrow = g_v + (size_t)l * DVV + h * HDVV;
        float z0 = 0.f, z1 = 0.f;
        #pragma unroll 4
        for (int d = 0; d < HDVV; d++) {
            float vv = vrow[d];
            z0 += vv * rw[(h * HDVV + d) * 2 + 0];
            z1 += vv * rw[(h * HDVV + d) * 2 + 1];
        }
        int sel = (z1 > z0) ? 1 : 0;
        float m = fmaxf(z0, z1);
        float e0 = expf(z0 - m), e1 = expf(z1 - m);
        s_sel[l]   = sel;
        s_score[l] = ((sel == 0) ? e0 : e1) / (e0 + e1);
    }
    __syncthreads();
    if (threadIdx.x == 0) {
        int c0 = 0, c1 = 0;
        const float scale = 0.125f;   // HDK^{-1/2}
        for (int l = 0; l < LL; l++) {
            int sel = s_sel[l];
            int cnt;
            if (sel == 0) { c0++; cnt = c0; } else { c1++; cnt = c1; }
            g_rsel[h * LL + l] = sel;
            g_coef[h * LL + l] = s_score[l] / (float)cnt * scale;
        }
    }
}

// ---------------- stage 5: tensor-core attention ---------------------------
// grid (32, 16) — heavy q-tiles first. 256 threads (8 warps).
// S = coef(l) * (q_l . k_m) * [expert match] * [causal], O = S @ V.
// All operands 3-term tf32 hi/lo split (error ~1e-5).
#define ST 68     // stride for Q/K/S tiles (64 cols + pad)
#define VT 136    // stride for V tile (128 cols + pad)
// float offsets in dynamic smem
#define OF_QH 0
#define OF_QL (OF_QH + 64*ST)
#define OF_KH (OF_QL + 64*ST)
#define OF_KL (OF_KH + 64*ST)
#define OF_SH (OF_KL + 64*ST)
#define OF_SL (OF_SH + 64*ST)
#define OF_VH (OF_SL + 64*ST)
#define OF_VL (OF_VH + 64*VT)
#define OF_CF (OF_VL + 64*VT)
#define OF_RR (OF_CF + 64)
#define OF_RC (OF_RR + 64)
#define ATTN2_FLOATS (OF_RC + 64)
#define ATTN2_BYTES  (ATTN2_FLOATS * 4)

__global__ __launch_bounds__(256, 1) void attn_tc() {
    extern __shared__ float smf[];
    float* Qh = smf + OF_QH;  float* Ql = smf + OF_QL;
    float* Kh = smf + OF_KH;  float* Kl = smf + OF_KL;
    float* Sh = smf + OF_SH;  float* Sl = smf + OF_SL;
    float* Vh = smf + OF_VH;  float* Vl = smf + OF_VL;
    float* coef_r = smf + OF_CF;
    int*   rsel_r = (int*)(smf + OF_RR);
    int*   rsel_c = (int*)(smf + OF_RC);

    int h   = blockIdx.y;
    int l0  = (gridDim.x - 1 - blockIdx.x) * 64;   // heavy tiles first
    int tid = threadIdx.x, lane = tid & 31, warp = tid >> 5;
    int g = lane >> 2, t = lane & 3;
    int wm  = (warp >> 1) * 16;       // S/O row base for this warp
    int wns = (warp & 1) * 32;        // S col base (QK)
    int wno = (warp & 1) * 64;        // O col base (SV)

    // load Q tile (split) + row metadata
    for (int i = tid; i < 64 * 64; i += 256) {
        int r = i >> 6, c = i & 63;
        float v = g_q[(size_t)(l0 + r) * DKK + h * HDKK + c];
        float hi, lo; split_tf(v, hi, lo);
        Qh[r * ST + c] = hi; Ql[r * ST + c] = lo;
    }
    if (tid < 64) {
        rsel_r[tid] = g_rsel[h * LL + l0 + tid];
        coef_r[tid] = g_coef[h * LL + l0 + tid];
    }

    float acc_o[8][4];
    #pragma unroll
    for (int fn = 0; fn < 8; fn++)
        #pragma unroll
        for (int r = 0; r < 4; r++) acc_o[fn][r] = 0.f;

    int ntiles = (l0 >> 6) + 1;
    for (int mt = 0; mt < ntiles; mt++) {
        int m0 = mt * 64;
        __syncthreads();   // previous iteration's reads of K/V/S done
        // load K tile (split)
        for (int i = tid; i < 64 * 64; i += 256) {
            int r = i >> 6, c = i & 63;
            float v = g_k[(size_t)(m0 + r) * DKK + h * HDKK + c];
            float hi, lo; split_tf(v, hi, lo);
            Kh[r * ST + c] = hi; Kl[r * ST + c] = lo;
        }
        // load V tile (split)
        for (int i = tid; i < 64 * 128; i += 256) {
            int r = i >> 7, c = i & 127;
            float v = g_v[(size_t)(m0 + r) * DVV + h * HDVV + c];
            float hi, lo; split_tf(v, hi, lo);
            Vh[r * VT + c] = hi; Vl[r * VT + c] = lo;
        }
        if (tid < 64) rsel_c[tid] = g_rsel[h * LL + m0 + tid];
        __syncthreads();

        // ---- QK^T: warp tile 16x32 ----
        float acc_s[4][4];
        #pragma unroll
        for (int fn = 0; fn < 4; fn++)
            #pragma unroll
            for (int r = 0; r < 4; r++) acc_s[fn][r] = 0.f;

        #pragma unroll
        for (int ko = 0; ko < 64; ko += 8) {
            int r0 = wm + g;
            unsigned ah[4], al[4];
            ah[0] = __float_as_uint(Qh[ r0      * ST + ko + t]);
            ah[1] = __float_as_uint(Qh[(r0 + 8) * ST + ko + t]);
            ah[2] = __float_as_uint(Qh[ r0      * ST + ko + t + 4]);
            ah[3] = __float_as_uint(Qh[(r0 + 8) * ST + ko + t + 4]);
            al[0] = __float_as_uint(Ql[ r0      * ST + ko + t]);
            al[1] = __float_as_uint(Ql[(r0 + 8) * ST + ko + t]);
            al[2] = __float_as_uint(Ql[ r0      * ST + ko + t + 4]);
            al[3] = __float_as_uint(Ql[(r0 + 8) * ST + ko + t + 4]);
            #pragma unroll
            for (int fn = 0; fn < 4; fn++) {
                int c0 = wns + fn * 8 + g;
                unsigned bh0 = __float_as_uint(Kh[c0 * ST + ko + t]);
                unsigned bh1 = __float_as_uint(Kh[c0 * ST + ko + t + 4]);
                unsigned bl0 = __float_as_uint(Kl[c0 * ST + ko + t]);
                unsigned bl1 = __float_as_uint(Kl[c0 * ST + ko + t + 4]);
                mma8(acc_s[fn], ah[0], ah[1], ah[2], ah[3], bh0, bh1);
                mma8(acc_s[fn], ah[0], ah[1], ah[2], ah[3], bl0, bl1);
                mma8(acc_s[fn], al[0], al[1], al[2], al[3], bh0, bh1);
            }
        }

        // ---- mask + coef, split-store S ----
        {
            int r0 = wm + g, r1 = r0 + 8;
            int gl0 = l0 + r0, gl1 = l0 + r1;
            int e0 = rsel_r[r0], e1 = rsel_r[r1];
            float cf0 = coef_r[r0], cf1 = coef_r[r1];
            #pragma unroll
            for (int fn = 0; fn < 4; fn++) {
                int c = wns + fn * 8 + 2 * t;
                int gm0 = m0 + c, gm1 = gm0 + 1;
                int ec0 = rsel_c[c], ec1 = rsel_c[c + 1];
                float s00 = (gm0 <= gl0 && ec0 == e0) ? acc_s[fn][0] * cf0 : 0.f;
                float s01 = (gm1 <= gl0 && ec1 == e0) ? acc_s[fn][1] * cf0 : 0.f;
                float s10 = (gm0 <= gl1 && ec0 == e1) ? acc_s[fn][2] * cf1 : 0.f;
                float s11 = (gm1 <= gl1 && ec1 == e1) ? acc_s[fn][3] * cf1 : 0.f;
                float h00, l00, h01, l01, h10, l10, h11, l11;
                split_tf(s00, h00, l00); split_tf(s01, h01, l01);
                split_tf(s10, h10, l10); split_tf(s11, h11, l11);
                *(float2*)&Sh[r0 * ST + c] = make_float2(h00, h01);
                *(float2*)&Sl[r0 * ST + c] = make_float2(l00, l01);
                *(float2*)&Sh[r1 * ST + c] = make_float2(h10, h11);
                *(float2*)&Sl[r1 * ST + c] = make_float2(l10, l11);
            }
        }
        __syncthreads();

        // ---- O += S @ V: warp tile 16x64 ----
        #pragma unroll
        for (int ko = 0; ko < 64; ko += 8) {
            int r0 = wm + g;
            unsigned ah[4], al[4];
            ah[0] = __float_as_uint(Sh[ r0      * ST + ko + t]);
            ah[1] = __float_as_uint(Sh[(r0 + 8) * ST + ko + t]);
            ah[2] = __float_as_uint(Sh[ r0      * ST + ko + t + 4]);
            ah[3] = __float_as_uint(Sh[(r0 + 8) * ST + ko + t + 4]);
            al[0] = __float_as_uint(Sl[ r0      * ST + ko + t]);
            al[1] = __float_as_uint(Sl[(r0 + 8) * ST + ko + t]);
            al[2] = __float_as_uint(Sl[ r0      * ST + ko + t + 4]);
            al[3] = __float_as_uint(Sl[(r0 + 8) * ST + ko + t + 4]);
            #pragma unroll
            for (int fn = 0; fn < 8; fn++) {
                int c0 = wno + fn * 8 + g;
                unsigned bh0 = __float_as_uint(Vh[(ko + t    ) * VT + c0]);
                unsigned bh1 = __float_as_uint(Vh[(ko + t + 4) * VT + c0]);
                unsigned bl0 = __float_as_uint(Vl[(ko + t    ) * VT + c0]);
                unsigned bl1 = __float_as_uint(Vl[(ko + t + 4) * VT + c0]);
                mma8(acc_o[fn], ah[0], ah[1], ah[2], ah[3], bh0, bh1);
                mma8(acc_o[fn], ah[0], ah[1], ah[2], ah[3], bl0, bl1);
                mma8(acc_o[fn], al[0], al[1], al[2], al[3], bh0, bh1);
            }
        }
    }

    // ---- store O ----
    int r0 = wm + g;
    #pragma unroll
    for (int fn = 0; fn < 8; fn++) {
        int c = wno + fn * 8 + 2 * t;
        *(float2*)(g_o + (size_t)(l0 + r0    ) * DVV + h * HDVV + c)
            = make_float2(acc_o[fn][0], acc_o[fn][1]);
        *(float2*)(g_o + (size_t)(l0 + r0 + 8) * DVV + h * HDVV + c)
            = make_float2(acc_o[fn][2], acc_o[fn][3]);
    }
}

// ---------------- stage 6: LayerNorm(128) * silu(gate) ---------------------
__global__ void ln_gate_kernel() {
    int h = blockIdx.x;
    int l = blockIdx.y;
    int j = threadIdx.x;    // 128
    size_t base = (size_t)l * DVV + h * HDVV;
    float o = g_o[base + j];
    float sum = o, sumsq = o * o;
    #pragma unroll
    for (int off = 16; off; off >>= 1) {
        sum   += __shfl_down_sync(0xffffffffu, sum,   off);
        sumsq += __shfl_down_sync(0xffffffffu, sumsq, off);
    }
    __shared__ float s1[4], s2[4];
    if ((j & 31) == 0) { s1[j >> 5] = sum; s2[j >> 5] = sumsq; }
    __syncthreads();
    float tot   = s1[0] + s1[1] + s1[2] + s1[3];
    float totsq = s2[0] + s2[1] + s2[2] + s2[3];
    float mu  = tot * (1.f / 128.f);
    float var = totsq * (1.f / 128.f) - mu * mu;
    float inv = rsqrtf(var + 1e-5f);
    float gt  = g_gt[base + j];
    g_y[base + j] = silu_f(gt) * (o - mu) * inv;
}

// ---------------- launch ----------------------------------------------------
extern "C" void kernel_launch(void* const* d_in, const int* in_sizes, int n_in,
                              void* d_out, int out_size) {
    const float* x    = (const float*)d_in[0];
    const float* cw   = (const float*)d_in[1];
    const float* Wq   = (const float*)d_in[2];
    const float* Wk   = (const float*)d_in[3];
    const float* Wv   = (const float*)d_in[4];
    const float* Wg   = (const float*)d_in[5];
    const float* rw   = (const float*)d_in[6];
    const float* Wout = (const float*)d_in[7];
    float* out = (float*)d_out;

    float *p_xc, *p_q, *p_k, *p_v, *p_gt, *p_y;
    cudaGetSymbolAddress((void**)&p_xc, g_xc);
    cudaGetSymbolAddress((void**)&p_q,  g_q);
    cudaGetSymbolAddress((void**)&p_k,  g_k);
    cudaGetSymbolAddress((void**)&p_v,  g_v);
    cudaGetSymbolAddress((void**)&p_gt, g_gt);
    cudaGetSymbolAddress((void**)&p_y,  g_y);

    cudaFuncSetAttribute(attn_tc,
                         cudaFuncAttributeMaxDynamicSharedMemorySize, ATTN2_BYTES);
    cudaFuncSetAttribute(gemm_tc<0, true>,
                         cudaFuncAttributeMaxDynamicSharedMemorySize, SMEM_GEMM0);
    cudaFuncSetAttribute(gemm_tc<0, false>,
                         cudaFuncAttributeMaxDynamicSharedMemorySize, SMEM_GEMM0);
    cudaFuncSetAttribute(gemm_tc<1, false>,
                         cudaFuncAttributeMaxDynamicSharedMemorySize, SMEM_GEMM1);

    conv_silu_kernel<<<(LL*DD)/256, 256>>>(x, cw);

    gemm_tc<0, true ><<<dim3(DKK/128, LL/128), 256, SMEM_GEMM0>>>(p_xc, Wq, p_q,  LL, DKK, DD);
    gemm_tc<0, false><<<dim3(DKK/128, LL/128), 256, SMEM_GEMM0>>>(p_xc, Wk, p_k,  LL, DKK, DD);
    gemm_tc<1, false><<<dim3(DVV/128, LL/128), 256, SMEM_GEMM1>>>(p_xc, Wv, p_v,  LL, DVV, DD);
    gemm_tc<0, false><<<dim3(DVV/128, LL/128), 256, SMEM_GEMM0>>>(p_xc, Wg, p_gt, LL, DVV, DD);

    rope_kernel<<<(LL*HH*32)/256, 256>>>();
    router_kernel<<<HH, 256>>>(rw);

    attn_tc<<<dim3(LL/64, HH), 256, ATTN2_BYTES>>>();

    ln_gate_kernel<<<dim3(HH, LL), 128>>>();

    gemm_tc<0, false><<<dim3(DD/128, LL/128), 256, SMEM_GEMM0>>>(p_y, Wout, out, LL, DD, DD);
}

// round 5
// speedup vs baseline: 2.1526x; 1.0252x over previous
#include <cuda_runtime.h>
#include <math.h>

#define LL   2048
#define DD   2048
#define HH   16
#define DKK  1024
#define DVV  2048
#define HDKK 64
#define HDVV 128
#define NCAT 6144              // q(1024) | k(1024) | v(2048) | g(2048)

// ---------------- scratch (device globals; no allocation allowed) ----------
__device__ float g_xc  [LL*DD];      // conv+silu output
__device__ float g_wcat[DD*NCAT];    // Wq|Wk|Wv|Wg concatenated
__device__ float g_qkvg[LL*NCAT];    // fused projection output
__device__ float g_w2  [DD*32];      // Wv @ router_w  (fp32 exact)
__device__ float g_rlog[LL*32];      // router logits  (fp32 exact)
__device__ float g_o   [LL*DVV];     // attention output
__device__ float g_y   [LL*DVV];     // silu(g)*LN(o)
__device__ float g_coef[HH*LL];      // score_max/count * HDK^-0.5
__device__ int   g_rsel[HH*LL];      // selected expert per (h,l)

__device__ __forceinline__ float silu_f(float z) { return z / (1.f + expf(-z)); }

__device__ __forceinline__ unsigned f2tf(float f) {
    unsigned r;
    asm("cvt.rna.tf32.f32 %0, %1;" : "=r"(r) : "f"(f));
    return r;
}

__device__ __forceinline__ void split_tf(float v, float& hi, float& lo) {
    hi = __uint_as_float(f2tf(v));
    lo = __uint_as_float(f2tf(v - hi));
}

__device__ __forceinline__ void mma8(float* c,
                                     unsigned a0, unsigned a1, unsigned a2, unsigned a3,
                                     unsigned b0, unsigned b1) {
    asm("mma.sync.aligned.m16n8k8.row.col.f32.tf32.tf32.f32 "
        "{%0,%1,%2,%3}, {%4,%5,%6,%7}, {%8,%9}, {%0,%1,%2,%3};"
        : "+f"(c[0]), "+f"(c[1]), "+f"(c[2]), "+f"(c[3])
        : "r"(a0), "r"(a1), "r"(a2), "r"(a3), "r"(b0), "r"(b1));
}

// ---------------- stage 1: shifted conv + silu -----------------------------
__global__ void conv_silu_kernel(const float* __restrict__ x,
                                 const float* __restrict__ cw) {
    int idx = blockIdx.x * blockDim.x + threadIdx.x;  // over L*D
    if (idx >= LL*DD) return;
    int d = idx & (DD-1);
    int l = idx >> 11;
    float prev = (l == 0) ? 0.f : x[idx - DD];
    float z = prev * cw[2*d] + x[idx] * cw[2*d + 1];
    g_xc[idx] = silu_f(z);
}

// ---------------- weight concat: Wq|Wk|Wv|Wg -> g_wcat ---------------------
__global__ void wcat_kernel(const float* __restrict__ Wq,
                            const float* __restrict__ Wk,
                            const float* __restrict__ Wv,
                            const float* __restrict__ Wg) {
    int idx = blockIdx.x * blockDim.x + threadIdx.x;   // over DD*NCAT/4
    if (idx >= DD * NCAT / 4) return;
    int n = (idx % (NCAT / 4)) * 4;
    int k = idx / (NCAT / 4);
    float4 v;
    if      (n < 1024) v = *(const float4*)(Wq + (size_t)k * DKK + n);
    else if (n < 2048) v = *(const float4*)(Wk + (size_t)k * DKK + (n - 1024));
    else if (n < 4096) v = *(const float4*)(Wv + (size_t)k * DVV + (n - 2048));
    else               v = *(const float4*)(Wg + (size_t)k * DVV + (n - 4096));
    *(float4*)(g_wcat + (size_t)k * NCAT + n) = v;
}

// ---------------- W2 = Wv @ router_w (fp32 exact, [2048][32]) --------------
__global__ void w2_kernel(const float* __restrict__ Wv,
                          const float* __restrict__ rw) {
    int k  = blockIdx.x;          // 2048 blocks
    int t  = threadIdx.x;         // 32 threads: h*2+r
    int h  = t >> 1, r = t & 1;
    const float* wrow = Wv + (size_t)k * DVV + h * HDVV;
    const float* rr   = rw + (h * HDVV) * 2 + r;
    float acc = 0.f;
    #pragma unroll 8
    for (int d = 0; d < HDVV; d++)
        acc += wrow[d] * rr[2 * d];
    g_w2[k * 32 + t] = acc;
}

// ---------------- router logits = xc @ W2 (fp32 exact, [2048][32]) ---------
__global__ void rlog_kernel() {
    // block: 8 l-rows x 32 hr = 256 threads
    int tid = threadIdx.x;
    int hr  = tid & 31;
    int l   = blockIdx.x * 8 + (tid >> 5);
    const float* xrow = g_xc + (size_t)l * DD;
    float acc = 0.f;
    #pragma unroll 4
    for (int k = 0; k < DD; k++)
        acc += xrow[k] * g_w2[k * 32 + hr];
    g_rlog[l * 32 + hr] = acc;
}

// ---------------- tensor-core GEMM (TF32): C = A @ B, row-major ------------
// silu applied to columns < silu_ncols.
#define AP 36
#define BP 132
#define SMEM_GEMM0 ((128*AP + 32*BP) * 4)

__global__ void gemm_tc(const float* __restrict__ A,
                        const float* __restrict__ B,
                        float* __restrict__ C,
                        int M, int N, int K, int silu_ncols) {
    extern __shared__ float sm[];
    float* Ah = sm;                 // [128][AP]
    float* Bh = Ah + 128*AP;        // [32][BP]

    int tid = threadIdx.x, lane = tid & 31, warp = tid >> 5;
    int bm = blockIdx.y * 128, bn = blockIdx.x * 128;
    int wm = (warp >> 2) * 64, wn = (warp & 3) * 32;
    int g = lane >> 2, t = lane & 3;

    float acc[4][4][4];
    #pragma unroll
    for (int i = 0; i < 4; i++)
        #pragma unroll
        for (int j = 0; j < 4; j++)
            #pragma unroll
            for (int r = 0; r < 4; r++) acc[i][j][r] = 0.f;

    int ar[4], ac[4], br[4], bc[4];
    #pragma unroll
    for (int i = 0; i < 4; i++) {
        int idx = tid + i * 256;
        ar[i] = idx >> 3;  ac[i] = (idx & 7) * 4;
        br[i] = idx >> 5;  bc[i] = (idx & 31) * 4;
    }

    const float* Abase = A + (size_t)bm * K;
    const float* Bbase = B + bn;

    float4 pa[4], pb[4];
    #pragma unroll
    for (int i = 0; i < 4; i++) {
        pa[i] = *(const float4*)(Abase + (size_t)ar[i] * K + ac[i]);
        pb[i] = *(const float4*)(Bbase + (size_t)br[i] * N + bc[i]);
    }

    int nk = K >> 5;
    for (int kt = 0; kt < nk; kt++) {
        #pragma unroll
        for (int i = 0; i < 4; i++) {
            float va[4] = {pa[i].x, pa[i].y, pa[i].z, pa[i].w};
            float vb[4] = {pb[i].x, pb[i].y, pb[i].z, pb[i].w};
            #pragma unroll
            for (int j = 0; j < 4; j++) {
                Ah[ar[i]*AP + ac[i] + j] = __uint_as_float(f2tf(va[j]));
                Bh[br[i]*BP + bc[i] + j] = __uint_as_float(f2tf(vb[j]));
            }
        }
        __syncthreads();

        if (kt + 1 < nk) {
            int k0 = (kt + 1) * 32;
            #pragma unroll
            for (int i = 0; i < 4; i++) {
                pa[i] = *(const float4*)(Abase + (size_t)ar[i] * K + k0 + ac[i]);
                pb[i] = *(const float4*)(Bbase + (size_t)(k0 + br[i]) * N + bc[i]);
            }
        }

        #pragma unroll
        for (int ko = 0; ko < 32; ko += 8) {
            unsigned af[4][4], bf[4][2];
            #pragma unroll
            for (int fm = 0; fm < 4; fm++) {
                int r0 = wm + fm * 16 + g;
                af[fm][0] = __float_as_uint(Ah[ r0      * AP + ko + t]);
                af[fm][1] = __float_as_uint(Ah[(r0 + 8) * AP + ko + t]);
                af[fm][2] = __float_as_uint(Ah[ r0      * AP + ko + t + 4]);
                af[fm][3] = __float_as_uint(Ah[(r0 + 8) * AP + ko + t + 4]);
            }
            #pragma unroll
            for (int fn = 0; fn < 4; fn++) {
                int c0 = wn + fn * 8 + g;
                bf[fn][0] = __float_as_uint(Bh[(ko + t    ) * BP + c0]);
                bf[fn][1] = __float_as_uint(Bh[(ko + t + 4) * BP + c0]);
            }
            #pragma unroll
            for (int fm = 0; fm < 4; fm++)
                #pragma unroll
                for (int fn = 0; fn < 4; fn++)
                    mma8(acc[fm][fn], af[fm][0], af[fm][1], af[fm][2], af[fm][3],
                         bf[fn][0], bf[fn][1]);
        }
        __syncthreads();
    }

    #pragma unroll
    for (int fm = 0; fm < 4; fm++) {
        int r0 = bm + wm + fm * 16 + g;
        #pragma unroll
        for (int fn = 0; fn < 4; fn++) {
            int c0 = bn + wn + fn * 8 + 2 * t;
            float v0 = acc[fm][fn][0], v1 = acc[fm][fn][1];
            float v2 = acc[fm][fn][2], v3 = acc[fm][fn][3];
            if (c0 < silu_ncols) {
                v0 = silu_f(v0); v1 = silu_f(v1);
                v2 = silu_f(v2); v3 = silu_f(v3);
            }
            *(float2*)(C + (size_t)r0 * N + c0)       = make_float2(v0, v1);
            *(float2*)(C + (size_t)(r0 + 8) * N + c0) = make_float2(v2, v3);
        }
    }
}

// ---------------- stage 3: RoPE on q and k (in place, qkvg layout) ---------
__global__ void rope_kernel() {
    int idx = blockIdx.x * blockDim.x + threadIdx.x;   // L*H*32
    if (idx >= LL * HH * 32) return;
    int i  = idx & 31;
    int lh = idx >> 5;
    int h  = lh & (HH-1);
    int l  = lh >> 4;
    float invf = powf(10000.f, -(float)i / 32.f);
    float ang = (float)l * invf;
    float c = cosf(ang), s = sinf(ang);
    size_t qb = (size_t)l * NCAT + h * HDKK;           // q block
    size_t kb = qb + DKK;                              // k block
    float q1 = g_qkvg[qb + i], q2 = g_qkvg[qb + 32 + i];
    g_qkvg[qb + i]      = q1 * c - q2 * s;
    g_qkvg[qb + 32 + i] = q2 * c + q1 * s;
    float k1 = g_qkvg[kb + i], k2 = g_qkvg[kb + 32 + i];
    g_qkvg[kb + i]      = k1 * c - k2 * s;
    g_qkvg[kb + 32 + i] = k2 * c + k1 * s;
}

// ---------------- stage 4: router decision + sequential count scan ---------
__global__ void router_kernel() {
    int h = blockIdx.x;                    // 16 blocks, 256 threads
    __shared__ float s_score[LL];
    __shared__ int   s_sel[LL];
    for (int l = threadIdx.x; l < LL; l += blockDim.x) {
        float z0 = g_rlog[l * 32 + h * 2 + 0];
        float z1 = g_rlog[l * 32 + h * 2 + 1];
        int sel = (z1 > z0) ? 1 : 0;
        float m = fmaxf(z0, z1);
        float e0 = expf(z0 - m), e1 = expf(z1 - m);
        s_sel[l]   = sel;
        s_score[l] = ((sel == 0) ? e0 : e1) / (e0 + e1);
    }
    __syncthreads();
    if (threadIdx.x == 0) {
        int c0 = 0, c1 = 0;
        const float scale = 0.125f;   // HDK^{-1/2}
        for (int l = 0; l < LL; l++) {
            int sel = s_sel[l];
            int cnt;
            if (sel == 0) { c0++; cnt = c0; } else { c1++; cnt = c1; }
            g_rsel[h * LL + l] = sel;
            g_coef[h * LL + l] = s_score[l] / (float)cnt * scale;
        }
    }
}

// ---------------- stage 5: tensor-core attention ---------------------------
#define ST 68
#define VT 136
#define OF_QH 0
#define OF_QL (OF_QH + 64*ST)
#define OF_KH (OF_QL + 64*ST)
#define OF_KL (OF_KH + 64*ST)
#define OF_SH (OF_KL + 64*ST)
#define OF_SL (OF_SH + 64*ST)
#define OF_VH (OF_SL + 64*ST)
#define OF_VL (OF_VH + 64*VT)
#define OF_CF (OF_VL + 64*VT)
#define OF_RR (OF_CF + 64)
#define OF_RC (OF_RR + 64)
#define ATTN2_FLOATS (OF_RC + 64)
#define ATTN2_BYTES  (ATTN2_FLOATS * 4)

__global__ __launch_bounds__(256, 1) void attn_tc() {
    extern __shared__ float smf[];
    float* Qh = smf + OF_QH;  float* Ql = smf + OF_QL;
    float* Kh = smf + OF_KH;  float* Kl = smf + OF_KL;
    float* Sh = smf + OF_SH;  float* Sl = smf + OF_SL;
    float* Vh = smf + OF_VH;  float* Vl = smf + OF_VL;
    float* coef_r = smf + OF_CF;
    int*   rsel_r = (int*)(smf + OF_RR);
    int*   rsel_c = (int*)(smf + OF_RC);

    int h   = blockIdx.y;
    int l0  = (gridDim.x - 1 - blockIdx.x) * 64;   // heavy tiles first
    int tid = threadIdx.x, lane = tid & 31, warp = tid >> 5;
    int g = lane >> 2, t = lane & 3;
    int wm  = (warp >> 1) * 16;
    int wns = (warp & 1) * 32;
    int wno = (warp & 1) * 64;

    for (int i = tid; i < 64 * 64; i += 256) {
        int r = i >> 6, c = i & 63;
        float v = g_qkvg[(size_t)(l0 + r) * NCAT + h * HDKK + c];
        float hi, lo; split_tf(v, hi, lo);
        Qh[r * ST + c] = hi; Ql[r * ST + c] = lo;
    }
    if (tid < 64) {
        rsel_r[tid] = g_rsel[h * LL + l0 + tid];
        coef_r[tid] = g_coef[h * LL + l0 + tid];
    }

    float acc_o[8][4];
    #pragma unroll
    for (int fn = 0; fn < 8; fn++)
        #pragma unroll
        for (int r = 0; r < 4; r++) acc_o[fn][r] = 0.f;

    int ntiles = (l0 >> 6) + 1;
    for (int mt = 0; mt < ntiles; mt++) {
        int m0 = mt * 64;
        __syncthreads();
        for (int i = tid; i < 64 * 64; i += 256) {
            int r = i >> 6, c = i & 63;
            float v = g_qkvg[(size_t)(m0 + r) * NCAT + DKK + h * HDKK + c];
            float hi, lo; split_tf(v, hi, lo);
            Kh[r * ST + c] = hi; Kl[r * ST + c] = lo;
        }
        for (int i = tid; i < 64 * 128; i += 256) {
            int r = i >> 7, c = i & 127;
            float v = g_qkvg[(size_t)(m0 + r) * NCAT + 2*DKK + h * HDVV + c];
            float hi, lo; split_tf(v, hi, lo);
            Vh[r * VT + c] = hi; Vl[r * VT + c] = lo;
        }
        if (tid < 64) rsel_c[tid] = g_rsel[h * LL + m0 + tid];
        __syncthreads();

        // ---- QK^T: warp tile 16x32 ----
        float acc_s[4][4];
        #pragma unroll
        for (int fn = 0; fn < 4; fn++)
            #pragma unroll
            for (int r = 0; r < 4; r++) acc_s[fn][r] = 0.f;

        #pragma unroll
        for (int ko = 0; ko < 64; ko += 8) {
            int r0 = wm + g;
            unsigned ah[4], al[4];
            ah[0] = __float_as_uint(Qh[ r0      * ST + ko + t]);
            ah[1] = __float_as_uint(Qh[(r0 + 8) * ST + ko + t]);
            ah[2] = __float_as_uint(Qh[ r0      * ST + ko + t + 4]);
            ah[3] = __float_as_uint(Qh[(r0 + 8) * ST + ko + t + 4]);
            al[0] = __float_as_uint(Ql[ r0      * ST + ko + t]);
            al[1] = __float_as_uint(Ql[(r0 + 8) * ST + ko + t]);
            al[2] = __float_as_uint(Ql[ r0      * ST + ko + t + 4]);
            al[3] = __float_as_uint(Ql[(r0 + 8) * ST + ko + t + 4]);
            #pragma unroll
            for (int fn = 0; fn < 4; fn++) {
                int c0 = wns + fn * 8 + g;
                unsigned bh0 = __float_as_uint(Kh[c0 * ST + ko + t]);
                unsigned bh1 = __float_as_uint(Kh[c0 * ST + ko + t + 4]);
                unsigned bl0 = __float_as_uint(Kl[c0 * ST + ko + t]);
                unsigned bl1 = __float_as_uint(Kl[c0 * ST + ko + t + 4]);
                mma8(acc_s[fn], ah[0], ah[1], ah[2], ah[3], bh0, bh1);
                mma8(acc_s[fn], ah[0], ah[1], ah[2], ah[3], bl0, bl1);
                mma8(acc_s[fn], al[0], al[1], al[2], al[3], bh0, bh1);
            }
        }

        // ---- mask + coef, split-store S ----
        {
            int r0 = wm + g, r1 = r0 + 8;
            int gl0 = l0 + r0, gl1 = l0 + r1;
            int e0 = rsel_r[r0], e1 = rsel_r[r1];
            float cf0 = coef_r[r0], cf1 = coef_r[r1];
            #pragma unroll
            for (int fn = 0; fn < 4; fn++) {
                int c = wns + fn * 8 + 2 * t;
                int gm0 = m0 + c, gm1 = gm0 + 1;
                int ec0 = rsel_c[c], ec1 = rsel_c[c + 1];
                float s00 = (gm0 <= gl0 && ec0 == e0) ? acc_s[fn][0] * cf0 : 0.f;
                float s01 = (gm1 <= gl0 && ec1 == e0) ? acc_s[fn][1] * cf0 : 0.f;
                float s10 = (gm0 <= gl1 && ec0 == e1) ? acc_s[fn][2] * cf1 : 0.f;
                float s11 = (gm1 <= gl1 && ec1 == e1) ? acc_s[fn][3] * cf1 : 0.f;
                float h00, l00, h01, l01, h10, l10, h11, l11;
                split_tf(s00, h00, l00); split_tf(s01, h01, l01);
                split_tf(s10, h10, l10); split_tf(s11, h11, l11);
                *(float2*)&Sh[r0 * ST + c] = make_float2(h00, h01);
                *(float2*)&Sl[r0 * ST + c] = make_float2(l00, l01);
                *(float2*)&Sh[r1 * ST + c] = make_float2(h10, h11);
                *(float2*)&Sl[r1 * ST + c] = make_float2(l10, l11);
            }
        }
        __syncthreads();

        // ---- O += S @ V: warp tile 16x64 ----
        #pragma unroll
        for (int ko = 0; ko < 64; ko += 8) {
            int r0 = wm + g;
            unsigned ah[4], al[4];
            ah[0] = __float_as_uint(Sh[ r0      * ST + ko + t]);
            ah[1] = __float_as_uint(Sh[(r0 + 8) * ST + ko + t]);
            ah[2] = __float_as_uint(Sh[ r0      * ST + ko + t + 4]);
            ah[3] = __float_as_uint(Sh[(r0 + 8) * ST + ko + t + 4]);
            al[0] = __float_as_uint(Sl[ r0      * ST + ko + t]);
            al[1] = __float_as_uint(Sl[(r0 + 8) * ST + ko + t]);
            al[2] = __float_as_uint(Sl[ r0      * ST + ko + t + 4]);
            al[3] = __float_as_uint(Sl[(r0 + 8) * ST + ko + t + 4]);
            #pragma unroll
            for (int fn = 0; fn < 8; fn++) {
                int c0 = wno + fn * 8 + g;
                unsigned bh0 = __float_as_uint(Vh[(ko + t    ) * VT + c0]);
                unsigned bh1 = __float_as_uint(Vh[(ko + t + 4) * VT + c0]);
                unsigned bl0 = __float_as_uint(Vl[(ko + t    ) * VT + c0]);
                unsigned bl1 = __float_as_uint(Vl[(ko + t + 4) * VT + c0]);
                mma8(acc_o[fn], ah[0], ah[1], ah[2], ah[3], bh0, bh1);
                mma8(acc_o[fn], ah[0], ah[1], ah[2], ah[3], bl0, bl1);
                mma8(acc_o[fn], al[0], al[1], al[2], al[3], bh0, bh1);
            }
        }
    }

    // ---- store O ----
    int r0 = wm + g;
    #pragma unroll
    for (int fn = 0; fn < 8; fn++) {
        int c = wno + fn * 8 + 2 * t;
        *(float2*)(g_o + (size_t)(l0 + r0    ) * DVV + h * HDVV + c)
            = make_float2(acc_o[fn][0], acc_o[fn][1]);
        *(float2*)(g_o + (size_t)(l0 + r0 + 8) * DVV + h * HDVV + c)
            = make_float2(acc_o[fn][2], acc_o[fn][3]);
    }
}

// ---------------- stage 6: LayerNorm(128) * silu(gate) ---------------------
__global__ void ln_gate_kernel() {
    int h = blockIdx.x;
    int l = blockIdx.y;
    int j = threadIdx.x;    // 128
    size_t obase = (size_t)l * DVV + h * HDVV;
    float o = g_o[obase + j];
    float sum = o, sumsq = o * o;
    #pragma unroll
    for (int off = 16; off; off >>= 1) {
        sum   += __shfl_down_sync(0xffffffffu, sum,   off);
        sumsq += __shfl_down_sync(0xffffffffu, sumsq, off);
    }
    __shared__ float s1[4], s2[4];
    if ((j & 31) == 0) { s1[j >> 5] = sum; s2[j >> 5] = sumsq; }
    __syncthreads();
    float tot   = s1[0] + s1[1] + s1[2] + s1[3];
    float totsq = s2[0] + s2[1] + s2[2] + s2[3];
    float mu  = tot * (1.f / 128.f);
    float var = totsq * (1.f / 128.f) - mu * mu;
    float inv = rsqrtf(var + 1e-5f);
    float gt  = g_qkvg[(size_t)l * NCAT + 2*DKK + DVV + h * HDVV + j];
    g_y[obase + j] = silu_f(gt) * (o - mu) * inv;
}

// ---------------- launch ----------------------------------------------------
extern "C" void kernel_launch(void* const* d_in, const int* in_sizes, int n_in,
                              void* d_out, int out_size) {
    const float* x    = (const float*)d_in[0];
    const float* cw   = (const float*)d_in[1];
    const float* Wq   = (const float*)d_in[2];
    const float* Wk   = (const float*)d_in[3];
    const float* Wv   = (const float*)d_in[4];
    const float* Wg   = (const float*)d_in[5];
    const float* rw   = (const float*)d_in[6];
    const float* Wout = (const float*)d_in[7];
    float* out = (float*)d_out;

    float *p_xc, *p_wcat, *p_qkvg, *p_y;
    cudaGetSymbolAddress((void**)&p_xc,   g_xc);
    cudaGetSymbolAddress((void**)&p_wcat, g_wcat);
    cudaGetSymbolAddress((void**)&p_qkvg, g_qkvg);
    cudaGetSymbolAddress((void**)&p_y,    g_y);

    cudaFuncSetAttribute(attn_tc,
                         cudaFuncAttributeMaxDynamicSharedMemorySize, ATTN2_BYTES);
    cudaFuncSetAttribute(gemm_tc,
                         cudaFuncAttributeMaxDynamicSharedMemorySize, SMEM_GEMM0);

    conv_silu_kernel<<<(LL*DD)/256, 256>>>(x, cw);
    wcat_kernel<<<(DD*NCAT/4 + 255)/256, 256>>>(Wq, Wk, Wv, Wg);
    w2_kernel<<<DD, 32>>>(Wv, rw);

    // fused QKVG projection (silu on q columns)
    gemm_tc<<<dim3(NCAT/128, LL/128), 256, SMEM_GEMM0>>>(p_xc, p_wcat, p_qkvg,
                                                         LL, NCAT, DD, DKK);
    rlog_kernel<<<LL/8, 256>>>();

    rope_kernel<<<(LL*HH*32)/256, 256>>>();
    router_kernel<<<HH, 256>>>();

    attn_tc<<<dim3(LL/64, HH), 256, ATTN2_BYTES>>>();

    ln_gate_kernel<<<dim3(HH, LL), 128>>>();

    gemm_tc<<<dim3(DD/128, LL/128), 256, SMEM_GEMM0>>>(p_y, Wout, out,
                                                       LL, DD, DVV, 0);
}

// round 6
// speedup vs baseline: 2.5594x; 1.1890x over previous
#include <cuda_runtime.h>
#include <math.h>

#define LL   2048
#define DD   2048
#define HH   16
#define DKK  1024
#define DVV  2048
#define HDKK 64
#define HDVV 128
#define NCAT 6144              // q(1024) | k(1024) | v(2048) | g(2048)

// ---------------- scratch (device globals; no allocation allowed) ----------
__device__ float g_xc  [LL*DD];      // conv+silu output
__device__ float g_wcat[DD*NCAT];    // Wq|Wk|Wv|Wg concatenated
__device__ float g_qkvg[LL*NCAT];    // fused projection output
__device__ float g_w2  [DD*32];      // Wv @ router_w  (fp32 exact)
__device__ float g_rlog[LL*32];      // router logits  (fp32 exact)
__device__ float g_o   [LL*DVV];     // attention output
__device__ float g_y   [LL*DVV];     // silu(g)*LN(o)
__device__ float g_coef[HH*LL];      // score_max/count * HDK^-0.5
__device__ int   g_rsel[HH*LL];      // selected expert per (h,l)

__device__ __forceinline__ float silu_f(float z) { return z / (1.f + expf(-z)); }

__device__ __forceinline__ unsigned f2tf(float f) {
    unsigned r;
    asm("cvt.rna.tf32.f32 %0, %1;" : "=r"(r) : "f"(f));
    return r;
}

__device__ __forceinline__ void split_tf(float v, float& hi, float& lo) {
    hi = __uint_as_float(f2tf(v));
    lo = __uint_as_float(f2tf(v - hi));
}

__device__ __forceinline__ void mma8(float* c,
                                     unsigned a0, unsigned a1, unsigned a2, unsigned a3,
                                     unsigned b0, unsigned b1) {
    asm("mma.sync.aligned.m16n8k8.row.col.f32.tf32.tf32.f32 "
        "{%0,%1,%2,%3}, {%4,%5,%6,%7}, {%8,%9}, {%0,%1,%2,%3};"
        : "+f"(c[0]), "+f"(c[1]), "+f"(c[2]), "+f"(c[3])
        : "r"(a0), "r"(a1), "r"(a2), "r"(a3), "r"(b0), "r"(b1));
}

__device__ __forceinline__ void cp16(float* smem_dst, const float* gsrc) {
    unsigned sa = (unsigned)__cvta_generic_to_shared(smem_dst);
    asm volatile("cp.async.cg.shared.global [%0], [%1], 16;\n"
                 :: "r"(sa), "l"(gsrc));
}

// ---------------- stage 1: shifted conv + silu -----------------------------
__global__ void conv_silu_kernel(const float* __restrict__ x,
                                 const float* __restrict__ cw) {
    int idx = blockIdx.x * blockDim.x + threadIdx.x;  // over L*D
    if (idx >= LL*DD) return;
    int d = idx & (DD-1);
    int l = idx >> 11;
    float prev = (l == 0) ? 0.f : x[idx - DD];
    float z = prev * cw[2*d] + x[idx] * cw[2*d + 1];
    g_xc[idx] = silu_f(z);
}

// ---------------- weight concat: Wq|Wk|Wv|Wg -> g_wcat ---------------------
__global__ void wcat_kernel(const float* __restrict__ Wq,
                            const float* __restrict__ Wk,
                            const float* __restrict__ Wv,
                            const float* __restrict__ Wg) {
    int idx = blockIdx.x * blockDim.x + threadIdx.x;   // over DD*NCAT/4
    if (idx >= DD * NCAT / 4) return;
    int n = (idx % (NCAT / 4)) * 4;
    int k = idx / (NCAT / 4);
    float4 v;
    if      (n < 1024) v = *(const float4*)(Wq + (size_t)k * DKK + n);
    else if (n < 2048) v = *(const float4*)(Wk + (size_t)k * DKK + (n - 1024));
    else if (n < 4096) v = *(const float4*)(Wv + (size_t)k * DVV + (n - 2048));
    else               v = *(const float4*)(Wg + (size_t)k * DVV + (n - 4096));
    *(float4*)(g_wcat + (size_t)k * NCAT + n) = v;
}

// ---------------- W2 = Wv @ router_w (fp32 exact, [2048][32]) --------------
__global__ void w2_kernel(const float* __restrict__ Wv,
                          const float* __restrict__ rw) {
    int k  = blockIdx.x;          // 2048 blocks
    int t  = threadIdx.x;         // 32 threads: h*2+r
    int h  = t >> 1, r = t & 1;
    const float* wrow = Wv + (size_t)k * DVV + h * HDVV;
    const float* rr   = rw + (h * HDVV) * 2 + r;
    float acc = 0.f;
    #pragma unroll 8
    for (int d = 0; d < HDVV; d++)
        acc += wrow[d] * rr[2 * d];
    g_w2[k * 32 + t] = acc;
}

// ---------------- router logits = xc @ W2 (fp32 exact, [2048][32]) ---------
__global__ void rlog_kernel() {
    int tid = threadIdx.x;
    int hr  = tid & 31;
    int l   = blockIdx.x * 8 + (tid >> 5);
    const float* xrow = g_xc + (size_t)l * DD;
    float acc = 0.f;
    #pragma unroll 4
    for (int k = 0; k < DD; k++)
        acc += xrow[k] * g_w2[k * 32 + hr];
    g_rlog[l * 32 + hr] = acc;
}

// ---------------- tensor-core GEMM (TF32): C = A @ B, row-major ------------
// cp.async 2-stage double buffer, raw fp32 in smem, cvt at fragment load.
// silu applied to columns < silu_ncols. 2 CTAs/SM.
#define AP 36
#define BPAD 136
#define STGF (128*AP + 32*BPAD)       // floats per stage = 8960
#define SMEM_GEMM (2 * STGF * 4)      // 71680 bytes

__global__ __launch_bounds__(256, 2) void gemm_tc(
        const float* __restrict__ A,
        const float* __restrict__ B,
        float* __restrict__ C,
        int M, int N, int K, int silu_ncols) {
    extern __shared__ float sm[];

    int tid = threadIdx.x, lane = tid & 31, warp = tid >> 5;
    int bm = blockIdx.y * 128, bn = blockIdx.x * 128;
    int wm = (warp >> 2) * 64, wn = (warp & 3) * 32;
    int g = lane >> 2, t = lane & 3;

    float acc[4][4][4];
    #pragma unroll
    for (int i = 0; i < 4; i++)
        #pragma unroll
        for (int j = 0; j < 4; j++)
            #pragma unroll
            for (int r = 0; r < 4; r++) acc[i][j][r] = 0.f;

    // per-thread async-copy slots: 4 A chunks + 4 B chunks of 16B
    const float* agp[4];
    const float* bgp[4];
    int asp[4], bsp[4];
    #pragma unroll
    for (int i = 0; i < 4; i++) {
        int idx = tid + i * 256;
        int ar = idx >> 3, ac = (idx & 7) * 4;    // A: 128 rows x 32 k
        int br = idx >> 5, bc = (idx & 31) * 4;   // B: 32 k x 128 cols
        agp[i] = A + (size_t)(bm + ar) * K + ac;
        bgp[i] = B + (size_t)br * N + bn + bc;
        asp[i] = ar * AP + ac;
        bsp[i] = 128 * AP + br * BPAD + bc;
    }

#define LOAD_STAGE(s, k0) do {                                          \
        float* base_ = sm + (s) * STGF;                                 \
        _Pragma("unroll")                                               \
        for (int i_ = 0; i_ < 4; i_++) {                                \
            cp16(base_ + asp[i_], agp[i_] + (k0));                      \
            cp16(base_ + bsp[i_], bgp[i_] + (size_t)(k0) * N);          \
        }                                                               \
        asm volatile("cp.async.commit_group;\n" ::);                    \
    } while (0)

    int nk = K >> 5;
    LOAD_STAGE(0, 0);
    LOAD_STAGE(1, 32);

    for (int kt = 0; kt < nk; kt++) {
        int s = kt & 1;
        asm volatile("cp.async.wait_group 1;\n" ::);
        __syncthreads();
        const float* Ah = sm + s * STGF;
        const float* Bh = Ah + 128 * AP;

        #pragma unroll
        for (int ko = 0; ko < 32; ko += 8) {
            unsigned af[4][4], bf[4][2];
            #pragma unroll
            for (int fm = 0; fm < 4; fm++) {
                int r0 = wm + fm * 16 + g;
                af[fm][0] = f2tf(Ah[ r0      * AP + ko + t]);
                af[fm][1] = f2tf(Ah[(r0 + 8) * AP + ko + t]);
                af[fm][2] = f2tf(Ah[ r0      * AP + ko + t + 4]);
                af[fm][3] = f2tf(Ah[(r0 + 8) * AP + ko + t + 4]);
            }
            #pragma unroll
            for (int fn = 0; fn < 4; fn++) {
                int c0 = wn + fn * 8 + g;
                bf[fn][0] = f2tf(Bh[(ko + t    ) * BPAD + c0]);
                bf[fn][1] = f2tf(Bh[(ko + t + 4) * BPAD + c0]);
            }
            #pragma unroll
            for (int fm = 0; fm < 4; fm++)
                #pragma unroll
                for (int fn = 0; fn < 4; fn++)
                    mma8(acc[fm][fn], af[fm][0], af[fm][1], af[fm][2], af[fm][3],
                         bf[fn][0], bf[fn][1]);
        }
        __syncthreads();
        if (kt + 2 < nk) LOAD_STAGE(s, (kt + 2) * 32);
    }

    #pragma unroll
    for (int fm = 0; fm < 4; fm++) {
        int r0 = bm + wm + fm * 16 + g;
        #pragma unroll
        for (int fn = 0; fn < 4; fn++) {
            int c0 = bn + wn + fn * 8 + 2 * t;
            float v0 = acc[fm][fn][0], v1 = acc[fm][fn][1];
            float v2 = acc[fm][fn][2], v3 = acc[fm][fn][3];
            if (c0 < silu_ncols) {
                v0 = silu_f(v0); v1 = silu_f(v1);
                v2 = silu_f(v2); v3 = silu_f(v3);
            }
            *(float2*)(C + (size_t)r0 * N + c0)       = make_float2(v0, v1);
            *(float2*)(C + (size_t)(r0 + 8) * N + c0) = make_float2(v2, v3);
        }
    }
}

// ---------------- stage 3: RoPE on q and k (in place, qkvg layout) ---------
__global__ void rope_kernel() {
    int idx = blockIdx.x * blockDim.x + threadIdx.x;   // L*H*32
    if (idx >= LL * HH * 32) return;
    int i  = idx & 31;
    int lh = idx >> 5;
    int h  = lh & (HH-1);
    int l  = lh >> 4;
    float invf = powf(10000.f, -(float)i / 32.f);
    float ang = (float)l * invf;
    float c = cosf(ang), s = sinf(ang);
    size_t qb = (size_t)l * NCAT + h * HDKK;           // q block
    size_t kb = qb + DKK;                              // k block
    float q1 = g_qkvg[qb + i], q2 = g_qkvg[qb + 32 + i];
    g_qkvg[qb + i]      = q1 * c - q2 * s;
    g_qkvg[qb + 32 + i] = q2 * c + q1 * s;
    float k1 = g_qkvg[kb + i], k2 = g_qkvg[kb + 32 + i];
    g_qkvg[kb + i]      = k1 * c - k2 * s;
    g_qkvg[kb + 32 + i] = k2 * c + k1 * s;
}

// ---------------- stage 4: router decision + sequential count scan ---------
__global__ void router_kernel() {
    int h = blockIdx.x;                    // 16 blocks, 256 threads
    __shared__ float s_score[LL];
    __shared__ int   s_sel[LL];
    for (int l = threadIdx.x; l < LL; l += blockDim.x) {
        float z0 = g_rlog[l * 32 + h * 2 + 0];
        float z1 = g_rlog[l * 32 + h * 2 + 1];
        int sel = (z1 > z0) ? 1 : 0;
        float m = fmaxf(z0, z1);
        float e0 = expf(z0 - m), e1 = expf(z1 - m);
        s_sel[l]   = sel;
        s_score[l] = ((sel == 0) ? e0 : e1) / (e0 + e1);
    }
    __syncthreads();
    if (threadIdx.x == 0) {
        int c0 = 0, c1 = 0;
        const float scale = 0.125f;   // HDK^{-1/2}
        for (int l = 0; l < LL; l++) {
            int sel = s_sel[l];
            int cnt;
            if (sel == 0) { c0++; cnt = c0; } else { c1++; cnt = c1; }
            g_rsel[h * LL + l] = sel;
            g_coef[h * LL + l] = s_score[l] / (float)cnt * scale;
        }
    }
}

// ---------------- stage 5: tensor-core attention ---------------------------
#define ST 68
#define VT 136
#define OF_QH 0
#define OF_QL (OF_QH + 64*ST)
#define OF_KH (OF_QL + 64*ST)
#define OF_KL (OF_KH + 64*ST)
#define OF_SH (OF_KL + 64*ST)
#define OF_SL (OF_SH + 64*ST)
#define OF_VH (OF_SL + 64*ST)
#define OF_VL (OF_VH + 64*VT)
#define OF_CF (OF_VL + 64*VT)
#define OF_RR (OF_CF + 64)
#define OF_RC (OF_RR + 64)
#define ATTN2_FLOATS (OF_RC + 64)
#define ATTN2_BYTES  (ATTN2_FLOATS * 4)

__global__ __launch_bounds__(256, 1) void attn_tc() {
    extern __shared__ float smf[];
    float* Qh = smf + OF_QH;  float* Ql = smf + OF_QL;
    float* Kh = smf + OF_KH;  float* Kl = smf + OF_KL;
    float* Sh = smf + OF_SH;  float* Sl = smf + OF_SL;
    float* Vh = smf + OF_VH;  float* Vl = smf + OF_VL;
    float* coef_r = smf + OF_CF;
    int*   rsel_r = (int*)(smf + OF_RR);
    int*   rsel_c = (int*)(smf + OF_RC);

    int h   = blockIdx.y;
    int l0  = (gridDim.x - 1 - blockIdx.x) * 64;   // heavy tiles first
    int tid = threadIdx.x, lane = tid & 31, warp = tid >> 5;
    int g = lane >> 2, t = lane & 3;
    int wm  = (warp >> 1) * 16;
    int wns = (warp & 1) * 32;
    int wno = (warp & 1) * 64;

    for (int i = tid; i < 64 * 64; i += 256) {
        int r = i >> 6, c = i & 63;
        float v = g_qkvg[(size_t)(l0 + r) * NCAT + h * HDKK + c];
        float hi, lo; split_tf(v, hi, lo);
        Qh[r * ST + c] = hi; Ql[r * ST + c] = lo;
    }
    if (tid < 64) {
        rsel_r[tid] = g_rsel[h * LL + l0 + tid];
        coef_r[tid] = g_coef[h * LL + l0 + tid];
    }

    float acc_o[8][4];
    #pragma unroll
    for (int fn = 0; fn < 8; fn++)
        #pragma unroll
        for (int r = 0; r < 4; r++) acc_o[fn][r] = 0.f;

    int ntiles = (l0 >> 6) + 1;
    for (int mt = 0; mt < ntiles; mt++) {
        int m0 = mt * 64;
        __syncthreads();
        for (int i = tid; i < 64 * 64; i += 256) {
            int r = i >> 6, c = i & 63;
            float v = g_qkvg[(size_t)(m0 + r) * NCAT + DKK + h * HDKK + c];
            float hi, lo; split_tf(v, hi, lo);
            Kh[r * ST + c] = hi; Kl[r * ST + c] = lo;
        }
        for (int i = tid; i < 64 * 128; i += 256) {
            int r = i >> 7, c = i & 127;
            float v = g_qkvg[(size_t)(m0 + r) * NCAT + 2*DKK + h * HDVV + c];
            float hi, lo; split_tf(v, hi, lo);
            Vh[r * VT + c] = hi; Vl[r * VT + c] = lo;
        }
        if (tid < 64) rsel_c[tid] = g_rsel[h * LL + m0 + tid];
        __syncthreads();

        // ---- QK^T: warp tile 16x32 ----
        float acc_s[4][4];
        #pragma unroll
        for (int fn = 0; fn < 4; fn++)
            #pragma unroll
            for (int r = 0; r < 4; r++) acc_s[fn][r] = 0.f;

        #pragma unroll
        for (int ko = 0; ko < 64; ko += 8) {
            int r0 = wm + g;
            unsigned ah[4], al[4];
            ah[0] = __float_as_uint(Qh[ r0      * ST + ko + t]);
            ah[1] = __float_as_uint(Qh[(r0 + 8) * ST + ko + t]);
            ah[2] = __float_as_uint(Qh[ r0      * ST + ko + t + 4]);
            ah[3] = __float_as_uint(Qh[(r0 + 8) * ST + ko + t + 4]);
            al[0] = __float_as_uint(Ql[ r0      * ST + ko + t]);
            al[1] = __float_as_uint(Ql[(r0 + 8) * ST + ko + t]);
            al[2] = __float_as_uint(Ql[ r0      * ST + ko + t + 4]);
            al[3] = __float_as_uint(Ql[(r0 + 8) * ST + ko + t + 4]);
            #pragma unroll
            for (int fn = 0; fn < 4; fn++) {
                int c0 = wns + fn * 8 + g;
                unsigned bh0 = __float_as_uint(Kh[c0 * ST + ko + t]);
                unsigned bh1 = __float_as_uint(Kh[c0 * ST + ko + t + 4]);
                unsigned bl0 = __float_as_uint(Kl[c0 * ST + ko + t]);
                unsigned bl1 = __float_as_uint(Kl[c0 * ST + ko + t + 4]);
                mma8(acc_s[fn], ah[0], ah[1], ah[2], ah[3], bh0, bh1);
                mma8(acc_s[fn], ah[0], ah[1], ah[2], ah[3], bl0, bl1);
                mma8(acc_s[fn], al[0], al[1], al[2], al[3], bh0, bh1);
            }
        }

        // ---- mask + coef, split-store S ----
        {
            int r0 = wm + g, r1 = r0 + 8;
            int gl0 = l0 + r0, gl1 = l0 + r1;
            int e0 = rsel_r[r0], e1 = rsel_r[r1];
            float cf0 = coef_r[r0], cf1 = coef_r[r1];
            #pragma unroll
            for (int fn = 0; fn < 4; fn++) {
                int c = wns + fn * 8 + 2 * t;
                int gm0 = m0 + c, gm1 = gm0 + 1;
                int ec0 = rsel_c[c], ec1 = rsel_c[c + 1];
                float s00 = (gm0 <= gl0 && ec0 == e0) ? acc_s[fn][0] * cf0 : 0.f;
                float s01 = (gm1 <= gl0 && ec1 == e0) ? acc_s[fn][1] * cf0 : 0.f;
                float s10 = (gm0 <= gl1 && ec0 == e1) ? acc_s[fn][2] * cf1 : 0.f;
                float s11 = (gm1 <= gl1 && ec1 == e1) ? acc_s[fn][3] * cf1 : 0.f;
                float h00, l00, h01, l01, h10, l10, h11, l11;
                split_tf(s00, h00, l00); split_tf(s01, h01, l01);
                split_tf(s10, h10, l10); split_tf(s11, h11, l11);
                *(float2*)&Sh[r0 * ST + c] = make_float2(h00, h01);
                *(float2*)&Sl[r0 * ST + c] = make_float2(l00, l01);
                *(float2*)&Sh[r1 * ST + c] = make_float2(h10, h11);
                *(float2*)&Sl[r1 * ST + c] = make_float2(l10, l11);
            }
        }
        __syncthreads();

        // ---- O += S @ V: warp tile 16x64 ----
        #pragma unroll
        for (int ko = 0; ko < 64; ko += 8) {
            int r0 = wm + g;
            unsigned ah[4], al[4];
            ah[0] = __float_as_uint(Sh[ r0      * ST + ko + t]);
            ah[1] = __float_as_uint(Sh[(r0 + 8) * ST + ko + t]);
            ah[2] = __float_as_uint(Sh[ r0      * ST + ko + t + 4]);
            ah[3] = __float_as_uint(Sh[(r0 + 8) * ST + ko + t + 4]);
            al[0] = __float_as_uint(Sl[ r0      * ST + ko + t]);
            al[1] = __float_as_uint(Sl[(r0 + 8) * ST + ko + t]);
            al[2] = __float_as_uint(Sl[ r0      * ST + ko + t + 4]);
            al[3] = __float_as_uint(Sl[(r0 + 8) * ST + ko + t + 4]);
            #pragma unroll
            for (int fn = 0; fn < 8; fn++) {
                int c0 = wno + fn * 8 + g;
                unsigned bh0 = __float_as_uint(Vh[(ko + t    ) * VT + c0]);
                unsigned bh1 = __float_as_uint(Vh[(ko + t + 4) * VT + c0]);
                unsigned bl0 = __float_as_uint(Vl[(ko + t    ) * VT + c0]);
                unsigned bl1 = __float_as_uint(Vl[(ko + t + 4) * VT + c0]);
                mma8(acc_o[fn], ah[0], ah[1], ah[2], ah[3], bh0, bh1);
                mma8(acc_o[fn], ah[0], ah[1], ah[2], ah[3], bl0, bl1);
                mma8(acc_o[fn], al[0], al[1], al[2], al[3], bh0, bh1);
            }
        }
    }

    // ---- store O ----
    int r0 = wm + g;
    #pragma unroll
    for (int fn = 0; fn < 8; fn++) {
        int c = wno + fn * 8 + 2 * t;
        *(float2*)(g_o + (size_t)(l0 + r0    ) * DVV + h * HDVV + c)
            = make_float2(acc_o[fn][0], acc_o[fn][1]);
        *(float2*)(g_o + (size_t)(l0 + r0 + 8) * DVV + h * HDVV + c)
            = make_float2(acc_o[fn][2], acc_o[fn][3]);
    }
}

// ---------------- stage 6: LayerNorm(128) * silu(gate) ---------------------
__global__ void ln_gate_kernel() {
    int h = blockIdx.x;
    int l = blockIdx.y;
    int j = threadIdx.x;    // 128
    size_t obase = (size_t)l * DVV + h * HDVV;
    float o = g_o[obase + j];
    float sum = o, sumsq = o * o;
    #pragma unroll
    for (int off = 16; off; off >>= 1) {
        sum   += __shfl_down_sync(0xffffffffu, sum,   off);
        sumsq += __shfl_down_sync(0xffffffffu, sumsq, off);
    }
    __shared__ float s1[4], s2[4];
    if ((j & 31) == 0) { s1[j >> 5] = sum; s2[j >> 5] = sumsq; }
    __syncthreads();
    float tot   = s1[0] + s1[1] + s1[2] + s1[3];
    float totsq = s2[0] + s2[1] + s2[2] + s2[3];
    float mu  = tot * (1.f / 128.f);
    float var = totsq * (1.f / 128.f) - mu * mu;
    float inv = rsqrtf(var + 1e-5f);
    float gt  = g_qkvg[(size_t)l * NCAT + 2*DKK + DVV + h * HDVV + j];
    g_y[obase + j] = silu_f(gt) * (o - mu) * inv;
}

// ---------------- launch ----------------------------------------------------
extern "C" void kernel_launch(void* const* d_in, const int* in_sizes, int n_in,
                              void* d_out, int out_size) {
    const float* x    = (const float*)d_in[0];
    const float* cw   = (const float*)d_in[1];
    const float* Wq   = (const float*)d_in[2];
    const float* Wk   = (const float*)d_in[3];
    const float* Wv   = (const float*)d_in[4];
    const float* Wg   = (const float*)d_in[5];
    const float* rw   = (const float*)d_in[6];
    const float* Wout = (const float*)d_in[7];
    float* out = (float*)d_out;

    float *p_xc, *p_wcat, *p_qkvg, *p_y;
    cudaGetSymbolAddress((void**)&p_xc,   g_xc);
    cudaGetSymbolAddress((void**)&p_wcat, g_wcat);
    cudaGetSymbolAddress((void**)&p_qkvg, g_qkvg);
    cudaGetSymbolAddress((void**)&p_y,    g_y);

    cudaFuncSetAttribute(attn_tc,
                         cudaFuncAttributeMaxDynamicSharedMemorySize, ATTN2_BYTES);
    cudaFuncSetAttribute(gemm_tc,
                         cudaFuncAttributeMaxDynamicSharedMemorySize, SMEM_GEMM);

    conv_silu_kernel<<<(LL*DD)/256, 256>>>(x, cw);
    wcat_kernel<<<(DD*NCAT/4 + 255)/256, 256>>>(Wq, Wk, Wv, Wg);
    w2_kernel<<<DD, 32>>>(Wv, rw);

    // fused QKVG projection (silu on q columns)
    gemm_tc<<<dim3(NCAT/128, LL/128), 256, SMEM_GEMM>>>(p_xc, p_wcat, p_qkvg,
                                                        LL, NCAT, DD, DKK);
    rlog_kernel<<<LL/8, 256>>>();

    rope_kernel<<<(LL*HH*32)/256, 256>>>();
    router_kernel<<<HH, 256>>>();

    attn_tc<<<dim3(LL/64, HH), 256, ATTN2_BYTES>>>();

    ln_gate_kernel<<<dim3(HH, LL), 128>>>();

    gemm_tc<<<dim3(DD/128, LL/128), 256, SMEM_GEMM>>>(p_y, Wout, out,
                                                      LL, DD, DVV, 0);
}

// round 7
// speedup vs baseline: 3.2547x; 1.2716x over previous
#include <cuda_runtime.h>
#include <math.h>

#define LL   2048
#define DD   2048
#define HH   16
#define DKK  1024
#define DVV  2048
#define HDKK 64
#define HDVV 128
#define NCAT 6144              // q(1024) | k(1024) | v(2048) | g(2048)

// ---------------- scratch (device globals; no allocation allowed) ----------
__device__ float g_xc  [LL*DD];      // conv+silu output
__device__ float g_wcat[DD*NCAT];    // Wq|Wk|Wv|Wg concatenated
__device__ float g_qkvg[LL*NCAT];    // fused projection output
__device__ float g_w2  [DD*32];      // Wv @ router_w  (fp32 exact)
__device__ float g_rlog[LL*32];      // router logits  (fp32 exact)
__device__ float g_qh  [LL*DKK];     // roped q, hi part, head-major
__device__ float g_ql  [LL*DKK];     // roped q, lo part
__device__ float g_kh  [LL*DKK];     // roped k, hi part
__device__ float g_kl  [LL*DKK];     // roped k, lo part
__device__ float g_vh  [LL*DVV];     // v hi, head-major
__device__ float g_vl  [LL*DVV];     // v lo
__device__ float g_o   [LL*DVV];     // attention output
__device__ float g_y   [LL*DVV];     // silu(g)*LN(o)
__device__ float g_coef[HH*LL];      // score_max/count * HDK^-0.5
__device__ int   g_rsel[HH*LL];      // selected expert per (h,l)

__device__ __forceinline__ float silu_f(float z) { return z / (1.f + expf(-z)); }

__device__ __forceinline__ unsigned f2tf(float f) {
    unsigned r;
    asm("cvt.rna.tf32.f32 %0, %1;" : "=r"(r) : "f"(f));
    return r;
}

__device__ __forceinline__ void split_tf(float v, float& hi, float& lo) {
    hi = __uint_as_float(f2tf(v));
    lo = __uint_as_float(f2tf(v - hi));
}

__device__ __forceinline__ void mma8(float* c,
                                     unsigned a0, unsigned a1, unsigned a2, unsigned a3,
                                     unsigned b0, unsigned b1) {
    asm("mma.sync.aligned.m16n8k8.row.col.f32.tf32.tf32.f32 "
        "{%0,%1,%2,%3}, {%4,%5,%6,%7}, {%8,%9}, {%0,%1,%2,%3};"
        : "+f"(c[0]), "+f"(c[1]), "+f"(c[2]), "+f"(c[3])
        : "r"(a0), "r"(a1), "r"(a2), "r"(a3), "r"(b0), "r"(b1));
}

__device__ __forceinline__ void cp16(float* smem_dst, const float* gsrc) {
    unsigned sa = (unsigned)__cvta_generic_to_shared(smem_dst);
    asm volatile("cp.async.cg.shared.global [%0], [%1], 16;\n"
                 :: "r"(sa), "l"(gsrc));
}

// ---------------- stage 1: shifted conv + silu -----------------------------
__global__ void conv_silu_kernel(const float* __restrict__ x,
                                 const float* __restrict__ cw) {
    int idx = blockIdx.x * blockDim.x + threadIdx.x;  // over L*D
    if (idx >= LL*DD) return;
    int d = idx & (DD-1);
    int l = idx >> 11;
    float prev = (l == 0) ? 0.f : x[idx - DD];
    float z = prev * cw[2*d] + x[idx] * cw[2*d + 1];
    g_xc[idx] = silu_f(z);
}

// ---------------- weight concat: Wq|Wk|Wv|Wg -> g_wcat ---------------------
__global__ void wcat_kernel(const float* __restrict__ Wq,
                            const float* __restrict__ Wk,
                            const float* __restrict__ Wv,
                            const float* __restrict__ Wg) {
    int idx = blockIdx.x * blockDim.x + threadIdx.x;   // over DD*NCAT/4
    if (idx >= DD * NCAT / 4) return;
    int n = (idx % (NCAT / 4)) * 4;
    int k = idx / (NCAT / 4);
    float4 v;
    if      (n < 1024) v = *(const float4*)(Wq + (size_t)k * DKK + n);
    else if (n < 2048) v = *(const float4*)(Wk + (size_t)k * DKK + (n - 1024));
    else if (n < 4096) v = *(const float4*)(Wv + (size_t)k * DVV + (n - 2048));
    else               v = *(const float4*)(Wg + (size_t)k * DVV + (n - 4096));
    *(float4*)(g_wcat + (size_t)k * NCAT + n) = v;
}

// ---------------- W2 = Wv @ router_w (fp32 exact, [2048][32]) --------------
__global__ void w2_kernel(const float* __restrict__ Wv,
                          const float* __restrict__ rw) {
    int k  = blockIdx.x;          // 2048 blocks
    int t  = threadIdx.x;         // 32 threads: h*2+r
    int h  = t >> 1, r = t & 1;
    const float* wrow = Wv + (size_t)k * DVV + h * HDVV;
    const float* rr   = rw + (h * HDVV) * 2 + r;
    float acc = 0.f;
    #pragma unroll 8
    for (int d = 0; d < HDVV; d++)
        acc += wrow[d] * rr[2 * d];
    g_w2[k * 32 + t] = acc;
}

// ---------------- router logits = xc @ W2 (fp32 exact, [2048][32]) ---------
__global__ void rlog_kernel() {
    int tid = threadIdx.x;
    int hr  = tid & 31;
    int l   = blockIdx.x * 8 + (tid >> 5);
    const float* xrow = g_xc + (size_t)l * DD;
    float acc = 0.f;
    #pragma unroll 4
    for (int k = 0; k < DD; k++)
        acc += xrow[k] * g_w2[k * 32 + hr];
    g_rlog[l * 32 + hr] = acc;
}

// ---------------- tensor-core GEMM (TF32): C = A @ B, row-major ------------
#define AP 36
#define BPAD 136
#define STGF (128*AP + 32*BPAD)       // floats per stage = 8960
#define SMEM_GEMM (2 * STGF * 4)      // 71680 bytes

__global__ __launch_bounds__(256, 2) void gemm_tc(
        const float* __restrict__ A,
        const float* __restrict__ B,
        float* __restrict__ C,
        int M, int N, int K, int silu_ncols) {
    extern __shared__ float sm[];

    int tid = threadIdx.x, lane = tid & 31, warp = tid >> 5;
    int bm = blockIdx.y * 128, bn = blockIdx.x * 128;
    int wm = (warp >> 2) * 64, wn = (warp & 3) * 32;
    int g = lane >> 2, t = lane & 3;

    float acc[4][4][4];
    #pragma unroll
    for (int i = 0; i < 4; i++)
        #pragma unroll
        for (int j = 0; j < 4; j++)
            #pragma unroll
            for (int r = 0; r < 4; r++) acc[i][j][r] = 0.f;

    const float* agp[4];
    const float* bgp[4];
    int asp[4], bsp[4];
    #pragma unroll
    for (int i = 0; i < 4; i++) {
        int idx = tid + i * 256;
        int ar = idx >> 3, ac = (idx & 7) * 4;
        int br = idx >> 5, bc = (idx & 31) * 4;
        agp[i] = A + (size_t)(bm + ar) * K + ac;
        bgp[i] = B + (size_t)br * N + bn + bc;
        asp[i] = ar * AP + ac;
        bsp[i] = 128 * AP + br * BPAD + bc;
    }

#define LOAD_STAGE(s, k0) do {                                          \
        float* base_ = sm + (s) * STGF;                                 \
        _Pragma("unroll")                                               \
        for (int i_ = 0; i_ < 4; i_++) {                                \
            cp16(base_ + asp[i_], agp[i_] + (k0));                      \
            cp16(base_ + bsp[i_], bgp[i_] + (size_t)(k0) * N);          \
        }                                                               \
        asm volatile("cp.async.commit_group;\n" ::);                    \
    } while (0)

    int nk = K >> 5;
    LOAD_STAGE(0, 0);
    LOAD_STAGE(1, 32);

    for (int kt = 0; kt < nk; kt++) {
        int s = kt & 1;
        asm volatile("cp.async.wait_group 1;\n" ::);
        __syncthreads();
        const float* Ah = sm + s * STGF;
        const float* Bh = Ah + 128 * AP;

        #pragma unroll
        for (int ko = 0; ko < 32; ko += 8) {
            unsigned af[4][4], bf[4][2];
            #pragma unroll
            for (int fm = 0; fm < 4; fm++) {
                int r0 = wm + fm * 16 + g;
                af[fm][0] = f2tf(Ah[ r0      * AP + ko + t]);
                af[fm][1] = f2tf(Ah[(r0 + 8) * AP + ko + t]);
                af[fm][2] = f2tf(Ah[ r0      * AP + ko + t + 4]);
                af[fm][3] = f2tf(Ah[(r0 + 8) * AP + ko + t + 4]);
            }
            #pragma unroll
            for (int fn = 0; fn < 4; fn++) {
                int c0 = wn + fn * 8 + g;
                bf[fn][0] = f2tf(Bh[(ko + t    ) * BPAD + c0]);
                bf[fn][1] = f2tf(Bh[(ko + t + 4) * BPAD + c0]);
            }
            #pragma unroll
            for (int fm = 0; fm < 4; fm++)
                #pragma unroll
                for (int fn = 0; fn < 4; fn++)
                    mma8(acc[fm][fn], af[fm][0], af[fm][1], af[fm][2], af[fm][3],
                         bf[fn][0], bf[fn][1]);
        }
        __syncthreads();
        if (kt + 2 < nk) LOAD_STAGE(s, (kt + 2) * 32);
    }

    #pragma unroll
    for (int fm = 0; fm < 4; fm++) {
        int r0 = bm + wm + fm * 16 + g;
        #pragma unroll
        for (int fn = 0; fn < 4; fn++) {
            int c0 = bn + wn + fn * 8 + 2 * t;
            float v0 = acc[fm][fn][0], v1 = acc[fm][fn][1];
            float v2 = acc[fm][fn][2], v3 = acc[fm][fn][3];
            if (c0 < silu_ncols) {
                v0 = silu_f(v0); v1 = silu_f(v1);
                v2 = silu_f(v2); v3 = silu_f(v3);
            }
            *(float2*)(C + (size_t)r0 * N + c0)       = make_float2(v0, v1);
            *(float2*)(C + (size_t)(r0 + 8) * N + c0) = make_float2(v2, v3);
        }
    }
}

// ---------------- stage 3: RoPE + hi/lo split to head-major buffers --------
__global__ void rope_split_kernel() {
    int idx = blockIdx.x * blockDim.x + threadIdx.x;   // L*H*32
    if (idx >= LL * HH * 32) return;
    int i  = idx & 31;
    int lh = idx >> 5;
    int h  = lh & (HH-1);
    int l  = lh >> 4;
    float invf = powf(10000.f, -(float)i / 32.f);
    float ang = (float)l * invf;
    float c = cosf(ang), s = sinf(ang);
    size_t qb = (size_t)l * NCAT + h * HDKK;
    size_t kb = qb + DKK;
    size_t ob = ((size_t)h * LL + l) * HDKK;
    float q1 = g_qkvg[qb + i], q2 = g_qkvg[qb + 32 + i];
    float k1 = g_qkvg[kb + i], k2 = g_qkvg[kb + 32 + i];
    float qa = q1 * c - q2 * s, qbv = q2 * c + q1 * s;
    float ka = k1 * c - k2 * s, kbv = k2 * c + k1 * s;
    float hi, lo;
    split_tf(qa, hi, lo);  g_qh[ob + i]      = hi;  g_ql[ob + i]      = lo;
    split_tf(qbv, hi, lo); g_qh[ob + 32 + i] = hi;  g_ql[ob + 32 + i] = lo;
    split_tf(ka, hi, lo);  g_kh[ob + i]      = hi;  g_kl[ob + i]      = lo;
    split_tf(kbv, hi, lo); g_kh[ob + 32 + i] = hi;  g_kl[ob + 32 + i] = lo;
}

// ---------------- v hi/lo split to head-major ------------------------------
__global__ void vsplit_kernel() {
    int idx = blockIdx.x * blockDim.x + threadIdx.x;   // L*DVV
    if (idx >= LL * DVV) return;
    int l  = idx >> 11;
    int hc = idx & (DVV-1);
    int h  = hc >> 7, c = hc & 127;
    float v = g_qkvg[(size_t)l * NCAT + 2*DKK + hc];
    float hi, lo; split_tf(v, hi, lo);
    size_t ob = ((size_t)h * LL + l) * HDVV + c;
    g_vh[ob] = hi;
    g_vl[ob] = lo;
}

// ---------------- stage 4: router decision + sequential count scan ---------
__global__ void router_kernel() {
    int h = blockIdx.x;                    // 16 blocks, 256 threads
    __shared__ float s_score[LL];
    __shared__ int   s_sel[LL];
    for (int l = threadIdx.x; l < LL; l += blockDim.x) {
        float z0 = g_rlog[l * 32 + h * 2 + 0];
        float z1 = g_rlog[l * 32 + h * 2 + 1];
        int sel = (z1 > z0) ? 1 : 0;
        float m = fmaxf(z0, z1);
        float e0 = expf(z0 - m), e1 = expf(z1 - m);
        s_sel[l]   = sel;
        s_score[l] = ((sel == 0) ? e0 : e1) / (e0 + e1);
    }
    __syncthreads();
    if (threadIdx.x == 0) {
        int c0 = 0, c1 = 0;
        const float scale = 0.125f;   // HDK^{-1/2}
        for (int l = 0; l < LL; l++) {
            int sel = s_sel[l];
            int cnt;
            if (sel == 0) { c0++; cnt = c0; } else { c1++; cnt = c1; }
            g_rsel[h * LL + l] = sel;
            g_coef[h * LL + l] = s_score[l] / (float)cnt * scale;
        }
    }
}

// ---------------- stage 5: tensor-core attention (cp.async pipelined) ------
#define ST 68
#define VT 136
// float offsets
#define AQH 0
#define AQL (AQH + 64*ST)
#define AKB (AQL + 64*ST)          // K: 2 stages x (hi, lo), each 64*ST
#define AKSTG (2*64*ST)
#define ASH (AKB + 2*AKSTG)
#define ASL (ASH + 64*ST)
#define AVH (ASL + 64*ST)
#define AVL (AVH + 64*VT)
#define ACF (AVL + 64*VT)
#define ARR (ACF + 64)
#define ARC (ARR + 64)
#define ATTN3_FLOATS (ARC + 64)
#define ATTN3_BYTES  (ATTN3_FLOATS * 4)   // ~209.7 KB

__global__ __launch_bounds__(256, 1) void attn_tc() {
    extern __shared__ float smf[];
    float* Qh = smf + AQH;  float* Ql = smf + AQL;
    float* Sh = smf + ASH;  float* Sl = smf + ASL;
    float* Vh = smf + AVH;  float* Vl = smf + AVL;
    float* coef_r = smf + ACF;
    int*   rsel_r = (int*)(smf + ARR);
    int*   rsel_c = (int*)(smf + ARC);

    int h   = blockIdx.y;
    int l0  = (gridDim.x - 1 - blockIdx.x) * 64;   // heavy tiles first
    int tid = threadIdx.x, lane = tid & 31, warp = tid >> 5;
    int g = lane >> 2, t = lane & 3;
    int wm  = (warp >> 1) * 16;
    int wns = (warp & 1) * 32;
    int wno = (warp & 1) * 64;

    const float* Kh_g = g_kh + ((size_t)h * LL) * HDKK;
    const float* Kl_g = g_kl + ((size_t)h * LL) * HDKK;
    const float* Vh_g = g_vh + ((size_t)h * LL) * HDVV;
    const float* Vl_g = g_vl + ((size_t)h * LL) * HDVV;

    // K-copy slots: 4 chunks hi + 4 lo per thread
    int kr[4], kc[4];
    #pragma unroll
    for (int i = 0; i < 4; i++) {
        int idx = tid + i * 256;
        kr[i] = idx >> 4; kc[i] = (idx & 15) * 4;
    }
    // V-copy slots: 8 chunks hi + 8 lo per thread
    int vr[8], vc[8];
    #pragma unroll
    for (int i = 0; i < 8; i++) {
        int idx = tid + i * 256;
        vr[i] = idx >> 5; vc[i] = (idx & 31) * 4;
    }

#define LOAD_K(s, m0) do {                                                  \
        float* kh_ = smf + AKB + (s) * AKSTG;                               \
        float* kl_ = kh_ + 64*ST;                                           \
        _Pragma("unroll")                                                   \
        for (int i_ = 0; i_ < 4; i_++) {                                    \
            cp16(kh_ + kr[i_]*ST + kc[i_], Kh_g + (size_t)((m0)+kr[i_])*HDKK + kc[i_]); \
            cp16(kl_ + kr[i_]*ST + kc[i_], Kl_g + (size_t)((m0)+kr[i_])*HDKK + kc[i_]); \
        }                                                                   \
        asm volatile("cp.async.commit_group;\n" ::);                        \
    } while (0)

#define LOAD_V(m0) do {                                                     \
        _Pragma("unroll")                                                   \
        for (int i_ = 0; i_ < 8; i_++) {                                    \
            cp16(Vh + vr[i_]*VT + vc[i_], Vh_g + (size_t)((m0)+vr[i_])*HDVV + vc[i_]); \
            cp16(Vl + vr[i_]*VT + vc[i_], Vl_g + (size_t)((m0)+vr[i_])*HDVV + vc[i_]); \
        }                                                                   \
        asm volatile("cp.async.commit_group;\n" ::);                        \
    } while (0)

    // prologue: K(0) in flight, load Q + metadata
    LOAD_K(0, 0);
    for (int i = tid; i < 64 * 16; i += 256) {
        int r = i >> 4, c4 = (i & 15) * 4;
        size_t gq = ((size_t)h * LL + l0 + r) * HDKK + c4;
        *(float4*)(Qh + r * ST + c4) = *(const float4*)(g_qh + gq);
        *(float4*)(Ql + r * ST + c4) = *(const float4*)(g_ql + gq);
    }
    if (tid < 64) {
        rsel_r[tid] = g_rsel[h * LL + l0 + tid];
        coef_r[tid] = g_coef[h * LL + l0 + tid];
    }

    float acc_o[8][4];
    #pragma unroll
    for (int fn = 0; fn < 8; fn++)
        #pragma unroll
        for (int r = 0; r < 4; r++) acc_o[fn][r] = 0.f;

    int ntiles = (l0 >> 6) + 1;
    for (int mt = 0; mt < ntiles; mt++) {
        int m0 = mt * 64;
        int s  = mt & 1;
        __syncthreads();                    // V/S from previous iter fully read
        LOAD_V(m0);                         // V load overlaps QK below
        if (tid < 64) rsel_c[tid] = g_rsel[h * LL + m0 + tid];
        asm volatile("cp.async.wait_group 1;\n" ::);   // K(mt) done
        __syncthreads();

        const float* Kts = smf + AKB + s * AKSTG;
        const float* Kls = Kts + 64*ST;

        // ---- QK^T: warp tile 16x32 ----
        float acc_s[4][4];
        #pragma unroll
        for (int fn = 0; fn < 4; fn++)
            #pragma unroll
            for (int r = 0; r < 4; r++) acc_s[fn][r] = 0.f;

        #pragma unroll
        for (int ko = 0; ko < 64; ko += 8) {
            int r0 = wm + g;
            unsigned ah[4], al[4];
            ah[0] = __float_as_uint(Qh[ r0      * ST + ko + t]);
            ah[1] = __float_as_uint(Qh[(r0 + 8) * ST + ko + t]);
            ah[2] = __float_as_uint(Qh[ r0      * ST + ko + t + 4]);
            ah[3] = __float_as_uint(Qh[(r0 + 8) * ST + ko + t + 4]);
            al[0] = __float_as_uint(Ql[ r0      * ST + ko + t]);
            al[1] = __float_as_uint(Ql[(r0 + 8) * ST + ko + t]);
            al[2] = __float_as_uint(Ql[ r0      * ST + ko + t + 4]);
            al[3] = __float_as_uint(Ql[(r0 + 8) * ST + ko + t + 4]);
            #pragma unroll
            for (int fn = 0; fn < 4; fn++) {
                int c0 = wns + fn * 8 + g;
                unsigned bh0 = __float_as_uint(Kts[c0 * ST + ko + t]);
                unsigned bh1 = __float_as_uint(Kts[c0 * ST + ko + t + 4]);
                unsigned bl0 = __float_as_uint(Kls[c0 * ST + ko + t]);
                unsigned bl1 = __float_as_uint(Kls[c0 * ST + ko + t + 4]);
                mma8(acc_s[fn], ah[0], ah[1], ah[2], ah[3], bh0, bh1);
                mma8(acc_s[fn], ah[0], ah[1], ah[2], ah[3], bl0, bl1);
                mma8(acc_s[fn], al[0], al[1], al[2], al[3], bh0, bh1);
            }
        }

        // prefetch K(mt+1) — K(mt) reads are done
        if (mt + 1 < ntiles) LOAD_K(s ^ 1, m0 + 64);

        // ---- mask + coef, split-store S ----
        {
            int r0 = wm + g, r1 = r0 + 8;
            int gl0 = l0 + r0, gl1 = l0 + r1;
            int e0 = rsel_r[r0], e1 = rsel_r[r1];
            float cf0 = coef_r[r0], cf1 = coef_r[r1];
            #pragma unroll
            for (int fn = 0; fn < 4; fn++) {
                int c = wns + fn * 8 + 2 * t;
                int gm0 = m0 + c, gm1 = gm0 + 1;
                int ec0 = rsel_c[c], ec1 = rsel_c[c + 1];
                float s00 = (gm0 <= gl0 && ec0 == e0) ? acc_s[fn][0] * cf0 : 0.f;
                float s01 = (gm1 <= gl0 && ec1 == e0) ? acc_s[fn][1] * cf0 : 0.f;
                float s10 = (gm0 <= gl1 && ec0 == e1) ? acc_s[fn][2] * cf1 : 0.f;
                float s11 = (gm1 <= gl1 && ec1 == e1) ? acc_s[fn][3] * cf1 : 0.f;
                float h00, l00, h01, l01, h10, l10, h11, l11;
                split_tf(s00, h00, l00); split_tf(s01, h01, l01);
                split_tf(s10, h10, l10); split_tf(s11, h11, l11);
                *(float2*)&Sh[r0 * ST + c] = make_float2(h00, h01);
                *(float2*)&Sl[r0 * ST + c] = make_float2(l00, l01);
                *(float2*)&Sh[r1 * ST + c] = make_float2(h10, h11);
                *(float2*)&Sl[r1 * ST + c] = make_float2(l10, l11);
            }
        }
        asm volatile("cp.async.wait_group 1;\n" ::);   // V(mt) done (K(mt+1) pending)
        __syncthreads();                               // S + V visible

        // ---- O += S @ V: warp tile 16x64 ----
        #pragma unroll
        for (int ko = 0; ko < 64; ko += 8) {
            int r0 = wm + g;
            unsigned ah[4], al[4];
            ah[0] = __float_as_uint(Sh[ r0      * ST + ko + t]);
            ah[1] = __float_as_uint(Sh[(r0 + 8) * ST + ko + t]);
            ah[2] = __float_as_uint(Sh[ r0      * ST + ko + t + 4]);
            ah[3] = __float_as_uint(Sh[(r0 + 8) * ST + ko + t + 4]);
            al[0] = __float_as_uint(Sl[ r0      * ST + ko + t]);
            al[1] = __float_as_uint(Sl[(r0 + 8) * ST + ko + t]);
            al[2] = __float_as_uint(Sl[ r0      * ST + ko + t + 4]);
            al[3] = __float_as_uint(Sl[(r0 + 8) * ST + ko + t + 4]);
            #pragma unroll
            for (int fn = 0; fn < 8; fn++) {
                int c0 = wno + fn * 8 + g;
                unsigned bh0 = __float_as_uint(Vh[(ko + t    ) * VT + c0]);
                unsigned bh1 = __float_as_uint(Vh[(ko + t + 4) * VT + c0]);
                unsigned bl0 = __float_as_uint(Vl[(ko + t    ) * VT + c0]);
                unsigned bl1 = __float_as_uint(Vl[(ko + t + 4) * VT + c0]);
                mma8(acc_o[fn], ah[0], ah[1], ah[2], ah[3], bh0, bh1);
                mma8(acc_o[fn], ah[0], ah[1], ah[2], ah[3], bl0, bl1);
                mma8(acc_o[fn], al[0], al[1], al[2], al[3], bh0, bh1);
            }
        }
    }

    // ---- store O ----
    int r0 = wm + g;
    #pragma unroll
    for (int fn = 0; fn < 8; fn++) {
        int c = wno + fn * 8 + 2 * t;
        *(float2*)(g_o + (size_t)(l0 + r0    ) * DVV + h * HDVV + c)
            = make_float2(acc_o[fn][0], acc_o[fn][1]);
        *(float2*)(g_o + (size_t)(l0 + r0 + 8) * DVV + h * HDVV + c)
            = make_float2(acc_o[fn][2], acc_o[fn][3]);
    }
}

// ---------------- stage 6: LayerNorm(128) * silu(gate) ---------------------
__global__ void ln_gate_kernel() {
    int h = blockIdx.x;
    int l = blockIdx.y;
    int j = threadIdx.x;    // 128
    size_t obase = (size_t)l * DVV + h * HDVV;
    float o = g_o[obase + j];
    float sum = o, sumsq = o * o;
    #pragma unroll
    for (int off = 16; off; off >>= 1) {
        sum   += __shfl_down_sync(0xffffffffu, sum,   off);
        sumsq += __shfl_down_sync(0xffffffffu, sumsq, off);
    }
    __shared__ float s1[4], s2[4];
    if ((j & 31) == 0) { s1[j >> 5] = sum; s2[j >> 5] = sumsq; }
    __syncthreads();
    float tot   = s1[0] + s1[1] + s1[2] + s1[3];
    float totsq = s2[0] + s2[1] + s2[2] + s2[3];
    float mu  = tot * (1.f / 128.f);
    float var = totsq * (1.f / 128.f) - mu * mu;
    float inv = rsqrtf(var + 1e-5f);
    float gt  = g_qkvg[(size_t)l * NCAT + 2*DKK + DVV + h * HDVV + j];
    g_y[obase + j] = silu_f(gt) * (o - mu) * inv;
}

// ---------------- launch ----------------------------------------------------
extern "C" void kernel_launch(void* const* d_in, const int* in_sizes, int n_in,
                              void* d_out, int out_size) {
    const float* x    = (const float*)d_in[0];
    const float* cw   = (const float*)d_in[1];
    const float* Wq   = (const float*)d_in[2];
    const float* Wk   = (const float*)d_in[3];
    const float* Wv   = (const float*)d_in[4];
    const float* Wg   = (const float*)d_in[5];
    const float* rw   = (const float*)d_in[6];
    const float* Wout = (const float*)d_in[7];
    float* out = (float*)d_out;

    float *p_xc, *p_wcat, *p_qkvg, *p_y;
    cudaGetSymbolAddress((void**)&p_xc,   g_xc);
    cudaGetSymbolAddress((void**)&p_wcat, g_wcat);
    cudaGetSymbolAddress((void**)&p_qkvg, g_qkvg);
    cudaGetSymbolAddress((void**)&p_y,    g_y);

    cudaFuncSetAttribute(attn_tc,
                         cudaFuncAttributeMaxDynamicSharedMemorySize, ATTN3_BYTES);
    cudaFuncSetAttribute(gemm_tc,
                         cudaFuncAttributeMaxDynamicSharedMemorySize, SMEM_GEMM);

    conv_silu_kernel<<<(LL*DD)/256, 256>>>(x, cw);
    wcat_kernel<<<(DD*NCAT/4 + 255)/256, 256>>>(Wq, Wk, Wv, Wg);
    w2_kernel<<<DD, 32>>>(Wv, rw);

    // fused QKVG projection (silu on q columns)
    gemm_tc<<<dim3(NCAT/128, LL/128), 256, SMEM_GEMM>>>(p_xc, p_wcat, p_qkvg,
                                                        LL, NCAT, DD, DKK);
    rlog_kernel<<<LL/8, 256>>>();

    rope_split_kernel<<<(LL*HH*32)/256, 256>>>();
    vsplit_kernel<<<(LL*DVV)/256, 256>>>();
    router_kernel<<<HH, 256>>>();

    attn_tc<<<dim3(LL/64, HH), 256, ATTN3_BYTES>>>();

    ln_gate_kernel<<<dim3(HH, LL), 128>>>();

    gemm_tc<<<dim3(DD/128, LL/128), 256, SMEM_GEMM>>>(p_y, Wout, out,
                                                      LL, DD, DVV, 0);
}

// round 8
// speedup vs baseline: 3.3334x; 1.0242x over previous
#include <cuda_runtime.h>
#include <math.h>

#define LL   2048
#define DD   2048
#define HH   16
#define DKK  1024
#define DVV  2048
#define HDKK 64
#define HDVV 128
#define NCAT 6144              // q(1024) | k(1024) | v(2048) | g(2048)

// ---------------- scratch (device globals; no allocation allowed) ----------
__device__ float g_xc  [LL*DD];      // conv+silu output (fp32 exact, for router)
__device__ float g_xctf[LL*DD];      // conv+silu output, tf32-rounded (GEMM A)
__device__ float g_wcat[DD*NCAT];    // Wq|Wk|Wv|Wg concatenated, tf32-rounded
__device__ float g_wtf [DD*DD];      // Wout tf32-rounded
__device__ float g_qkvg[LL*NCAT];    // fused projection output
__device__ float g_w2  [DD*32];      // Wv @ router_w  (fp32 exact)
__device__ float g_rlog[LL*32];      // router logits  (fp32 exact)
__device__ float g_qh  [LL*DKK];     // roped q, hi part, head-major
__device__ float g_ql  [LL*DKK];     // roped q, lo part
__device__ float g_kh  [LL*DKK];     // roped k, hi part
__device__ float g_kl  [LL*DKK];     // roped k, lo part
__device__ float g_vh  [LL*DVV];     // v hi, head-major
__device__ float g_vl  [LL*DVV];     // v lo
__device__ float g_o   [LL*DVV];     // attention output
__device__ float g_y   [LL*DVV];     // silu(g)*LN(o), tf32-rounded
__device__ float g_coef[HH*LL];      // score_max/count * HDK^-0.5
__device__ int   g_rsel[HH*LL];      // selected expert per (h,l)

__device__ __forceinline__ float silu_f(float z) { return z / (1.f + expf(-z)); }

__device__ __forceinline__ unsigned f2tf(float f) {
    unsigned r;
    asm("cvt.rna.tf32.f32 %0, %1;" : "=r"(r) : "f"(f));
    return r;
}

__device__ __forceinline__ float tf32r(float f) { return __uint_as_float(f2tf(f)); }

__device__ __forceinline__ void split_tf(float v, float& hi, float& lo) {
    hi = __uint_as_float(f2tf(v));
    lo = __uint_as_float(f2tf(v - hi));
}

__device__ __forceinline__ void mma8(float* c,
                                     unsigned a0, unsigned a1, unsigned a2, unsigned a3,
                                     unsigned b0, unsigned b1) {
    asm("mma.sync.aligned.m16n8k8.row.col.f32.tf32.tf32.f32 "
        "{%0,%1,%2,%3}, {%4,%5,%6,%7}, {%8,%9}, {%0,%1,%2,%3};"
        : "+f"(c[0]), "+f"(c[1]), "+f"(c[2]), "+f"(c[3])
        : "r"(a0), "r"(a1), "r"(a2), "r"(a3), "r"(b0), "r"(b1));
}

__device__ __forceinline__ void cp16(float* smem_dst, const float* gsrc) {
    unsigned sa = (unsigned)__cvta_generic_to_shared(smem_dst);
    asm volatile("cp.async.cg.shared.global [%0], [%1], 16;\n"
                 :: "r"(sa), "l"(gsrc));
}

// ---------------- stage 1: shifted conv + silu -----------------------------
__global__ void conv_silu_kernel(const float* __restrict__ x,
                                 const float* __restrict__ cw) {
    int idx = blockIdx.x * blockDim.x + threadIdx.x;  // over L*D
    if (idx >= LL*DD) return;
    int d = idx & (DD-1);
    int l = idx >> 11;
    float prev = (l == 0) ? 0.f : x[idx - DD];
    float z = prev * cw[2*d] + x[idx] * cw[2*d + 1];
    float v = silu_f(z);
    g_xc[idx]   = v;
    g_xctf[idx] = tf32r(v);
}

// ---------------- weight concat (tf32-rounded): Wq|Wk|Wv|Wg ---------------
__global__ void wcat_kernel(const float* __restrict__ Wq,
                            const float* __restrict__ Wk,
                            const float* __restrict__ Wv,
                            const float* __restrict__ Wg) {
    int idx = blockIdx.x * blockDim.x + threadIdx.x;   // over DD*NCAT/4
    if (idx >= DD * NCAT / 4) return;
    int n = (idx % (NCAT / 4)) * 4;
    int k = idx / (NCAT / 4);
    float4 v;
    if      (n < 1024) v = *(const float4*)(Wq + (size_t)k * DKK + n);
    else if (n < 2048) v = *(const float4*)(Wk + (size_t)k * DKK + (n - 1024));
    else if (n < 4096) v = *(const float4*)(Wv + (size_t)k * DVV + (n - 2048));
    else               v = *(const float4*)(Wg + (size_t)k * DVV + (n - 4096));
    v.x = tf32r(v.x); v.y = tf32r(v.y); v.z = tf32r(v.z); v.w = tf32r(v.w);
    *(float4*)(g_wcat + (size_t)k * NCAT + n) = v;
}

// ---------------- Wout tf32-rounded copy -----------------------------------
__global__ void wout_kernel(const float* __restrict__ Wout) {
    int idx = blockIdx.x * blockDim.x + threadIdx.x;   // over DD*DD/4
    if (idx >= DD * DD / 4) return;
    float4 v = *(const float4*)(Wout + (size_t)idx * 4);
    v.x = tf32r(v.x); v.y = tf32r(v.y); v.z = tf32r(v.z); v.w = tf32r(v.w);
    *(float4*)(g_wtf + (size_t)idx * 4) = v;
}

// ---------------- W2 = Wv @ router_w (fp32 exact, [2048][32]) --------------
__global__ void w2_kernel(const float* __restrict__ Wv,
                          const float* __restrict__ rw) {
    int k  = blockIdx.x;          // 2048 blocks
    int t  = threadIdx.x;         // 32 threads: h*2+r
    int h  = t >> 1, r = t & 1;
    const float* wrow = Wv + (size_t)k * DVV + h * HDVV;
    const float* rr   = rw + (h * HDVV) * 2 + r;
    float acc = 0.f;
    #pragma unroll 8
    for (int d = 0; d < HDVV; d++)
        acc += wrow[d] * rr[2 * d];
    g_w2[k * 32 + t] = acc;
}

// ---------------- router logits = xc @ W2 (fp32 exact, [2048][32]) ---------
__global__ void rlog_kernel() {
    int tid = threadIdx.x;
    int hr  = tid & 31;
    int l   = blockIdx.x * 8 + (tid >> 5);
    const float* xrow = g_xc + (size_t)l * DD;
    float acc = 0.f;
    #pragma unroll 4
    for (int k = 0; k < DD; k++)
        acc += xrow[k] * g_w2[k * 32 + hr];
    g_rlog[l * 32 + hr] = acc;
}

// ---------------- tensor-core GEMM (TF32, pre-rounded operands) ------------
#define AP 36
#define BPAD 136
#define STGF (128*AP + 32*BPAD)       // floats per stage = 8960
#define SMEM_GEMM (2 * STGF * 4)      // 71680 bytes

__global__ __launch_bounds__(256, 2) void gemm_tc(
        const float* __restrict__ A,
        const float* __restrict__ B,
        float* __restrict__ C,
        int M, int N, int K, int silu_ncols) {
    extern __shared__ float sm[];

    int tid = threadIdx.x, lane = tid & 31, warp = tid >> 5;
    int bm = blockIdx.y * 128, bn = blockIdx.x * 128;
    int wm = (warp >> 2) * 64, wn = (warp & 3) * 32;
    int g = lane >> 2, t = lane & 3;

    float acc[4][4][4];
    #pragma unroll
    for (int i = 0; i < 4; i++)
        #pragma unroll
        for (int j = 0; j < 4; j++)
            #pragma unroll
            for (int r = 0; r < 4; r++) acc[i][j][r] = 0.f;

    const float* agp[4];
    const float* bgp[4];
    int asp[4], bsp[4];
    #pragma unroll
    for (int i = 0; i < 4; i++) {
        int idx = tid + i * 256;
        int ar = idx >> 3, ac = (idx & 7) * 4;
        int br = idx >> 5, bc = (idx & 31) * 4;
        agp[i] = A + (size_t)(bm + ar) * K + ac;
        bgp[i] = B + (size_t)br * N + bn + bc;
        asp[i] = ar * AP + ac;
        bsp[i] = 128 * AP + br * BPAD + bc;
    }

#define LOAD_STAGE(s, k0) do {                                          \
        float* base_ = sm + (s) * STGF;                                 \
        _Pragma("unroll")                                               \
        for (int i_ = 0; i_ < 4; i_++) {                                \
            cp16(base_ + asp[i_], agp[i_] + (k0));                      \
            cp16(base_ + bsp[i_], bgp[i_] + (size_t)(k0) * N);          \
        }                                                               \
        asm volatile("cp.async.commit_group;\n" ::);                    \
    } while (0)

    int nk = K >> 5;
    LOAD_STAGE(0, 0);
    LOAD_STAGE(1, 32);

    for (int kt = 0; kt < nk; kt++) {
        int s = kt & 1;
        asm volatile("cp.async.wait_group 1;\n" ::);
        __syncthreads();
        const float* Ah = sm + s * STGF;
        const float* Bh = Ah + 128 * AP;

        #pragma unroll
        for (int ko = 0; ko < 32; ko += 8) {
            unsigned af[4][4], bf[4][2];
            #pragma unroll
            for (int fm = 0; fm < 4; fm++) {
                int r0 = wm + fm * 16 + g;
                af[fm][0] = __float_as_uint(Ah[ r0      * AP + ko + t]);
                af[fm][1] = __float_as_uint(Ah[(r0 + 8) * AP + ko + t]);
                af[fm][2] = __float_as_uint(Ah[ r0      * AP + ko + t + 4]);
                af[fm][3] = __float_as_uint(Ah[(r0 + 8) * AP + ko + t + 4]);
            }
            #pragma unroll
            for (int fn = 0; fn < 4; fn++) {
                int c0 = wn + fn * 8 + g;
                bf[fn][0] = __float_as_uint(Bh[(ko + t    ) * BPAD + c0]);
                bf[fn][1] = __float_as_uint(Bh[(ko + t + 4) * BPAD + c0]);
            }
            #pragma unroll
            for (int fm = 0; fm < 4; fm++)
                #pragma unroll
                for (int fn = 0; fn < 4; fn++)
                    mma8(acc[fm][fn], af[fm][0], af[fm][1], af[fm][2], af[fm][3],
                         bf[fn][0], bf[fn][1]);
        }
        __syncthreads();
        if (kt + 2 < nk) LOAD_STAGE(s, (kt + 2) * 32);
    }

    #pragma unroll
    for (int fm = 0; fm < 4; fm++) {
        int r0 = bm + wm + fm * 16 + g;
        #pragma unroll
        for (int fn = 0; fn < 4; fn++) {
            int c0 = bn + wn + fn * 8 + 2 * t;
            float v0 = acc[fm][fn][0], v1 = acc[fm][fn][1];
            float v2 = acc[fm][fn][2], v3 = acc[fm][fn][3];
            if (c0 < silu_ncols) {
                v0 = silu_f(v0); v1 = silu_f(v1);
                v2 = silu_f(v2); v3 = silu_f(v3);
            }
            *(float2*)(C + (size_t)r0 * N + c0)       = make_float2(v0, v1);
            *(float2*)(C + (size_t)(r0 + 8) * N + c0) = make_float2(v2, v3);
        }
    }
}

// ---------------- stage 3: RoPE + hi/lo split to head-major buffers --------
__global__ void rope_split_kernel() {
    int idx = blockIdx.x * blockDim.x + threadIdx.x;   // L*H*32
    if (idx >= LL * HH * 32) return;
    int i  = idx & 31;
    int lh = idx >> 5;
    int h  = lh & (HH-1);
    int l  = lh >> 4;
    float invf = powf(10000.f, -(float)i / 32.f);
    float ang = (float)l * invf;
    float c = cosf(ang), s = sinf(ang);
    size_t qb = (size_t)l * NCAT + h * HDKK;
    size_t kb = qb + DKK;
    size_t ob = ((size_t)h * LL + l) * HDKK;
    float q1 = g_qkvg[qb + i], q2 = g_qkvg[qb + 32 + i];
    float k1 = g_qkvg[kb + i], k2 = g_qkvg[kb + 32 + i];
    float qa = q1 * c - q2 * s, qbv = q2 * c + q1 * s;
    float ka = k1 * c - k2 * s, kbv = k2 * c + k1 * s;
    float hi, lo;
    split_tf(qa, hi, lo);  g_qh[ob + i]      = hi;  g_ql[ob + i]      = lo;
    split_tf(qbv, hi, lo); g_qh[ob + 32 + i] = hi;  g_ql[ob + 32 + i] = lo;
    split_tf(ka, hi, lo);  g_kh[ob + i]      = hi;  g_kl[ob + i]      = lo;
    split_tf(kbv, hi, lo); g_kh[ob + 32 + i] = hi;  g_kl[ob + 32 + i] = lo;
}

// ---------------- v hi/lo split to head-major ------------------------------
__global__ void vsplit_kernel() {
    int idx = blockIdx.x * blockDim.x + threadIdx.x;   // L*DVV
    if (idx >= LL * DVV) return;
    int l  = idx >> 11;
    int hc = idx & (DVV-1);
    int h  = hc >> 7, c = hc & 127;
    float v = g_qkvg[(size_t)l * NCAT + 2*DKK + hc];
    float hi, lo; split_tf(v, hi, lo);
    size_t ob = ((size_t)h * LL + l) * HDVV + c;
    g_vh[ob] = hi;
    g_vl[ob] = lo;
}

// ---------------- stage 4: router decision + sequential count scan ---------
__global__ void router_kernel() {
    int h = blockIdx.x;                    // 16 blocks, 256 threads
    __shared__ float s_score[LL];
    __shared__ int   s_sel[LL];
    for (int l = threadIdx.x; l < LL; l += blockDim.x) {
        float z0 = g_rlog[l * 32 + h * 2 + 0];
        float z1 = g_rlog[l * 32 + h * 2 + 1];
        int sel = (z1 > z0) ? 1 : 0;
        float m = fmaxf(z0, z1);
        float e0 = expf(z0 - m), e1 = expf(z1 - m);
        s_sel[l]   = sel;
        s_score[l] = ((sel == 0) ? e0 : e1) / (e0 + e1);
    }
    __syncthreads();
    if (threadIdx.x == 0) {
        int c0 = 0, c1 = 0;
        const float scale = 0.125f;   // HDK^{-1/2}
        for (int l = 0; l < LL; l++) {
            int sel = s_sel[l];
            int cnt;
            if (sel == 0) { c0++; cnt = c0; } else { c1++; cnt = c1; }
            g_rsel[h * LL + l] = sel;
            g_coef[h * LL + l] = s_score[l] / (float)cnt * scale;
        }
    }
}

// ---------------- stage 5: tensor-core attention (cp.async pipelined) ------
#define ST 68
#define VT 136
#define AQH 0
#define AQL (AQH + 64*ST)
#define AKB (AQL + 64*ST)          // K: 2 stages x (hi, lo), each 64*ST
#define AKSTG (2*64*ST)
#define ASH (AKB + 2*AKSTG)
#define ASL (ASH + 64*ST)
#define AVH (ASL + 64*ST)
#define AVL (AVH + 64*VT)
#define ACF (AVL + 64*VT)
#define ARR (ACF + 64)
#define ARC (ARR + 64)
#define ATTN3_FLOATS (ARC + 64)
#define ATTN3_BYTES  (ATTN3_FLOATS * 4)

__global__ __launch_bounds__(256, 1) void attn_tc() {
    extern __shared__ float smf[];
    float* Qh = smf + AQH;  float* Ql = smf + AQL;
    float* Sh = smf + ASH;  float* Sl = smf + ASL;
    float* Vh = smf + AVH;  float* Vl = smf + AVL;
    float* coef_r = smf + ACF;
    int*   rsel_r = (int*)(smf + ARR);
    int*   rsel_c = (int*)(smf + ARC);

    int h   = blockIdx.y;
    int l0  = (gridDim.x - 1 - blockIdx.x) * 64;   // heavy tiles first
    int tid = threadIdx.x, lane = tid & 31, warp = tid >> 5;
    int g = lane >> 2, t = lane & 3;
    int wm  = (warp >> 1) * 16;
    int wns = (warp & 1) * 32;
    int wno = (warp & 1) * 64;

    const float* Kh_g = g_kh + ((size_t)h * LL) * HDKK;
    const float* Kl_g = g_kl + ((size_t)h * LL) * HDKK;
    const float* Vh_g = g_vh + ((size_t)h * LL) * HDVV;
    const float* Vl_g = g_vl + ((size_t)h * LL) * HDVV;

    int kr[4], kc[4];
    #pragma unroll
    for (int i = 0; i < 4; i++) {
        int idx = tid + i * 256;
        kr[i] = idx >> 4; kc[i] = (idx & 15) * 4;
    }
    int vr[8], vc[8];
    #pragma unroll
    for (int i = 0; i < 8; i++) {
        int idx = tid + i * 256;
        vr[i] = idx >> 5; vc[i] = (idx & 31) * 4;
    }

#define LOAD_K(s, m0) do {                                                  \
        float* kh_ = smf + AKB + (s) * AKSTG;                               \
        float* kl_ = kh_ + 64*ST;                                           \
        _Pragma("unroll")                                                   \
        for (int i_ = 0; i_ < 4; i_++) {                                    \
            cp16(kh_ + kr[i_]*ST + kc[i_], Kh_g + (size_t)((m0)+kr[i_])*HDKK + kc[i_]); \
            cp16(kl_ + kr[i_]*ST + kc[i_], Kl_g + (size_t)((m0)+kr[i_])*HDKK + kc[i_]); \
        }                                                                   \
        asm volatile("cp.async.commit_group;\n" ::);                        \
    } while (0)

#define LOAD_V(m0) do {                                                     \
        _Pragma("unroll")                                                   \
        for (int i_ = 0; i_ < 8; i_++) {                                    \
            cp16(Vh + vr[i_]*VT + vc[i_], Vh_g + (size_t)((m0)+vr[i_])*HDVV + vc[i_]); \
            cp16(Vl + vr[i_]*VT + vc[i_], Vl_g + (size_t)((m0)+vr[i_])*HDVV + vc[i_]); \
        }                                                                   \
        asm volatile("cp.async.commit_group;\n" ::);                        \
    } while (0)

    LOAD_K(0, 0);
    for (int i = tid; i < 64 * 16; i += 256) {
        int r = i >> 4, c4 = (i & 15) * 4;
        size_t gq = ((size_t)h * LL + l0 + r) * HDKK + c4;
        *(float4*)(Qh + r * ST + c4) = *(const float4*)(g_qh + gq);
        *(float4*)(Ql + r * ST + c4) = *(const float4*)(g_ql + gq);
    }
    if (tid < 64) {
        rsel_r[tid] = g_rsel[h * LL + l0 + tid];
        coef_r[tid] = g_coef[h * LL + l0 + tid];
    }

    float acc_o[8][4];
    #pragma unroll
    for (int fn = 0; fn < 8; fn++)
        #pragma unroll
        for (int r = 0; r < 4; r++) acc_o[fn][r] = 0.f;

    int ntiles = (l0 >> 6) + 1;
    for (int mt = 0; mt < ntiles; mt++) {
        int m0 = mt * 64;
        int s  = mt & 1;
        __syncthreads();
        LOAD_V(m0);
        if (tid < 64) rsel_c[tid] = g_rsel[h * LL + m0 + tid];
        asm volatile("cp.async.wait_group 1;\n" ::);   // K(mt) done
        __syncthreads();

        const float* Kts = smf + AKB + s * AKSTG;
        const float* Kls = Kts + 64*ST;

        float acc_s[4][4];
        #pragma unroll
        for (int fn = 0; fn < 4; fn++)
            #pragma unroll
            for (int r = 0; r < 4; r++) acc_s[fn][r] = 0.f;

        #pragma unroll
        for (int ko = 0; ko < 64; ko += 8) {
            int r0 = wm + g;
            unsigned ah[4], al[4];
            ah[0] = __float_as_uint(Qh[ r0      * ST + ko + t]);
            ah[1] = __float_as_uint(Qh[(r0 + 8) * ST + ko + t]);
            ah[2] = __float_as_uint(Qh[ r0      * ST + ko + t + 4]);
            ah[3] = __float_as_uint(Qh[(r0 + 8) * ST + ko + t + 4]);
            al[0] = __float_as_uint(Ql[ r0      * ST + ko + t]);
            al[1] = __float_as_uint(Ql[(r0 + 8) * ST + ko + t]);
            al[2] = __float_as_uint(Ql[ r0      * ST + ko + t + 4]);
            al[3] = __float_as_uint(Ql[(r0 + 8) * ST + ko + t + 4]);
            #pragma unroll
            for (int fn = 0; fn < 4; fn++) {
                int c0 = wns + fn * 8 + g;
                unsigned bh0 = __float_as_uint(Kts[c0 * ST + ko + t]);
                unsigned bh1 = __float_as_uint(Kts[c0 * ST + ko + t + 4]);
                unsigned bl0 = __float_as_uint(Kls[c0 * ST + ko + t]);
                unsigned bl1 = __float_as_uint(Kls[c0 * ST + ko + t + 4]);
                mma8(acc_s[fn], ah[0], ah[1], ah[2], ah[3], bh0, bh1);
                mma8(acc_s[fn], ah[0], ah[1], ah[2], ah[3], bl0, bl1);
                mma8(acc_s[fn], al[0], al[1], al[2], al[3], bh0, bh1);
            }
        }

        if (mt + 1 < ntiles) LOAD_K(s ^ 1, m0 + 64);

        {
            int r0 = wm + g, r1 = r0 + 8;
            int gl0 = l0 + r0, gl1 = l0 + r1;
            int e0 = rsel_r[r0], e1 = rsel_r[r1];
            float cf0 = coef_r[r0], cf1 = coef_r[r1];
            #pragma unroll
            for (int fn = 0; fn < 4; fn++) {
                int c = wns + fn * 8 + 2 * t;
                int gm0 = m0 + c, gm1 = gm0 + 1;
                int ec0 = rsel_c[c], ec1 = rsel_c[c + 1];
                float s00 = (gm0 <= gl0 && ec0 == e0) ? acc_s[fn][0] * cf0 : 0.f;
                float s01 = (gm1 <= gl0 && ec1 == e0) ? acc_s[fn][1] * cf0 : 0.f;
                float s10 = (gm0 <= gl1 && ec0 == e1) ? acc_s[fn][2] * cf1 : 0.f;
                float s11 = (gm1 <= gl1 && ec1 == e1) ? acc_s[fn][3] * cf1 : 0.f;
                float h00, l00, h01, l01, h10, l10, h11, l11;
                split_tf(s00, h00, l00); split_tf(s01, h01, l01);
                split_tf(s10, h10, l10); split_tf(s11, h11, l11);
                *(float2*)&Sh[r0 * ST + c] = make_float2(h00, h01);
                *(float2*)&Sl[r0 * ST + c] = make_float2(l00, l01);
                *(float2*)&Sh[r1 * ST + c] = make_float2(h10, h11);
                *(float2*)&Sl[r1 * ST + c] = make_float2(l10, l11);
            }
        }
        asm volatile("cp.async.wait_group 1;\n" ::);   // V(mt) done
        __syncthreads();

        #pragma unroll
        for (int ko = 0; ko < 64; ko += 8) {
            int r0 = wm + g;
            unsigned ah[4], al[4];
            ah[0] = __float_as_uint(Sh[ r0      * ST + ko + t]);
            ah[1] = __float_as_uint(Sh[(r0 + 8) * ST + ko + t]);
            ah[2] = __float_as_uint(Sh[ r0      * ST + ko + t + 4]);
            ah[3] = __float_as_uint(Sh[(r0 + 8) * ST + ko + t + 4]);
            al[0] = __float_as_uint(Sl[ r0      * ST + ko + t]);
            al[1] = __float_as_uint(Sl[(r0 + 8) * ST + ko + t]);
            al[2] = __float_as_uint(Sl[ r0      * ST + ko + t + 4]);
            al[3] = __float_as_uint(Sl[(r0 + 8) * ST + ko + t + 4]);
            #pragma unroll
            for (int fn = 0; fn < 8; fn++) {
                int c0 = wno + fn * 8 + g;
                unsigned bh0 = __float_as_uint(Vh[(ko + t    ) * VT + c0]);
                unsigned bh1 = __float_as_uint(Vh[(ko + t + 4) * VT + c0]);
                unsigned bl0 = __float_as_uint(Vl[(ko + t    ) * VT + c0]);
                unsigned bl1 = __float_as_uint(Vl[(ko + t + 4) * VT + c0]);
                mma8(acc_o[fn], ah[0], ah[1], ah[2], ah[3], bh0, bh1);
                mma8(acc_o[fn], ah[0], ah[1], ah[2], ah[3], bl0, bl1);
                mma8(acc_o[fn], al[0], al[1], al[2], al[3], bh0, bh1);
            }
        }
    }

    int r0 = wm + g;
    #pragma unroll
    for (int fn = 0; fn < 8; fn++) {
        int c = wno + fn * 8 + 2 * t;
        *(float2*)(g_o + (size_t)(l0 + r0    ) * DVV + h * HDVV + c)
            = make_float2(acc_o[fn][0], acc_o[fn][1]);
        *(float2*)(g_o + (size_t)(l0 + r0 + 8) * DVV + h * HDVV + c)
            = make_float2(acc_o[fn][2], acc_o[fn][3]);
    }
}

// ---------------- stage 6: LayerNorm(128) * silu(gate), tf32-rounded -------
__global__ void ln_gate_kernel() {
    int h = blockIdx.x;
    int l = blockIdx.y;
    int j = threadIdx.x;    // 128
    size_t obase = (size_t)l * DVV + h * HDVV;
    float o = g_o[obase + j];
    float sum = o, sumsq = o * o;
    #pragma unroll
    for (int off = 16; off; off >>= 1) {
        sum   += __shfl_down_sync(0xffffffffu, sum,   off);
        sumsq += __shfl_down_sync(0xffffffffu, sumsq, off);
    }
    __shared__ float s1[4], s2[4];
    if ((j & 31) == 0) { s1[j >> 5] = sum; s2[j >> 5] = sumsq; }
    __syncthreads();
    float tot   = s1[0] + s1[1] + s1[2] + s1[3];
    float totsq = s2[0] + s2[1] + s2[2] + s2[3];
    float mu  = tot * (1.f / 128.f);
    float var = totsq * (1.f / 128.f) - mu * mu;
    float inv = rsqrtf(var + 1e-5f);
    float gt  = g_qkvg[(size_t)l * NCAT + 2*DKK + DVV + h * HDVV + j];
    g_y[obase + j] = tf32r(silu_f(gt) * (o - mu) * inv);
}

// ---------------- launch ----------------------------------------------------
extern "C" void kernel_launch(void* const* d_in, const int* in_sizes, int n_in,
                              void* d_out, int out_size) {
    const float* x    = (const float*)d_in[0];
    const float* cw   = (const float*)d_in[1];
    const float* Wq   = (const float*)d_in[2];
    const float* Wk   = (const float*)d_in[3];
    const float* Wv   = (const float*)d_in[4];
    const float* Wg   = (const float*)d_in[5];
    const float* rw   = (const float*)d_in[6];
    const float* Wout = (const float*)d_in[7];
    float* out = (float*)d_out;

    float *p_xctf, *p_wcat, *p_wtf, *p_qkvg, *p_y;
    cudaGetSymbolAddress((void**)&p_xctf, g_xctf);
    cudaGetSymbolAddress((void**)&p_wcat, g_wcat);
    cudaGetSymbolAddress((void**)&p_wtf,  g_wtf);
    cudaGetSymbolAddress((void**)&p_qkvg, g_qkvg);
    cudaGetSymbolAddress((void**)&p_y,    g_y);

    cudaFuncSetAttribute(attn_tc,
                         cudaFuncAttributeMaxDynamicSharedMemorySize, ATTN3_BYTES);
    cudaFuncSetAttribute(gemm_tc,
                         cudaFuncAttributeMaxDynamicSharedMemorySize, SMEM_GEMM);

    conv_silu_kernel<<<(LL*DD)/256, 256>>>(x, cw);
    wcat_kernel<<<(DD*NCAT/4 + 255)/256, 256>>>(Wq, Wk, Wv, Wg);
    wout_kernel<<<(DD*DD/4 + 255)/256, 256>>>(Wout);
    w2_kernel<<<DD, 32>>>(Wv, rw);

    // fused QKVG projection (silu on q columns)
    gemm_tc<<<dim3(NCAT/128, LL/128), 256, SMEM_GEMM>>>(p_xctf, p_wcat, p_qkvg,
                                                        LL, NCAT, DD, DKK);
    rlog_kernel<<<LL/8, 256>>>();

    rope_split_kernel<<<(LL*HH*32)/256, 256>>>();
    vsplit_kernel<<<(LL*DVV)/256, 256>>>();
    router_kernel<<<HH, 256>>>();

    attn_tc<<<dim3(LL/64, HH), 256, ATTN3_BYTES>>>();

    ln_gate_kernel<<<dim3(HH, LL), 128>>>();

    gemm_tc<<<dim3(DD/128, LL/128), 256, SMEM_GEMM>>>(p_y, p_wtf, out,
                                                      LL, DD, DVV, 0);
}

// round 9
// speedup vs baseline: 3.8496x; 1.1549x over previous
#include <cuda_runtime.h>
#include <cuda_bf16.h>
#include <math.h>

#define LL   2048
#define DD   2048
#define HH   16
#define DKK  1024
#define DVV  2048
#define HDKK 64
#define HDVV 128
#define NCAT 6144              // q(1024) | k(1024) | v(2048) | g(2048)

// ---------------- scratch (device globals; no allocation allowed) ----------
__device__ float g_xc  [LL*DD];      // conv+silu output (fp32 exact, for router)
__device__ float g_xctf[LL*DD];      // conv+silu output, tf32-rounded (GEMM A)
__device__ float g_wcat[DD*NCAT];    // Wq|Wk|Wv|Wg concatenated, tf32-rounded
__device__ float g_wtf [DD*DD];      // Wout tf32-rounded
__device__ float g_qkvg[LL*NCAT];    // fused projection output
__device__ float g_w2  [DD*32];      // Wv @ router_w  (fp32 exact)
__device__ float g_rlog[LL*32];      // router logits  (fp32 exact)
__device__ __nv_bfloat16 g_qh[LL*DKK];   // roped q hi, [h][l][64]
__device__ __nv_bfloat16 g_ql[LL*DKK];   // roped q lo
__device__ __nv_bfloat16 g_kh[LL*DKK];   // roped k hi
__device__ __nv_bfloat16 g_kl[LL*DKK];   // roped k lo
__device__ __nv_bfloat16 g_vth[HH*HDVV*LL]; // v hi, TRANSPOSED [h][c][l]
__device__ __nv_bfloat16 g_vtl[HH*HDVV*LL]; // v lo, transposed
__device__ float g_o   [LL*DVV];     // attention output
__device__ float g_y   [LL*DVV];     // silu(g)*LN(o), tf32-rounded
__device__ float g_coef[HH*LL];      // score_max/count * HDK^-0.5
__device__ int   g_rsel[HH*LL];      // selected expert per (h,l)

__device__ __forceinline__ float silu_f(float z) { return z / (1.f + expf(-z)); }

__device__ __forceinline__ unsigned f2tf(float f) {
    unsigned r;
    asm("cvt.rna.tf32.f32 %0, %1;" : "=r"(r) : "f"(f));
    return r;
}
__device__ __forceinline__ float tf32r(float f) { return __uint_as_float(f2tf(f)); }

__device__ __forceinline__ unsigned f2bfu(float f) {
    return (unsigned)__bfloat16_as_ushort(__float2bfloat16_rn(f));
}
__device__ __forceinline__ float bfu2f(unsigned u) {
    return __bfloat162float(__ushort_as_bfloat16((unsigned short)u));
}
__device__ __forceinline__ void split_bf(float v, unsigned& hi, unsigned& lo) {
    hi = f2bfu(v);
    lo = f2bfu(v - bfu2f(hi));
}

__device__ __forceinline__ void mma8(float* c,
                                     unsigned a0, unsigned a1, unsigned a2, unsigned a3,
                                     unsigned b0, unsigned b1) {
    asm("mma.sync.aligned.m16n8k8.row.col.f32.tf32.tf32.f32 "
        "{%0,%1,%2,%3}, {%4,%5,%6,%7}, {%8,%9}, {%0,%1,%2,%3};"
        : "+f"(c[0]), "+f"(c[1]), "+f"(c[2]), "+f"(c[3])
        : "r"(a0), "r"(a1), "r"(a2), "r"(a3), "r"(b0), "r"(b1));
}

__device__ __forceinline__ void mma16(float* c,
                                      unsigned a0, unsigned a1, unsigned a2, unsigned a3,
                                      unsigned b0, unsigned b1) {
    asm("mma.sync.aligned.m16n8k16.row.col.f32.bf16.bf16.f32 "
        "{%0,%1,%2,%3}, {%4,%5,%6,%7}, {%8,%9}, {%0,%1,%2,%3};"
        : "+f"(c[0]), "+f"(c[1]), "+f"(c[2]), "+f"(c[3])
        : "r"(a0), "r"(a1), "r"(a2), "r"(a3), "r"(b0), "r"(b1));
}

__device__ __forceinline__ void cp16(float* smem_dst, const float* gsrc) {
    unsigned sa = (unsigned)__cvta_generic_to_shared(smem_dst);
    asm volatile("cp.async.cg.shared.global [%0], [%1], 16;\n"
                 :: "r"(sa), "l"(gsrc));
}
__device__ __forceinline__ void cp16b(unsigned* smem_dst, const __nv_bfloat16* gsrc) {
    unsigned sa = (unsigned)__cvta_generic_to_shared(smem_dst);
    asm volatile("cp.async.cg.shared.global [%0], [%1], 16;\n"
                 :: "r"(sa), "l"(gsrc));
}

// ---------------- stage 1: shifted conv + silu -----------------------------
__global__ void conv_silu_kernel(const float* __restrict__ x,
                                 const float* __restrict__ cw) {
    int idx = blockIdx.x * blockDim.x + threadIdx.x;  // over L*D
    if (idx >= LL*DD) return;
    int d = idx & (DD-1);
    int l = idx >> 11;
    float prev = (l == 0) ? 0.f : x[idx - DD];
    float z = prev * cw[2*d] + x[idx] * cw[2*d + 1];
    float v = silu_f(z);
    g_xc[idx]   = v;
    g_xctf[idx] = tf32r(v);
}

// ---------------- weight concat (tf32-rounded): Wq|Wk|Wv|Wg ---------------
__global__ void wcat_kernel(const float* __restrict__ Wq,
                            const float* __restrict__ Wk,
                            const float* __restrict__ Wv,
                            const float* __restrict__ Wg) {
    int idx = blockIdx.x * blockDim.x + threadIdx.x;   // over DD*NCAT/4
    if (idx >= DD * NCAT / 4) return;
    int n = (idx % (NCAT / 4)) * 4;
    int k = idx / (NCAT / 4);
    float4 v;
    if      (n < 1024) v = *(const float4*)(Wq + (size_t)k * DKK + n);
    else if (n < 2048) v = *(const float4*)(Wk + (size_t)k * DKK + (n - 1024));
    else if (n < 4096) v = *(const float4*)(Wv + (size_t)k * DVV + (n - 2048));
    else               v = *(const float4*)(Wg + (size_t)k * DVV + (n - 4096));
    v.x = tf32r(v.x); v.y = tf32r(v.y); v.z = tf32r(v.z); v.w = tf32r(v.w);
    *(float4*)(g_wcat + (size_t)k * NCAT + n) = v;
}

// ---------------- Wout tf32-rounded copy -----------------------------------
__global__ void wout_kernel(const float* __restrict__ Wout) {
    int idx = blockIdx.x * blockDim.x + threadIdx.x;   // over DD*DD/4
    if (idx >= DD * DD / 4) return;
    float4 v = *(const float4*)(Wout + (size_t)idx * 4);
    v.x = tf32r(v.x); v.y = tf32r(v.y); v.z = tf32r(v.z); v.w = tf32r(v.w);
    *(float4*)(g_wtf + (size_t)idx * 4) = v;
}

// ---------------- W2 = Wv @ router_w (fp32 exact, [2048][32]) --------------
__global__ void w2_kernel(const float* __restrict__ Wv,
                          const float* __restrict__ rw) {
    int k  = blockIdx.x;          // 2048 blocks
    int t  = threadIdx.x;         // 32 threads: h*2+r
    int h  = t >> 1, r = t & 1;
    const float* wrow = Wv + (size_t)k * DVV + h * HDVV;
    const float* rr   = rw + (h * HDVV) * 2 + r;
    float acc = 0.f;
    #pragma unroll 8
    for (int d = 0; d < HDVV; d++)
        acc += wrow[d] * rr[2 * d];
    g_w2[k * 32 + t] = acc;
}

// ---------------- router logits = xc @ W2 (fp32 exact, [2048][32]) ---------
__global__ void rlog_kernel() {
    int tid = threadIdx.x;
    int hr  = tid & 31;
    int l   = blockIdx.x * 8 + (tid >> 5);
    const float* xrow = g_xc + (size_t)l * DD;
    float acc = 0.f;
    #pragma unroll 4
    for (int k = 0; k < DD; k++)
        acc += xrow[k] * g_w2[k * 32 + hr];
    g_rlog[l * 32 + hr] = acc;
}

// ---------------- tensor-core GEMM (TF32, pre-rounded operands) ------------
#define AP 36
#define BPAD 136
#define STGF (128*AP + 32*BPAD)       // floats per stage = 8960
#define SMEM_GEMM (2 * STGF * 4)      // 71680 bytes

__global__ __launch_bounds__(256, 2) void gemm_tc(
        const float* __restrict__ A,
        const float* __restrict__ B,
        float* __restrict__ C,
        int M, int N, int K, int silu_ncols) {
    extern __shared__ float sm[];

    int tid = threadIdx.x, lane = tid & 31, warp = tid >> 5;
    int bm = blockIdx.y * 128, bn = blockIdx.x * 128;
    int wm = (warp >> 2) * 64, wn = (warp & 3) * 32;
    int g = lane >> 2, t = lane & 3;

    float acc[4][4][4];
    #pragma unroll
    for (int i = 0; i < 4; i++)
        #pragma unroll
        for (int j = 0; j < 4; j++)
            #pragma unroll
            for (int r = 0; r < 4; r++) acc[i][j][r] = 0.f;

    const float* agp[4];
    const float* bgp[4];
    int asp[4], bsp[4];
    #pragma unroll
    for (int i = 0; i < 4; i++) {
        int idx = tid + i * 256;
        int ar = idx >> 3, ac = (idx & 7) * 4;
        int br = idx >> 5, bc = (idx & 31) * 4;
        agp[i] = A + (size_t)(bm + ar) * K + ac;
        bgp[i] = B + (size_t)br * N + bn + bc;
        asp[i] = ar * AP + ac;
        bsp[i] = 128 * AP + br * BPAD + bc;
    }

#define LOAD_STAGE(s, k0) do {                                          \
        float* base_ = sm + (s) * STGF;                                 \
        _Pragma("unroll")                                               \
        for (int i_ = 0; i_ < 4; i_++) {                                \
            cp16(base_ + asp[i_], agp[i_] + (k0));                      \
            cp16(base_ + bsp[i_], bgp[i_] + (size_t)(k0) * N);          \
        }                                                               \
        asm volatile("cp.async.commit_group;\n" ::);                    \
    } while (0)

    int nk = K >> 5;
    LOAD_STAGE(0, 0);
    LOAD_STAGE(1, 32);

    for (int kt = 0; kt < nk; kt++) {
        int s = kt & 1;
        asm volatile("cp.async.wait_group 1;\n" ::);
        __syncthreads();
        const float* Ah = sm + s * STGF;
        const float* Bh = Ah + 128 * AP;

        #pragma unroll
        for (int ko = 0; ko < 32; ko += 8) {
            unsigned af[4][4], bf[4][2];
            #pragma unroll
            for (int fm = 0; fm < 4; fm++) {
                int r0 = wm + fm * 16 + g;
                af[fm][0] = __float_as_uint(Ah[ r0      * AP + ko + t]);
                af[fm][1] = __float_as_uint(Ah[(r0 + 8) * AP + ko + t]);
                af[fm][2] = __float_as_uint(Ah[ r0      * AP + ko + t + 4]);
                af[fm][3] = __float_as_uint(Ah[(r0 + 8) * AP + ko + t + 4]);
            }
            #pragma unroll
            for (int fn = 0; fn < 4; fn++) {
                int c0 = wn + fn * 8 + g;
                bf[fn][0] = __float_as_uint(Bh[(ko + t    ) * BPAD + c0]);
                bf[fn][1] = __float_as_uint(Bh[(ko + t + 4) * BPAD + c0]);
            }
            #pragma unroll
            for (int fm = 0; fm < 4; fm++)
                #pragma unroll
                for (int fn = 0; fn < 4; fn++)
                    mma8(acc[fm][fn], af[fm][0], af[fm][1], af[fm][2], af[fm][3],
                         bf[fn][0], bf[fn][1]);
        }
        __syncthreads();
        if (kt + 2 < nk) LOAD_STAGE(s, (kt + 2) * 32);
    }

    #pragma unroll
    for (int fm = 0; fm < 4; fm++) {
        int r0 = bm + wm + fm * 16 + g;
        #pragma unroll
        for (int fn = 0; fn < 4; fn++) {
            int c0 = bn + wn + fn * 8 + 2 * t;
            float v0 = acc[fm][fn][0], v1 = acc[fm][fn][1];
            float v2 = acc[fm][fn][2], v3 = acc[fm][fn][3];
            if (c0 < silu_ncols) {
                v0 = silu_f(v0); v1 = silu_f(v1);
                v2 = silu_f(v2); v3 = silu_f(v3);
            }
            *(float2*)(C + (size_t)r0 * N + c0)       = make_float2(v0, v1);
            *(float2*)(C + (size_t)(r0 + 8) * N + c0) = make_float2(v2, v3);
        }
    }
}

// ---------------- stage 3: RoPE + bf16 hi/lo split, head-major -------------
__global__ void rope_split_kernel() {
    int idx = blockIdx.x * blockDim.x + threadIdx.x;   // L*H*32
    if (idx >= LL * HH * 32) return;
    int i  = idx & 31;
    int lh = idx >> 5;
    int h  = lh & (HH-1);
    int l  = lh >> 4;
    float invf = powf(10000.f, -(float)i / 32.f);
    float ang = (float)l * invf;
    float c = cosf(ang), s = sinf(ang);
    size_t qb = (size_t)l * NCAT + h * HDKK;
    size_t kb = qb + DKK;
    size_t ob = ((size_t)h * LL + l) * HDKK;
    float q1 = g_qkvg[qb + i], q2 = g_qkvg[qb + 32 + i];
    float k1 = g_qkvg[kb + i], k2 = g_qkvg[kb + 32 + i];
    float qa = q1 * c - q2 * s, qbv = q2 * c + q1 * s;
    float ka = k1 * c - k2 * s, kbv = k2 * c + k1 * s;
    __nv_bfloat16 hb;
    hb = __float2bfloat16_rn(qa);
    g_qh[ob + i] = hb;  g_ql[ob + i] = __float2bfloat16_rn(qa - __bfloat162float(hb));
    hb = __float2bfloat16_rn(qbv);
    g_qh[ob + 32 + i] = hb;  g_ql[ob + 32 + i] = __float2bfloat16_rn(qbv - __bfloat162float(hb));
    hb = __float2bfloat16_rn(ka);
    g_kh[ob + i] = hb;  g_kl[ob + i] = __float2bfloat16_rn(ka - __bfloat162float(hb));
    hb = __float2bfloat16_rn(kbv);
    g_kh[ob + 32 + i] = hb;  g_kl[ob + 32 + i] = __float2bfloat16_rn(kbv - __bfloat162float(hb));
}

// ---------------- v transpose + bf16 split: [h][c][l] ----------------------
__global__ void vsplit_t_kernel() {
    __shared__ float tile[64][33];
    int l0 = blockIdx.x * 64, c0 = blockIdx.y * 32, h = blockIdx.z;
    int tid = threadIdx.x;
    for (int i = tid; i < 64 * 32; i += 256) {
        int li = i >> 5, ci = i & 31;
        tile[li][ci] = g_qkvg[(size_t)(l0 + li) * NCAT + 2*DKK + h * HDVV + c0 + ci];
    }
    __syncthreads();
    for (int i = tid; i < 32 * 64; i += 256) {
        int ci = i >> 6, li = i & 63;
        float v = tile[li][ci];
        __nv_bfloat16 hb = __float2bfloat16_rn(v);
        size_t ob = ((size_t)h * HDVV + c0 + ci) * LL + l0 + li;
        g_vth[ob] = hb;
        g_vtl[ob] = __float2bfloat16_rn(v - __bfloat162float(hb));
    }
}

// ---------------- stage 4: router decision + sequential count scan ---------
__global__ void router_kernel() {
    int h = blockIdx.x;                    // 16 blocks, 256 threads
    __shared__ float s_score[LL];
    __shared__ int   s_sel[LL];
    for (int l = threadIdx.x; l < LL; l += blockDim.x) {
        float z0 = g_rlog[l * 32 + h * 2 + 0];
        float z1 = g_rlog[l * 32 + h * 2 + 1];
        int sel = (z1 > z0) ? 1 : 0;
        float m = fmaxf(z0, z1);
        float e0 = expf(z0 - m), e1 = expf(z1 - m);
        s_sel[l]   = sel;
        s_score[l] = ((sel == 0) ? e0 : e1) / (e0 + e1);
    }
    __syncthreads();
    if (threadIdx.x == 0) {
        int c0 = 0, c1 = 0;
        const float scale = 0.125f;   // HDK^{-1/2}
        for (int l = 0; l < LL; l++) {
            int sel = s_sel[l];
            int cnt;
            if (sel == 0) { c0++; cnt = c0; } else { c1++; cnt = c1; }
            g_rsel[h * LL + l] = sel;
            g_coef[h * LL + l] = s_score[l] / (float)cnt * scale;
        }
    }
}

// ---------------- stage 5: bf16 tensor-core attention (cp.async) -----------
// smem layout in u32 words; each row = 32 data words (64 bf16) + 4 pad
#define SU 36
#define AQH 0
#define AQL (AQH + 64*SU)
#define AKB (AQL + 64*SU)            // K: 2 stages x (hi, lo)
#define AKSTG (2*64*SU)
#define ASH (AKB + 2*AKSTG)
#define ASL (ASH + 64*SU)
#define AVH (ASL + 64*SU)            // V^T: 128 rows
#define AVL (AVH + 128*SU)
#define ACF (AVL + 128*SU)
#define ARR (ACF + 64)
#define ARC (ARR + 64)
#define ATTN4_WORDS (ARC + 64)
#define ATTN4_BYTES (ATTN4_WORDS * 4)   // ~108.8 KB -> 2 CTAs/SM

__global__ __launch_bounds__(256, 2) void attn_tc() {
    extern __shared__ unsigned smu[];
    unsigned* Qh = smu + AQH;  unsigned* Ql = smu + AQL;
    unsigned* Sh = smu + ASH;  unsigned* Sl = smu + ASL;
    unsigned* Vh = smu + AVH;  unsigned* Vl = smu + AVL;
    float* coef_r = (float*)(smu + ACF);
    int*   rsel_r = (int*)(smu + ARR);
    int*   rsel_c = (int*)(smu + ARC);

    int h   = blockIdx.y;
    int l0  = (gridDim.x - 1 - blockIdx.x) * 64;   // heavy tiles first
    int tid = threadIdx.x, lane = tid & 31, warp = tid >> 5;
    int g = lane >> 2, t = lane & 3;
    int wm  = (warp >> 1) * 16;
    int wns = (warp & 1) * 32;
    int wno = (warp & 1) * 64;

    const __nv_bfloat16* Kh_g  = g_kh  + (size_t)h * LL * HDKK;
    const __nv_bfloat16* Kl_g  = g_kl  + (size_t)h * LL * HDKK;
    const __nv_bfloat16* Vth_g = g_vth + (size_t)h * HDVV * LL;
    const __nv_bfloat16* Vtl_g = g_vtl + (size_t)h * HDVV * LL;

#define LOAD_K(s, m0) do {                                                  \
        unsigned* kh_ = smu + AKB + (s) * AKSTG;                            \
        unsigned* kl_ = kh_ + 64*SU;                                        \
        _Pragma("unroll")                                                   \
        for (int i_ = 0; i_ < 2; i_++) {                                    \
            int idx_ = tid + i_ * 256, r_ = idx_ >> 3, j_ = idx_ & 7;       \
            cp16b(kh_ + r_*SU + j_*4, Kh_g + (size_t)((m0)+r_)*HDKK + j_*8);\
            cp16b(kl_ + r_*SU + j_*4, Kl_g + (size_t)((m0)+r_)*HDKK + j_*8);\
        }                                                                   \
        asm volatile("cp.async.commit_group;\n" ::);                        \
    } while (0)

#define LOAD_V(m0) do {                                                     \
        _Pragma("unroll")                                                   \
        for (int i_ = 0; i_ < 4; i_++) {                                    \
            int idx_ = tid + i_ * 256, r_ = idx_ >> 3, j_ = idx_ & 7;       \
            cp16b(Vh + r_*SU + j_*4, Vth_g + (size_t)r_*LL + (m0) + j_*8);  \
            cp16b(Vl + r_*SU + j_*4, Vtl_g + (size_t)r_*LL + (m0) + j_*8);  \
        }                                                                   \
        asm volatile("cp.async.commit_group;\n" ::);                        \
    } while (0)

    // prologue: K(0) in flight, load Q + metadata
    LOAD_K(0, 0);
    {
        const __nv_bfloat16* Qh_g = g_qh + (size_t)h * LL * HDKK;
        const __nv_bfloat16* Ql_g = g_ql + (size_t)h * LL * HDKK;
        for (int i = tid; i < 64 * 8; i += 256) {
            int r = i >> 3, j = i & 7;
            *(uint4*)(Qh + r*SU + j*4) = *(const uint4*)(Qh_g + (size_t)(l0 + r)*HDKK + j*8);
            *(uint4*)(Ql + r*SU + j*4) = *(const uint4*)(Ql_g + (size_t)(l0 + r)*HDKK + j*8);
        }
    }
    if (tid < 64) {
        rsel_r[tid] = g_rsel[h * LL + l0 + tid];
        coef_r[tid] = g_coef[h * LL + l0 + tid];
    }

    float acc_o[8][4];
    #pragma unroll
    for (int fn = 0; fn < 8; fn++)
        #pragma unroll
        for (int r = 0; r < 4; r++) acc_o[fn][r] = 0.f;

    int ntiles = (l0 >> 6) + 1;
    for (int mt = 0; mt < ntiles; mt++) {
        int m0 = mt * 64;
        int s  = mt & 1;
        __syncthreads();                    // prev V/S reads done
        LOAD_V(m0);
        if (tid < 64) rsel_c[tid] = g_rsel[h * LL + m0 + tid];
        asm volatile("cp.async.wait_group 1;\n" ::);   // K(mt) done
        __syncthreads();

        const unsigned* Kts = smu + AKB + s * AKSTG;
        const unsigned* Kls = Kts + 64*SU;

        // ---- QK^T (bf16 3-term): warp tile 16x32, 4 k16 steps ----
        float acc_s[4][4];
        #pragma unroll
        for (int fn = 0; fn < 4; fn++)
            #pragma unroll
            for (int r = 0; r < 4; r++) acc_s[fn][r] = 0.f;

        #pragma unroll
        for (int kk = 0; kk < 4; kk++) {
            int p0 = kk * 8;
            int r0 = wm + g;
            unsigned ah0 = Qh[ r0      * SU + p0 + t];
            unsigned ah1 = Qh[(r0 + 8) * SU + p0 + t];
            unsigned ah2 = Qh[ r0      * SU + p0 + t + 4];
            unsigned ah3 = Qh[(r0 + 8) * SU + p0 + t + 4];
            unsigned al0 = Ql[ r0      * SU + p0 + t];
            unsigned al1 = Ql[(r0 + 8) * SU + p0 + t];
            unsigned al2 = Ql[ r0      * SU + p0 + t + 4];
            unsigned al3 = Ql[(r0 + 8) * SU + p0 + t + 4];
            #pragma unroll
            for (int fn = 0; fn < 4; fn++) {
                int c0 = wns + fn * 8 + g;
                unsigned bh0 = Kts[c0 * SU + p0 + t];
                unsigned bh1 = Kts[c0 * SU + p0 + t + 4];
                unsigned bl0 = Kls[c0 * SU + p0 + t];
                unsigned bl1 = Kls[c0 * SU + p0 + t + 4];
                mma16(acc_s[fn], ah0, ah1, ah2, ah3, bh0, bh1);
                mma16(acc_s[fn], ah0, ah1, ah2, ah3, bl0, bl1);
                mma16(acc_s[fn], al0, al1, al2, al3, bh0, bh1);
            }
        }

        // prefetch K(mt+1) — K(mt) reads are done
        if (mt + 1 < ntiles) LOAD_K(s ^ 1, m0 + 64);

        // ---- mask + coef, pack bf16 hi/lo pairs into S ----
        {
            int r0 = wm + g, r1 = r0 + 8;
            int gl0 = l0 + r0, gl1 = l0 + r1;
            int e0 = rsel_r[r0], e1 = rsel_r[r1];
            float cf0 = coef_r[r0], cf1 = coef_r[r1];
            #pragma unroll
            for (int fn = 0; fn < 4; fn++) {
                int c = wns + fn * 8 + 2 * t;
                int gm0 = m0 + c, gm1 = gm0 + 1;
                int ec0 = rsel_c[c], ec1 = rsel_c[c + 1];
                float s00 = (gm0 <= gl0 && ec0 == e0) ? acc_s[fn][0] * cf0 : 0.f;
                float s01 = (gm1 <= gl0 && ec1 == e0) ? acc_s[fn][1] * cf0 : 0.f;
                float s10 = (gm0 <= gl1 && ec0 == e1) ? acc_s[fn][2] * cf1 : 0.f;
                float s11 = (gm1 <= gl1 && ec1 == e1) ? acc_s[fn][3] * cf1 : 0.f;
                unsigned h00, l00, h01, l01, h10, l10, h11, l11;
                split_bf(s00, h00, l00); split_bf(s01, h01, l01);
                split_bf(s10, h10, l10); split_bf(s11, h11, l11);
                int pi = (wns >> 1) + fn * 4 + t;
                Sh[r0 * SU + pi] = h00 | (h01 << 16);
                Sl[r0 * SU + pi] = l00 | (l01 << 16);
                Sh[r1 * SU + pi] = h10 | (h11 << 16);
                Sl[r1 * SU + pi] = l10 | (l11 << 16);
            }
        }
        if (mt + 1 < ntiles)
            asm volatile("cp.async.wait_group 1;\n" ::);  // V(mt) done, K(mt+1) pending
        else
            asm volatile("cp.async.wait_group 0;\n" ::);  // last tile: V must be done
        __syncthreads();                                   // S + V visible

        // ---- O += S @ V (bf16 3-term): warp tile 16x64, 4 k16 steps ----
        #pragma unroll
        for (int kk = 0; kk < 4; kk++) {
            int p0 = kk * 8;
            int r0 = wm + g;
            unsigned ah0 = Sh[ r0      * SU + p0 + t];
            unsigned ah1 = Sh[(r0 + 8) * SU + p0 + t];
            unsigned ah2 = Sh[ r0      * SU + p0 + t + 4];
            unsigned ah3 = Sh[(r0 + 8) * SU + p0 + t + 4];
            unsigned al0 = Sl[ r0      * SU + p0 + t];
            unsigned al1 = Sl[(r0 + 8) * SU + p0 + t];
            unsigned al2 = Sl[ r0      * SU + p0 + t + 4];
            unsigned al3 = Sl[(r0 + 8) * SU + p0 + t + 4];
            #pragma unroll
            for (int fn = 0; fn < 8; fn++) {
                int c0 = wno + fn * 8 + g;
                unsigned bh0 = Vh[c0 * SU + p0 + t];
                unsigned bh1 = Vh[c0 * SU + p0 + t + 4];
                unsigned bl0 = Vl[c0 * SU + p0 + t];
                unsigned bl1 = Vl[c0 * SU + p0 + t + 4];
                mma16(acc_o[fn], ah0, ah1, ah2, ah3, bh0, bh1);
                mma16(acc_o[fn], ah0, ah1, ah2, ah3, bl0, bl1);
                mma16(acc_o[fn], al0, al1, al2, al3, bh0, bh1);
            }
        }
    }

    // ---- store O ----
    int r0 = wm + g;
    #pragma unroll
    for (int fn = 0; fn < 8; fn++) {
        int c = wno + fn * 8 + 2 * t;
        *(float2*)(g_o + (size_t)(l0 + r0    ) * DVV + h * HDVV + c)
            = make_float2(acc_o[fn][0], acc_o[fn][1]);
        *(float2*)(g_o + (size_t)(l0 + r0 + 8) * DVV + h * HDVV + c)
            = make_float2(acc_o[fn][2], acc_o[fn][3]);
    }
}

// ---------------- stage 6: LayerNorm(128) * silu(gate), tf32-rounded -------
__global__ void ln_gate_kernel() {
    int h = blockIdx.x;
    int l = blockIdx.y;
    int j = threadIdx.x;    // 128
    size_t obase = (size_t)l * DVV + h * HDVV;
    float o = g_o[obase + j];
    float sum = o, sumsq = o * o;
    #pragma unroll
    for (int off = 16; off; off >>= 1) {
        sum   += __shfl_down_sync(0xffffffffu, sum,   off);
        sumsq += __shfl_down_sync(0xffffffffu, sumsq, off);
    }
    __shared__ float s1[4], s2[4];
    if ((j & 31) == 0) { s1[j >> 5] = sum; s2[j >> 5] = sumsq; }
    __syncthreads();
    float tot   = s1[0] + s1[1] + s1[2] + s1[3];
    float totsq = s2[0] + s2[1] + s2[2] + s2[3];
    float mu  = tot * (1.f / 128.f);
    float var = totsq * (1.f / 128.f) - mu * mu;
    float inv = rsqrtf(var + 1e-5f);
    float gt  = g_qkvg[(size_t)l * NCAT + 2*DKK + DVV + h * HDVV + j];
    g_y[obase + j] = tf32r(silu_f(gt) * (o - mu) * inv);
}

// ---------------- launch ----------------------------------------------------
extern "C" void kernel_launch(void* const* d_in, const int* in_sizes, int n_in,
                              void* d_out, int out_size) {
    const float* x    = (const float*)d_in[0];
    const float* cw   = (const float*)d_in[1];
    const float* Wq   = (const float*)d_in[2];
    const float* Wk   = (const float*)d_in[3];
    const float* Wv   = (const float*)d_in[4];
    const float* Wg   = (const float*)d_in[5];
    const float* rw   = (const float*)d_in[6];
    const float* Wout = (const float*)d_in[7];
    float* out = (float*)d_out;

    float *p_xctf, *p_wcat, *p_wtf, *p_qkvg, *p_y;
    cudaGetSymbolAddress((void**)&p_xctf, g_xctf);
    cudaGetSymbolAddress((void**)&p_wcat, g_wcat);
    cudaGetSymbolAddress((void**)&p_wtf,  g_wtf);
    cudaGetSymbolAddress((void**)&p_qkvg, g_qkvg);
    cudaGetSymbolAddress((void**)&p_y,    g_y);

    cudaFuncSetAttribute(attn_tc,
                         cudaFuncAttributeMaxDynamicSharedMemorySize, ATTN4_BYTES);
    cudaFuncSetAttribute(gemm_tc,
                         cudaFuncAttributeMaxDynamicSharedMemorySize, SMEM_GEMM);

    conv_silu_kernel<<<(LL*DD)/256, 256>>>(x, cw);
    wcat_kernel<<<(DD*NCAT/4 + 255)/256, 256>>>(Wq, Wk, Wv, Wg);
    wout_kernel<<<(DD*DD/4 + 255)/256, 256>>>(Wout);
    w2_kernel<<<DD, 32>>>(Wv, rw);

    // fused QKVG projection (silu on q columns)
    gemm_tc<<<dim3(NCAT/128, LL/128), 256, SMEM_GEMM>>>(p_xctf, p_wcat, p_qkvg,
                                                        LL, NCAT, DD, DKK);
    rlog_kernel<<<LL/8, 256>>>();

    rope_split_kernel<<<(LL*HH*32)/256, 256>>>();
    vsplit_t_kernel<<<dim3(LL/64, HDVV/32, HH), 256>>>();
    router_kernel<<<HH, 256>>>();

    attn_tc<<<dim3(LL/64, HH), 256, ATTN4_BYTES>>>();

    ln_gate_kernel<<<dim3(HH, LL), 128>>>();

    gemm_tc<<<dim3(DD/128, LL/128), 256, SMEM_GEMM>>>(p_y, p_wtf, out,
                                                      LL, DD, DVV, 0);
}

// round 10
// speedup vs baseline: 4.1581x; 1.0801x over previous
#include <cuda_runtime.h>
#include <cuda_bf16.h>
#include <math.h>

#define LL   2048
#define DD   2048
#define HH   16
#define DKK  1024
#define DVV  2048
#define HDKK 64
#define HDVV 128
#define NCAT 6144              // q(1024) | k(1024) | v(2048) | g(2048)

// ---------------- scratch (device globals; no allocation allowed) ----------
__device__ float g_xc  [LL*DD];      // conv+silu output (fp32 exact, for router)
__device__ float g_xctf[LL*DD];      // conv+silu output, tf32-rounded (GEMM A)
__device__ float g_wcat[DD*NCAT];    // Wq|Wk|Wv|Wg concatenated, tf32-rounded
__device__ float g_qkvg[LL*NCAT];    // fused projection output
__device__ float g_w2  [DD*32];      // Wv @ router_w  (fp32 exact)
__device__ float g_rlog[LL*32];      // router logits  (fp32 exact)
__device__ __nv_bfloat16 g_qh[LL*DKK];   // roped q hi, [h][l][64]
__device__ __nv_bfloat16 g_ql[LL*DKK];   // roped q lo
__device__ __nv_bfloat16 g_kh[LL*DKK];   // roped k hi
__device__ __nv_bfloat16 g_kl[LL*DKK];   // roped k lo
__device__ __nv_bfloat16 g_vth[HH*HDVV*LL]; // v hi, TRANSPOSED [h][c][l]
__device__ __nv_bfloat16 g_vtl[HH*HDVV*LL]; // v lo, transposed
__device__ float g_y   [LL*DVV];     // silu(g)*LN(o), tf32-rounded
__device__ float g_coef[HH*LL];      // score_max/count * HDK^-0.5
__device__ int   g_rsel[HH*LL];      // selected expert per (h,l)

__device__ __forceinline__ float silu_f(float z) { return z / (1.f + expf(-z)); }

__device__ __forceinline__ unsigned f2tf(float f) {
    unsigned r;
    asm("cvt.rna.tf32.f32 %0, %1;" : "=r"(r) : "f"(f));
    return r;
}
__device__ __forceinline__ float tf32r(float f) { return __uint_as_float(f2tf(f)); }

__device__ __forceinline__ unsigned f2bfu(float f) {
    return (unsigned)__bfloat16_as_ushort(__float2bfloat16_rn(f));
}
__device__ __forceinline__ float bfu2f(unsigned u) {
    return __bfloat162float(__ushort_as_bfloat16((unsigned short)u));
}
__device__ __forceinline__ void split_bf(float v, unsigned& hi, unsigned& lo) {
    hi = f2bfu(v);
    lo = f2bfu(v - bfu2f(hi));
}

__device__ __forceinline__ void mma8(float* c,
                                     unsigned a0, unsigned a1, unsigned a2, unsigned a3,
                                     unsigned b0, unsigned b1) {
    asm("mma.sync.aligned.m16n8k8.row.col.f32.tf32.tf32.f32 "
        "{%0,%1,%2,%3}, {%4,%5,%6,%7}, {%8,%9}, {%0,%1,%2,%3};"
        : "+f"(c[0]), "+f"(c[1]), "+f"(c[2]), "+f"(c[3])
        : "r"(a0), "r"(a1), "r"(a2), "r"(a3), "r"(b0), "r"(b1));
}

__device__ __forceinline__ void mma16(float* c,
                                      unsigned a0, unsigned a1, unsigned a2, unsigned a3,
                                      unsigned b0, unsigned b1) {
    asm("mma.sync.aligned.m16n8k16.row.col.f32.bf16.bf16.f32 "
        "{%0,%1,%2,%3}, {%4,%5,%6,%7}, {%8,%9}, {%0,%1,%2,%3};"
        : "+f"(c[0]), "+f"(c[1]), "+f"(c[2]), "+f"(c[3])
        : "r"(a0), "r"(a1), "r"(a2), "r"(a3), "r"(b0), "r"(b1));
}

__device__ __forceinline__ void cp16(float* smem_dst, const float* gsrc) {
    unsigned sa = (unsigned)__cvta_generic_to_shared(smem_dst);
    asm volatile("cp.async.cg.shared.global [%0], [%1], 16;\n"
                 :: "r"(sa), "l"(gsrc));
}
__device__ __forceinline__ void cp16b(unsigned* smem_dst, const __nv_bfloat16* gsrc) {
    unsigned sa = (unsigned)__cvta_generic_to_shared(smem_dst);
    asm volatile("cp.async.cg.shared.global [%0], [%1], 16;\n"
                 :: "r"(sa), "l"(gsrc));
}

// ---------------- stage 1: shifted conv + silu -----------------------------
__global__ void conv_silu_kernel(const float* __restrict__ x,
                                 const float* __restrict__ cw) {
    int idx = blockIdx.x * blockDim.x + threadIdx.x;  // over L*D
    if (idx >= LL*DD) return;
    int d = idx & (DD-1);
    int l = idx >> 11;
    float prev = (l == 0) ? 0.f : x[idx - DD];
    float z = prev * cw[2*d] + x[idx] * cw[2*d + 1];
    float v = silu_f(z);
    g_xc[idx]   = v;
    g_xctf[idx] = tf32r(v);
}

// ---------------- weight concat (tf32-rounded): Wq|Wk|Wv|Wg ---------------
__global__ void wcat_kernel(const float* __restrict__ Wq,
                            const float* __restrict__ Wk,
                            const float* __restrict__ Wv,
                            const float* __restrict__ Wg) {
    int idx = blockIdx.x * blockDim.x + threadIdx.x;   // over DD*NCAT/4
    if (idx >= DD * NCAT / 4) return;
    int n = (idx % (NCAT / 4)) * 4;
    int k = idx / (NCAT / 4);
    float4 v;
    if      (n < 1024) v = *(const float4*)(Wq + (size_t)k * DKK + n);
    else if (n < 2048) v = *(const float4*)(Wk + (size_t)k * DKK + (n - 1024));
    else if (n < 4096) v = *(const float4*)(Wv + (size_t)k * DVV + (n - 2048));
    else               v = *(const float4*)(Wg + (size_t)k * DVV + (n - 4096));
    v.x = tf32r(v.x); v.y = tf32r(v.y); v.z = tf32r(v.z); v.w = tf32r(v.w);
    *(float4*)(g_wcat + (size_t)k * NCAT + n) = v;
}

// ---------------- W2 = Wv @ router_w (fp32 exact, [2048][32]) --------------
__global__ void w2_kernel(const float* __restrict__ Wv,
                          const float* __restrict__ rw) {
    int tid = threadIdx.x;                 // 256 threads, 8 k-rows per block
    int k  = blockIdx.x * 8 + (tid >> 5);
    int t  = tid & 31;
    int h  = t >> 1, r = t & 1;
    const float* wrow = Wv + (size_t)k * DVV + h * HDVV;
    const float* rr   = rw + (h * HDVV) * 2 + r;
    float a0 = 0.f, a1 = 0.f, a2 = 0.f, a3 = 0.f;
    #pragma unroll 8
    for (int d = 0; d < HDVV; d += 4) {
        a0 += wrow[d]     * rr[2*d];
        a1 += wrow[d + 1] * rr[2*d + 2];
        a2 += wrow[d + 2] * rr[2*d + 4];
        a3 += wrow[d + 3] * rr[2*d + 6];
    }
    g_w2[k * 32 + t] = (a0 + a1) + (a2 + a3);
}

// ---------------- router logits = xc @ W2 (fp32 exact, [2048][32]) ---------
__global__ void rlog_kernel() {
    int tid = threadIdx.x;
    int hr  = tid & 31;
    int l   = blockIdx.x * 8 + (tid >> 5);
    const float* xrow = g_xc + (size_t)l * DD;
    float acc = 0.f;
    #pragma unroll 4
    for (int k = 0; k < DD; k++)
        acc += xrow[k] * g_w2[k * 32 + hr];
    g_rlog[l * 32 + hr] = acc;
}

// ---------------- tensor-core GEMM (TF32) ----------------------------------
// CVTB: convert B fragments to tf32 at load (B is raw fp32 in gmem).
#define AP 36
#define BPAD 136
#define STGF (128*AP + 32*BPAD)       // floats per stage = 8960
#define SMEM_GEMM (2 * STGF * 4)      // 71680 bytes

template<bool CVTB>
__global__ __launch_bounds__(256, 2) void gemm_tc(
        const float* __restrict__ A,
        const float* __restrict__ B,
        float* __restrict__ C,
        int M, int N, int K, int silu_ncols) {
    extern __shared__ float sm[];

    int tid = threadIdx.x, lane = tid & 31, warp = tid >> 5;
    int bm = blockIdx.y * 128, bn = blockIdx.x * 128;
    int wm = (warp >> 2) * 64, wn = (warp & 3) * 32;
    int g = lane >> 2, t = lane & 3;

    float acc[4][4][4];
    #pragma unroll
    for (int i = 0; i < 4; i++)
        #pragma unroll
        for (int j = 0; j < 4; j++)
            #pragma unroll
            for (int r = 0; r < 4; r++) acc[i][j][r] = 0.f;

    const float* agp[4];
    const float* bgp[4];
    int asp[4], bsp[4];
    #pragma unroll
    for (int i = 0; i < 4; i++) {
        int idx = tid + i * 256;
        int ar = idx >> 3, ac = (idx & 7) * 4;
        int br = idx >> 5, bc = (idx & 31) * 4;
        agp[i] = A + (size_t)(bm + ar) * K + ac;
        bgp[i] = B + (size_t)br * N + bn + bc;
        asp[i] = ar * AP + ac;
        bsp[i] = 128 * AP + br * BPAD + bc;
    }

#define LOAD_STAGE(s, k0) do {                                          \
        float* base_ = sm + (s) * STGF;                                 \
        _Pragma("unroll")                                               \
        for (int i_ = 0; i_ < 4; i_++) {                                \
            cp16(base_ + asp[i_], agp[i_] + (k0));                      \
            cp16(base_ + bsp[i_], bgp[i_] + (size_t)(k0) * N);          \
        }                                                               \
        asm volatile("cp.async.commit_group;\n" ::);                    \
    } while (0)

    int nk = K >> 5;
    LOAD_STAGE(0, 0);
    LOAD_STAGE(1, 32);

    for (int kt = 0; kt < nk; kt++) {
        int s = kt & 1;
        asm volatile("cp.async.wait_group 1;\n" ::);
        __syncthreads();
        const float* Ah = sm + s * STGF;
        const float* Bh = Ah + 128 * AP;

        #pragma unroll
        for (int ko = 0; ko < 32; ko += 8) {
            unsigned af[4][4], bf[4][2];
            #pragma unroll
            for (int fm = 0; fm < 4; fm++) {
                int r0 = wm + fm * 16 + g;
                af[fm][0] = __float_as_uint(Ah[ r0      * AP + ko + t]);
                af[fm][1] = __float_as_uint(Ah[(r0 + 8) * AP + ko + t]);
                af[fm][2] = __float_as_uint(Ah[ r0      * AP + ko + t + 4]);
                af[fm][3] = __float_as_uint(Ah[(r0 + 8) * AP + ko + t + 4]);
            }
            #pragma unroll
            for (int fn = 0; fn < 4; fn++) {
                int c0 = wn + fn * 8 + g;
                if (CVTB) {
                    bf[fn][0] = f2tf(Bh[(ko + t    ) * BPAD + c0]);
                    bf[fn][1] = f2tf(Bh[(ko + t + 4) * BPAD + c0]);
                } else {
                    bf[fn][0] = __float_as_uint(Bh[(ko + t    ) * BPAD + c0]);
                    bf[fn][1] = __float_as_uint(Bh[(ko + t + 4) * BPAD + c0]);
                }
            }
            #pragma unroll
            for (int fm = 0; fm < 4; fm++)
                #pragma unroll
                for (int fn = 0; fn < 4; fn++)
                    mma8(acc[fm][fn], af[fm][0], af[fm][1], af[fm][2], af[fm][3],
                         bf[fn][0], bf[fn][1]);
        }
        __syncthreads();
        if (kt + 2 < nk) LOAD_STAGE(s, (kt + 2) * 32);
    }

    #pragma unroll
    for (int fm = 0; fm < 4; fm++) {
        int r0 = bm + wm + fm * 16 + g;
        #pragma unroll
        for (int fn = 0; fn < 4; fn++) {
            int c0 = bn + wn + fn * 8 + 2 * t;
            float v0 = acc[fm][fn][0], v1 = acc[fm][fn][1];
            float v2 = acc[fm][fn][2], v3 = acc[fm][fn][3];
            if (c0 < silu_ncols) {
                v0 = silu_f(v0); v1 = silu_f(v1);
                v2 = silu_f(v2); v3 = silu_f(v3);
            }
            *(float2*)(C + (size_t)r0 * N + c0)       = make_float2(v0, v1);
            *(float2*)(C + (size_t)(r0 + 8) * N + c0) = make_float2(v2, v3);
        }
    }
}

// ---------------- stage 3: RoPE + bf16 hi/lo split, head-major -------------
__global__ void rope_split_kernel() {
    int idx = blockIdx.x * blockDim.x + threadIdx.x;   // L*H*32
    if (idx >= LL * HH * 32) return;
    int i  = idx & 31;
    int lh = idx >> 5;
    int h  = lh & (HH-1);
    int l  = lh >> 4;
    float invf = powf(10000.f, -(float)i / 32.f);
    float ang = (float)l * invf;
    float c = cosf(ang), s = sinf(ang);
    size_t qb = (size_t)l * NCAT + h * HDKK;
    size_t kb = qb + DKK;
    size_t ob = ((size_t)h * LL + l) * HDKK;
    float q1 = g_qkvg[qb + i], q2 = g_qkvg[qb + 32 + i];
    float k1 = g_qkvg[kb + i], k2 = g_qkvg[kb + 32 + i];
    float qa = q1 * c - q2 * s, qbv = q2 * c + q1 * s;
    float ka = k1 * c - k2 * s, kbv = k2 * c + k1 * s;
    __nv_bfloat16 hb;
    hb = __float2bfloat16_rn(qa);
    g_qh[ob + i] = hb;  g_ql[ob + i] = __float2bfloat16_rn(qa - __bfloat162float(hb));
    hb = __float2bfloat16_rn(qbv);
    g_qh[ob + 32 + i] = hb;  g_ql[ob + 32 + i] = __float2bfloat16_rn(qbv - __bfloat162float(hb));
    hb = __float2bfloat16_rn(ka);
    g_kh[ob + i] = hb;  g_kl[ob + i] = __float2bfloat16_rn(ka - __bfloat162float(hb));
    hb = __float2bfloat16_rn(kbv);
    g_kh[ob + 32 + i] = hb;  g_kl[ob + 32 + i] = __float2bfloat16_rn(kbv - __bfloat162float(hb));
}

// ---------------- v transpose + bf16 split: [h][c][l] ----------------------
__global__ void vsplit_t_kernel() {
    __shared__ float tile[64][33];
    int l0 = blockIdx.x * 64, c0 = blockIdx.y * 32, h = blockIdx.z;
    int tid = threadIdx.x;
    for (int i = tid; i < 64 * 32; i += 256) {
        int li = i >> 5, ci = i & 31;
        tile[li][ci] = g_qkvg[(size_t)(l0 + li) * NCAT + 2*DKK + h * HDVV + c0 + ci];
    }
    __syncthreads();
    for (int i = tid; i < 32 * 64; i += 256) {
        int ci = i >> 6, li = i & 63;
        float v = tile[li][ci];
        __nv_bfloat16 hb = __float2bfloat16_rn(v);
        size_t ob = ((size_t)h * HDVV + c0 + ci) * LL + l0 + li;
        g_vth[ob] = hb;
        g_vtl[ob] = __float2bfloat16_rn(v - __bfloat162float(hb));
    }
}

// ---------------- stage 4: router decision + parallel count scan -----------
__global__ void router_kernel() {
    int h = blockIdx.x;                    // 16 blocks, 256 threads
    int tid = threadIdx.x;
    __shared__ float s_score[LL];
    __shared__ unsigned char s_sel[LL];
    __shared__ int ps0[256], ps1[256];
    for (int l = tid; l < LL; l += 256) {
        float z0 = g_rlog[l * 32 + h * 2 + 0];
        float z1 = g_rlog[l * 32 + h * 2 + 1];
        int sel = (z1 > z0) ? 1 : 0;
        float m = fmaxf(z0, z1);
        float e0 = expf(z0 - m), e1 = expf(z1 - m);
        s_sel[l]   = (unsigned char)sel;
        s_score[l] = ((sel == 0) ? e0 : e1) / (e0 + e1);
    }
    __syncthreads();
    int base = tid * 8;
    int c0 = 0, c1 = 0;
    #pragma unroll
    for (int i = 0; i < 8; i++) {
        if (s_sel[base + i]) c1++; else c0++;
    }
    ps0[tid] = c0; ps1[tid] = c1;
    __syncthreads();
    for (int off = 1; off < 256; off <<= 1) {
        int v0 = (tid >= off) ? ps0[tid - off] : 0;
        int v1 = (tid >= off) ? ps1[tid - off] : 0;
        __syncthreads();
        ps0[tid] += v0; ps1[tid] += v1;
        __syncthreads();
    }
    int b0 = ps0[tid] - c0, b1 = ps1[tid] - c1;   // exclusive prefix
    const float scale = 0.125f;                   // HDK^{-1/2}
    #pragma unroll
    for (int i = 0; i < 8; i++) {
        int l = base + i;
        int sel = s_sel[l];
        int cnt;
        if (sel) { b1++; cnt = b1; } else { b0++; cnt = b0; }
        g_rsel[h * LL + l] = sel;
        g_coef[h * LL + l] = s_score[l] / (float)cnt * scale;
    }
}

// ---------------- stage 5: bf16 attention + fused LN/gate epilogue ---------
#define SU 36
#define AQH 0
#define AQL (AQH + 64*SU)
#define AKB (AQL + 64*SU)            // K: 2 stages x (hi, lo)
#define AKSTG (2*64*SU)
#define ASH (AKB + 2*AKSTG)
#define ASL (ASH + 64*SU)
#define AVH (ASL + 64*SU)            // V^T: 128 rows
#define AVL (AVH + 128*SU)
#define ACF (AVL + 128*SU)
#define ARR (ACF + 64)
#define ARC (ARR + 64)
#define ATTN4_WORDS (ARC + 64)
#define ATTN4_BYTES (ATTN4_WORDS * 4)   // ~108.8 KB -> 2 CTAs/SM

__global__ __launch_bounds__(256, 2) void attn_tc() {
    extern __shared__ unsigned smu[];
    unsigned* Qh = smu + AQH;  unsigned* Ql = smu + AQL;
    unsigned* Sh = smu + ASH;  unsigned* Sl = smu + ASL;
    unsigned* Vh = smu + AVH;  unsigned* Vl = smu + AVL;
    float* coef_r = (float*)(smu + ACF);
    int*   rsel_r = (int*)(smu + ARR);
    int*   rsel_c = (int*)(smu + ARC);

    int h   = blockIdx.y;
    int l0  = (gridDim.x - 1 - blockIdx.x) * 64;   // heavy tiles first
    int tid = threadIdx.x, lane = tid & 31, warp = tid >> 5;
    int g = lane >> 2, t = lane & 3;
    int wm  = (warp >> 1) * 16;
    int wns = (warp & 1) * 32;
    int wno = (warp & 1) * 64;

    const __nv_bfloat16* Kh_g  = g_kh  + (size_t)h * LL * HDKK;
    const __nv_bfloat16* Kl_g  = g_kl  + (size_t)h * LL * HDKK;
    const __nv_bfloat16* Vth_g = g_vth + (size_t)h * HDVV * LL;
    const __nv_bfloat16* Vtl_g = g_vtl + (size_t)h * HDVV * LL;

#define LOAD_K(s, m0) do {                                                  \
        unsigned* kh_ = smu + AKB + (s) * AKSTG;                            \
        unsigned* kl_ = kh_ + 64*SU;                                        \
        _Pragma("unroll")                                                   \
        for (int i_ = 0; i_ < 2; i_++) {                                    \
            int idx_ = tid + i_ * 256, r_ = idx_ >> 3, j_ = idx_ & 7;       \
            cp16b(kh_ + r_*SU + j_*4, Kh_g + (size_t)((m0)+r_)*HDKK + j_*8);\
            cp16b(kl_ + r_*SU + j_*4, Kl_g + (size_t)((m0)+r_)*HDKK + j_*8);\
        }                                                                   \
        asm volatile("cp.async.commit_group;\n" ::);                        \
    } while (0)

#define LOAD_V(m0) do {                                                     \
        _Pragma("unroll")                                                   \
        for (int i_ = 0; i_ < 4; i_++) {                                    \
            int idx_ = tid + i_ * 256, r_ = idx_ >> 3, j_ = idx_ & 7;       \
            cp16b(Vh + r_*SU + j_*4, Vth_g + (size_t)r_*LL + (m0) + j_*8);  \
            cp16b(Vl + r_*SU + j_*4, Vtl_g + (size_t)r_*LL + (m0) + j_*8);  \
        }                                                                   \
        asm volatile("cp.async.commit_group;\n" ::);                        \
    } while (0)

    // prologue: K(0) in flight, load Q + metadata
    LOAD_K(0, 0);
    {
        const __nv_bfloat16* Qh_g = g_qh + (size_t)h * LL * HDKK;
        const __nv_bfloat16* Ql_g = g_ql + (size_t)h * LL * HDKK;
        for (int i = tid; i < 64 * 8; i += 256) {
            int r = i >> 3, j = i & 7;
            *(uint4*)(Qh + r*SU + j*4) = *(const uint4*)(Qh_g + (size_t)(l0 + r)*HDKK + j*8);
            *(uint4*)(Ql + r*SU + j*4) = *(const uint4*)(Ql_g + (size_t)(l0 + r)*HDKK + j*8);
        }
    }
    if (tid < 64) {
        rsel_r[tid] = g_rsel[h * LL + l0 + tid];
        coef_r[tid] = g_coef[h * LL + l0 + tid];
    }

    float acc_o[8][4];
    #pragma unroll
    for (int fn = 0; fn < 8; fn++)
        #pragma unroll
        for (int r = 0; r < 4; r++) acc_o[fn][r] = 0.f;

    int ntiles = (l0 >> 6) + 1;
    for (int mt = 0; mt < ntiles; mt++) {
        int m0 = mt * 64;
        int s  = mt & 1;
        __syncthreads();                    // prev V/S reads done
        LOAD_V(m0);
        if (tid < 64) rsel_c[tid] = g_rsel[h * LL + m0 + tid];
        asm volatile("cp.async.wait_group 1;\n" ::);   // K(mt) done
        __syncthreads();

        const unsigned* Kts = smu + AKB + s * AKSTG;
        const unsigned* Kls = Kts + 64*SU;

        // ---- QK^T (bf16 3-term): warp tile 16x32, 4 k16 steps ----
        float acc_s[4][4];
        #pragma unroll
        for (int fn = 0; fn < 4; fn++)
            #pragma unroll
            for (int r = 0; r < 4; r++) acc_s[fn][r] = 0.f;

        #pragma unroll
        for (int kk = 0; kk < 4; kk++) {
            int p0 = kk * 8;
            int r0 = wm + g;
            unsigned ah0 = Qh[ r0      * SU + p0 + t];
            unsigned ah1 = Qh[(r0 + 8) * SU + p0 + t];
            unsigned ah2 = Qh[ r0      * SU + p0 + t + 4];
            unsigned ah3 = Qh[(r0 + 8) * SU + p0 + t + 4];
            unsigned al0 = Ql[ r0      * SU + p0 + t];
            unsigned al1 = Ql[(r0 + 8) * SU + p0 + t];
            unsigned al2 = Ql[ r0      * SU + p0 + t + 4];
            unsigned al3 = Ql[(r0 + 8) * SU + p0 + t + 4];
            #pragma unroll
            for (int fn = 0; fn < 4; fn++) {
                int c0 = wns + fn * 8 + g;
                unsigned bh0 = Kts[c0 * SU + p0 + t];
                unsigned bh1 = Kts[c0 * SU + p0 + t + 4];
                unsigned bl0 = Kls[c0 * SU + p0 + t];
                unsigned bl1 = Kls[c0 * SU + p0 + t + 4];
                mma16(acc_s[fn], ah0, ah1, ah2, ah3, bh0, bh1);
                mma16(acc_s[fn], ah0, ah1, ah2, ah3, bl0, bl1);
                mma16(acc_s[fn], al0, al1, al2, al3, bh0, bh1);
            }
        }

        // prefetch K(mt+1) — K(mt) reads are done
        if (mt + 1 < ntiles) LOAD_K(s ^ 1, m0 + 64);

        // ---- mask + coef, pack bf16 hi/lo pairs into S ----
        {
            int r0 = wm + g, r1 = r0 + 8;
            int gl0 = l0 + r0, gl1 = l0 + r1;
            int e0 = rsel_r[r0], e1 = rsel_r[r1];
            float cf0 = coef_r[r0], cf1 = coef_r[r1];
            #pragma unroll
            for (int fn = 0; fn < 4; fn++) {
                int c = wns + fn * 8 + 2 * t;
                int gm0 = m0 + c, gm1 = gm0 + 1;
                int ec0 = rsel_c[c], ec1 = rsel_c[c + 1];
                float s00 = (gm0 <= gl0 && ec0 == e0) ? acc_s[fn][0] * cf0 : 0.f;
                float s01 = (gm1 <= gl0 && ec1 == e0) ? acc_s[fn][1] * cf0 : 0.f;
                float s10 = (gm0 <= gl1 && ec0 == e1) ? acc_s[fn][2] * cf1 : 0.f;
                float s11 = (gm1 <= gl1 && ec1 == e1) ? acc_s[fn][3] * cf1 : 0.f;
                unsigned h00, l00, h01, l01, h10, l10, h11, l11;
                split_bf(s00, h00, l00); split_bf(s01, h01, l01);
                split_bf(s10, h10, l10); split_bf(s11, h11, l11);
                int pi = (wns >> 1) + fn * 4 + t;
                Sh[r0 * SU + pi] = h00 | (h01 << 16);
                Sl[r0 * SU + pi] = l00 | (l01 << 16);
                Sh[r1 * SU + pi] = h10 | (h11 << 16);
                Sl[r1 * SU + pi] = l10 | (l11 << 16);
            }
        }
        if (mt + 1 < ntiles)
            asm volatile("cp.async.wait_group 1;\n" ::);  // V(mt) done, K(mt+1) pending
        else
            asm volatile("cp.async.wait_group 0;\n" ::);  // last tile: V must be done
        __syncthreads();                                   // S + V visible

        // ---- O += S @ V (bf16 3-term): warp tile 16x64, 4 k16 steps ----
        #pragma unroll
        for (int kk = 0; kk < 4; kk++) {
            int p0 = kk * 8;
            int r0 = wm + g;
            unsigned ah0 = Sh[ r0      * SU + p0 + t];
            unsigned ah1 = Sh[(r0 + 8) * SU + p0 + t];
            unsigned ah2 = Sh[ r0      * SU + p0 + t + 4];
            unsigned ah3 = Sh[(r0 + 8) * SU + p0 + t + 4];
            unsigned al0 = Sl[ r0      * SU + p0 + t];
            unsigned al1 = Sl[(r0 + 8) * SU + p0 + t];
            unsigned al2 = Sl[ r0      * SU + p0 + t + 4];
            unsigned al3 = Sl[(r0 + 8) * SU + p0 + t + 4];
            #pragma unroll
            for (int fn = 0; fn < 8; fn++) {
                int c0 = wno + fn * 8 + g;
                unsigned bh0 = Vh[c0 * SU + p0 + t];
                unsigned bh1 = Vh[c0 * SU + p0 + t + 4];
                unsigned bl0 = Vl[c0 * SU + p0 + t];
                unsigned bl1 = Vl[c0 * SU + p0 + t + 4];
                mma16(acc_o[fn], ah0, ah1, ah2, ah3, bh0, bh1);
                mma16(acc_o[fn], ah0, ah1, ah2, ah3, bl0, bl1);
                mma16(acc_o[fn], al0, al1, al2, al3, bh0, bh1);
            }
        }
    }

    // ---- fused LayerNorm(128) * silu(gate) epilogue ----
    __syncthreads();                          // all smem reads done; reuse Sh region
    float* red_s = (float*)(smu + ASH);       // [128]: half*64 + row
    float* red_q = red_s + 128;               // [128]
    {
        int half = warp & 1;
        int r0 = wm + g, r1 = r0 + 8;
        float s0 = 0.f, q0 = 0.f, s1 = 0.f, q1 = 0.f;
        #pragma unroll
        for (int fn = 0; fn < 8; fn++) {
            float v0 = acc_o[fn][0], v1 = acc_o[fn][1];
            float v2 = acc_o[fn][2], v3 = acc_o[fn][3];
            s0 += v0 + v1;  q0 += v0*v0 + v1*v1;
            s1 += v2 + v3;  q1 += v2*v2 + v3*v3;
        }
        #pragma unroll
        for (int off = 1; off <= 2; off <<= 1) {
            s0 += __shfl_xor_sync(0xffffffffu, s0, off);
            q0 += __shfl_xor_sync(0xffffffffu, q0, off);
            s1 += __shfl_xor_sync(0xffffffffu, s1, off);
            q1 += __shfl_xor_sync(0xffffffffu, q1, off);
        }
        if (t == 0) {
            red_s[half*64 + r0] = s0;  red_q[half*64 + r0] = q0;
            red_s[half*64 + r1] = s1;  red_q[half*64 + r1] = q1;
        }
        __syncthreads();
        float S0 = red_s[r0] + red_s[64 + r0];
        float Q0 = red_q[r0] + red_q[64 + r0];
        float S1 = red_s[r1] + red_s[64 + r1];
        float Q1 = red_q[r1] + red_q[64 + r1];
        float mu0 = S0 * (1.f/128.f), mu1 = S1 * (1.f/128.f);
        float inv0 = rsqrtf(Q0 * (1.f/128.f) - mu0*mu0 + 1e-5f);
        float inv1 = rsqrtf(Q1 * (1.f/128.f) - mu1*mu1 + 1e-5f);
        size_t gbase0 = (size_t)(l0 + r0) * NCAT + 2*DKK + DVV + h * HDVV;
        size_t gbase1 = (size_t)(l0 + r1) * NCAT + 2*DKK + DVV + h * HDVV;
        size_t ybase0 = (size_t)(l0 + r0) * DVV + h * HDVV;
        size_t ybase1 = (size_t)(l0 + r1) * DVV + h * HDVV;
        #pragma unroll
        for (int fn = 0; fn < 8; fn++) {
            int c = wno + fn * 8 + 2 * t;
            float2 gt0 = *(const float2*)(g_qkvg + gbase0 + c);
            float2 gt1 = *(const float2*)(g_qkvg + gbase1 + c);
            float2 y0, y1;
            y0.x = tf32r(silu_f(gt0.x) * (acc_o[fn][0] - mu0) * inv0);
            y0.y = tf32r(silu_f(gt0.y) * (acc_o[fn][1] - mu0) * inv0);
            y1.x = tf32r(silu_f(gt1.x) * (acc_o[fn][2] - mu1) * inv1);
            y1.y = tf32r(silu_f(gt1.y) * (acc_o[fn][3] - mu1) * inv1);
            *(float2*)(g_y + ybase0 + c) = y0;
            *(float2*)(g_y + ybase1 + c) = y1;
        }
    }
}

// ---------------- launch ----------------------------------------------------
extern "C" void kernel_launch(void* const* d_in, const int* in_sizes, int n_in,
                              void* d_out, int out_size) {
    const float* x    = (const float*)d_in[0];
    const float* cw   = (const float*)d_in[1];
    const float* Wq   = (const float*)d_in[2];
    const float* Wk   = (const float*)d_in[3];
    const float* Wv   = (const float*)d_in[4];
    const float* Wg   = (const float*)d_in[5];
    const float* rw   = (const float*)d_in[6];
    const float* Wout = (const float*)d_in[7];
    float* out = (float*)d_out;

    float *p_xctf, *p_wcat, *p_qkvg, *p_y;
    cudaGetSymbolAddress((void**)&p_xctf, g_xctf);
    cudaGetSymbolAddress((void**)&p_wcat, g_wcat);
    cudaGetSymbolAddress((void**)&p_qkvg, g_qkvg);
    cudaGetSymbolAddress((void**)&p_y,    g_y);

    cudaFuncSetAttribute(attn_tc,
                         cudaFuncAttributeMaxDynamicSharedMemorySize, ATTN4_BYTES);
    cudaFuncSetAttribute(gemm_tc<false>,
                         cudaFuncAttributeMaxDynamicSharedMemorySize, SMEM_GEMM);
    cudaFuncSetAttribute(gemm_tc<true>,
                         cudaFuncAttributeMaxDynamicSharedMemorySize, SMEM_GEMM);

    conv_silu_kernel<<<(LL*DD)/256, 256>>>(x, cw);
    wcat_kernel<<<(DD*NCAT/4 + 255)/256, 256>>>(Wq, Wk, Wv, Wg);
    w2_kernel<<<DD/8, 256>>>(Wv, rw);

    // fused QKVG projection (silu on q columns)
    gemm_tc<false><<<dim3(NCAT/128, LL/128), 256, SMEM_GEMM>>>(p_xctf, p_wcat, p_qkvg,
                                                               LL, NCAT, DD, DKK);
    rlog_kernel<<<LL/8, 256>>>();

    rope_split_kernel<<<(LL*HH*32)/256, 256>>>();
    vsplit_t_kernel<<<dim3(LL/64, HDVV/32, HH), 256>>>();
    router_kernel<<<HH, 256>>>();

    attn_tc<<<dim3(LL/64, HH), 256, ATTN4_BYTES>>>();

    gemm_tc<true><<<dim3(DD/128, LL/128), 256, SMEM_GEMM>>>(p_y, Wout, out,
                                                            LL, DD, DVV, 0);
}

// round 12
// speedup vs baseline: 4.2110x; 1.0127x over previous
#include <cuda_runtime.h>
#include <cuda_bf16.h>
#include <math.h>

#define LL   2048
#define DD   2048
#define HH   16
#define DKK  1024
#define DVV  2048
#define HDKK 64
#define HDVV 128
#define NCAT 6144              // q(1024) | k(1024) | v(2048) | g(2048)

// ---------------- scratch (device globals; no allocation allowed) ----------
__device__ float g_xc  [LL*DD];      // conv+silu output (fp32 exact, for router)
__device__ float g_xctf[LL*DD];      // conv+silu output, tf32-rounded (GEMM A)
__device__ float g_qkvg[LL*NCAT];    // fused projection output
__device__ float g_w2  [DD*32];      // Wv @ router_w  (fp32 exact)
__device__ float g_rlog[LL*32];      // router logits  (fp32 exact)
__device__ __nv_bfloat16 g_qh[LL*DKK];   // roped q hi, [h][l][64]
__device__ __nv_bfloat16 g_ql[LL*DKK];   // roped q lo
__device__ __nv_bfloat16 g_kh[LL*DKK];   // roped k hi
__device__ __nv_bfloat16 g_kl[LL*DKK];   // roped k lo
__device__ __nv_bfloat16 g_vth[HH*HDVV*LL]; // v hi, TRANSPOSED [h][c][l]
__device__ __nv_bfloat16 g_vtl[HH*HDVV*LL]; // v lo, transposed
__device__ float g_y   [LL*DVV];     // silu(g)*LN(o), tf32-rounded
__device__ float g_coef[HH*LL];      // score_max/count * HDK^-0.5
__device__ int   g_rsel[HH*LL];      // selected expert per (h,l)

__device__ __forceinline__ float silu_f(float z) { return z / (1.f + expf(-z)); }

__device__ __forceinline__ unsigned f2tf(float f) {
    unsigned r;
    asm("cvt.rna.tf32.f32 %0, %1;" : "=r"(r) : "f"(f));
    return r;
}
__device__ __forceinline__ float tf32r(float f) { return __uint_as_float(f2tf(f)); }

__device__ __forceinline__ unsigned f2bfu(float f) {
    return (unsigned)__bfloat16_as_ushort(__float2bfloat16_rn(f));
}
__device__ __forceinline__ float bfu2f(unsigned u) {
    return __bfloat162float(__ushort_as_bfloat16((unsigned short)u));
}
__device__ __forceinline__ void split_bf(float v, unsigned& hi, unsigned& lo) {
    hi = f2bfu(v);
    lo = f2bfu(v - bfu2f(hi));
}

__device__ __forceinline__ void mma8(float* c,
                                     unsigned a0, unsigned a1, unsigned a2, unsigned a3,
                                     unsigned b0, unsigned b1) {
    asm("mma.sync.aligned.m16n8k8.row.col.f32.tf32.tf32.f32 "
        "{%0,%1,%2,%3}, {%4,%5,%6,%7}, {%8,%9}, {%0,%1,%2,%3};"
        : "+f"(c[0]), "+f"(c[1]), "+f"(c[2]), "+f"(c[3])
        : "r"(a0), "r"(a1), "r"(a2), "r"(a3), "r"(b0), "r"(b1));
}

__device__ __forceinline__ void mma16(float* c,
                                      unsigned a0, unsigned a1, unsigned a2, unsigned a3,
                                      unsigned b0, unsigned b1) {
    asm("mma.sync.aligned.m16n8k16.row.col.f32.bf16.bf16.f32 "
        "{%0,%1,%2,%3}, {%4,%5,%6,%7}, {%8,%9}, {%0,%1,%2,%3};"
        : "+f"(c[0]), "+f"(c[1]), "+f"(c[2]), "+f"(c[3])
        : "r"(a0), "r"(a1), "r"(a2), "r"(a3), "r"(b0), "r"(b1));
}

__device__ __forceinline__ void cp16(float* smem_dst, const float* gsrc) {
    unsigned sa = (unsigned)__cvta_generic_to_shared(smem_dst);
    asm volatile("cp.async.cg.shared.global [%0], [%1], 16;\n"
                 :: "r"(sa), "l"(gsrc));
}
__device__ __forceinline__ void cp16b(unsigned* smem_dst, const __nv_bfloat16* gsrc) {
    unsigned sa = (unsigned)__cvta_generic_to_shared(smem_dst);
    asm volatile("cp.async.cg.shared.global [%0], [%1], 16;\n"
                 :: "r"(sa), "l"(gsrc));
}

// ---------------- stage 1: shifted conv + silu -----------------------------
__global__ void conv_silu_kernel(const float* __restrict__ x,
                                 const float* __restrict__ cw) {
    int idx = blockIdx.x * blockDim.x + threadIdx.x;  // over L*D
    if (idx >= LL*DD) return;
    int d = idx & (DD-1);
    int l = idx >> 11;
    float prev = (l == 0) ? 0.f : x[idx - DD];
    float z = prev * cw[2*d] + x[idx] * cw[2*d + 1];
    float v = silu_f(z);
    g_xc[idx]   = v;
    g_xctf[idx] = tf32r(v);
}

// ---------------- W2 = Wv @ router_w (fp32 exact, [2048][32]) --------------
__global__ void w2_kernel(const float* __restrict__ Wv,
                          const float* __restrict__ rw) {
    int tid = threadIdx.x;                 // 256 threads, 8 k-rows per block
    int k  = blockIdx.x * 8 + (tid >> 5);
    int t  = tid & 31;
    int h  = t >> 1, r = t & 1;
    const float* wrow = Wv + (size_t)k * DVV + h * HDVV;
    const float* rr   = rw + (h * HDVV) * 2 + r;
    float a0 = 0.f, a1 = 0.f, a2 = 0.f, a3 = 0.f;
    #pragma unroll 8
    for (int d = 0; d < HDVV; d += 4) {
        a0 += wrow[d]     * rr[2*d];
        a1 += wrow[d + 1] * rr[2*d + 2];
        a2 += wrow[d + 2] * rr[2*d + 4];
        a3 += wrow[d + 3] * rr[2*d + 6];
    }
    g_w2[k * 32 + t] = (a0 + a1) + (a2 + a3);
}

// ---------------- router logits = xc @ W2 (fp32 exact, [2048][32]) ---------
__global__ void rlog_kernel() {
    int tid = threadIdx.x;
    int hr  = tid & 31;
    int l   = blockIdx.x * 8 + (tid >> 5);
    const float* xrow = g_xc + (size_t)l * DD;
    float acc = 0.f;
    #pragma unroll 4
    for (int k = 0; k < DD; k++)
        acc += xrow[k] * g_w2[k * 32 + hr];
    g_rlog[l * 32 + hr] = acc;
}

// ---------------- tensor-core GEMM (TF32, 3-stage cp.async) ----------------
// A pre-rounded tf32 in gmem. B raw fp32; fragments cvt'd in-loop.
// SEG: B segmented over {B0:q, B1:k, B2:v, B3:g} at 1024/2048/4096 col splits.
#define AP 36
#define BPAD 136
#define STGF (128*AP + 32*BPAD)       // floats per stage = 8960
#define SMEM_GEMM3 (3 * STGF * 4)     // 107520 bytes

template<bool SEG>
__global__ __launch_bounds__(256, 2) void gemm_tc(
        const float* __restrict__ A,
        const float* __restrict__ B0,
        const float* __restrict__ B1,
        const float* __restrict__ B2,
        const float* __restrict__ B3,
        float* __restrict__ C,
        int N, int K, int silu_ncols) {
    extern __shared__ float sm[];

    int tid = threadIdx.x, lane = tid & 31, warp = tid >> 5;
    int bm = blockIdx.y * 128, bn = blockIdx.x * 128;
    int wm = (warp >> 2) * 64, wn = (warp & 3) * 32;
    int g = lane >> 2, t = lane & 3;

    const float* Bseg; int ldb, bcol;
    if (SEG) {
        if (bn < 1024)      { Bseg = B0; ldb = 1024; bcol = bn; }
        else if (bn < 2048) { Bseg = B1; ldb = 1024; bcol = bn - 1024; }
        else if (bn < 4096) { Bseg = B2; ldb = 2048; bcol = bn - 2048; }
        else                { Bseg = B3; ldb = 2048; bcol = bn - 4096; }
    } else {
        Bseg = B0; ldb = N; bcol = bn;
    }

    float acc[4][4][4];
    #pragma unroll
    for (int i = 0; i < 4; i++)
        #pragma unroll
        for (int j = 0; j < 4; j++)
            #pragma unroll
            for (int r = 0; r < 4; r++) acc[i][j][r] = 0.f;

    const float* agp[4];
    const float* bgp[4];
    int asp[4], bsp[4];
    #pragma unroll
    for (int i = 0; i < 4; i++) {
        int idx = tid + i * 256;
        int ar = idx >> 3, ac = (idx & 7) * 4;
        int br = idx >> 5, bc = (idx & 31) * 4;
        agp[i] = A + (size_t)(bm + ar) * K + ac;
        bgp[i] = Bseg + (size_t)br * ldb + bcol + bc;
        asp[i] = ar * AP + ac;
        bsp[i] = 128 * AP + br * BPAD + bc;
    }

#define LOAD_STAGE(s, k0) do {                                          \
        float* base_ = sm + (s) * STGF;                                 \
        _Pragma("unroll")                                               \
        for (int i_ = 0; i_ < 4; i_++) {                                \
            cp16(base_ + asp[i_], agp[i_] + (k0));                      \
            cp16(base_ + bsp[i_], bgp[i_] + (size_t)(k0) * ldb);        \
        }                                                               \
        asm volatile("cp.async.commit_group;\n" ::);                    \
    } while (0)

    int nk = K >> 5;
    LOAD_STAGE(0, 0);
    LOAD_STAGE(1, 32);
    LOAD_STAGE(2, 64);

    int s = 0;
    for (int kt = 0; kt < nk; kt++) {
        asm volatile("cp.async.wait_group 2;\n" ::);
        __syncthreads();
        const float* Ah = sm + s * STGF;
        const float* Bh = Ah + 128 * AP;

        #pragma unroll
        for (int ko = 0; ko < 32; ko += 8) {
            unsigned af[4][4], bf[4][2];
            #pragma unroll
            for (int fm = 0; fm < 4; fm++) {
                int r0 = wm + fm * 16 + g;
                af[fm][0] = __float_as_uint(Ah[ r0      * AP + ko + t]);
                af[fm][1] = __float_as_uint(Ah[(r0 + 8) * AP + ko + t]);
                af[fm][2] = __float_as_uint(Ah[ r0      * AP + ko + t + 4]);
                af[fm][3] = __float_as_uint(Ah[(r0 + 8) * AP + ko + t + 4]);
            }
            #pragma unroll
            for (int fn = 0; fn < 4; fn++) {
                int c0 = wn + fn * 8 + g;
                bf[fn][0] = f2tf(Bh[(ko + t    ) * BPAD + c0]);
                bf[fn][1] = f2tf(Bh[(ko + t + 4) * BPAD + c0]);
            }
            #pragma unroll
            for (int fm = 0; fm < 4; fm++)
                #pragma unroll
                for (int fn = 0; fn < 4; fn++)
                    mma8(acc[fm][fn], af[fm][0], af[fm][1], af[fm][2], af[fm][3],
                         bf[fn][0], bf[fn][1]);
        }
        __syncthreads();
        if (kt + 3 < nk) LOAD_STAGE(s, (kt + 3) * 32);
        s = (s == 2) ? 0 : s + 1;
    }

    #pragma unroll
    for (int fm = 0; fm < 4; fm++) {
        int r0 = bm + wm + fm * 16 + g;
        #pragma unroll
        for (int fn = 0; fn < 4; fn++) {
            int c0 = bn + wn + fn * 8 + 2 * t;
            float v0 = acc[fm][fn][0], v1 = acc[fm][fn][1];
            float v2 = acc[fm][fn][2], v3 = acc[fm][fn][3];
            if (c0 < silu_ncols) {
                v0 = silu_f(v0); v1 = silu_f(v1);
                v2 = silu_f(v2); v3 = silu_f(v3);
            }
            *(float2*)(C + (size_t)r0 * N + c0)       = make_float2(v0, v1);
            *(float2*)(C + (size_t)(r0 + 8) * N + c0) = make_float2(v2, v3);
        }
    }
#undef LOAD_STAGE
}

// ---------------- stage 3: RoPE + bf16 hi/lo split, head-major -------------
__global__ void rope_split_kernel() {
    int idx = blockIdx.x * blockDim.x + threadIdx.x;   // L*H*32
    if (idx >= LL * HH * 32) return;
    int i  = idx & 31;
    int lh = idx >> 5;
    int h  = lh & (HH-1);
    int l  = lh >> 4;
    float invf = powf(10000.f, -(float)i / 32.f);
    float ang = (float)l * invf;
    float c = cosf(ang), s = sinf(ang);
    size_t qb = (size_t)l * NCAT + h * HDKK;
    size_t kb = qb + DKK;
    size_t ob = ((size_t)h * LL + l) * HDKK;
    float q1 = g_qkvg[qb + i], q2 = g_qkvg[qb + 32 + i];
    float k1 = g_qkvg[kb + i], k2 = g_qkvg[kb + 32 + i];
    float qa = q1 * c - q2 * s, qbv = q2 * c + q1 * s;
    float ka = k1 * c - k2 * s, kbv = k2 * c + k1 * s;
    __nv_bfloat16 hb;
    hb = __float2bfloat16_rn(qa);
    g_qh[ob + i] = hb;  g_ql[ob + i] = __float2bfloat16_rn(qa - __bfloat162float(hb));
    hb = __float2bfloat16_rn(qbv);
    g_qh[ob + 32 + i] = hb;  g_ql[ob + 32 + i] = __float2bfloat16_rn(qbv - __bfloat162float(hb));
    hb = __float2bfloat16_rn(ka);
    g_kh[ob + i] = hb;  g_kl[ob + i] = __float2bfloat16_rn(ka - __bfloat162float(hb));
    hb = __float2bfloat16_rn(kbv);
    g_kh[ob + 32 + i] = hb;  g_kl[ob + 32 + i] = __float2bfloat16_rn(kbv - __bfloat162float(hb));
}

// ---------------- v transpose + bf16 split: [h][c][l] ----------------------
__global__ void vsplit_t_kernel() {
    __shared__ float tile[64][33];
    int l0 = blockIdx.x * 64, c0 = blockIdx.y * 32, h = blockIdx.z;
    int tid = threadIdx.x;
    for (int i = tid; i < 64 * 32; i += 256) {
        int li = i >> 5, ci = i & 31;
        tile[li][ci] = g_qkvg[(size_t)(l0 + li) * NCAT + 2*DKK + h * HDVV + c0 + ci];
    }
    __syncthreads();
    for (int i = tid; i < 32 * 64; i += 256) {
        int ci = i >> 6, li = i & 63;
        float v = tile[li][ci];
        __nv_bfloat16 hb = __float2bfloat16_rn(v);
        size_t ob = ((size_t)h * HDVV + c0 + ci) * LL + l0 + li;
        g_vth[ob] = hb;
        g_vtl[ob] = __float2bfloat16_rn(v - __bfloat162float(hb));
    }
}

// ---------------- stage 4: router decision + parallel count scan -----------
__global__ void router_kernel() {
    int h = blockIdx.x;                    // 16 blocks, 256 threads
    int tid = threadIdx.x;
    __shared__ float s_score[LL];
    __shared__ unsigned char s_sel[LL];
    __shared__ int ps0[256], ps1[256];
    for (int l = tid; l < LL; l += 256) {
        float z0 = g_rlog[l * 32 + h * 2 + 0];
        float z1 = g_rlog[l * 32 + h * 2 + 1];
        int sel = (z1 > z0) ? 1 : 0;
        float m = fmaxf(z0, z1);
        float e0 = expf(z0 - m), e1 = expf(z1 - m);
        s_sel[l]   = (unsigned char)sel;
        s_score[l] = ((sel == 0) ? e0 : e1) / (e0 + e1);
    }
    __syncthreads();
    int base = tid * 8;
    int c0 = 0, c1 = 0;
    #pragma unroll
    for (int i = 0; i < 8; i++) {
        if (s_sel[base + i]) c1++; else c0++;
    }
    ps0[tid] = c0; ps1[tid] = c1;
    __syncthreads();
    for (int off = 1; off < 256; off <<= 1) {
        int v0 = (tid >= off) ? ps0[tid - off] : 0;
        int v1 = (tid >= off) ? ps1[tid - off] : 0;
        __syncthreads();
        ps0[tid] += v0; ps1[tid] += v1;
        __syncthreads();
    }
    int b0 = ps0[tid] - c0, b1 = ps1[tid] - c1;   // exclusive prefix
    const float scale = 0.125f;                   // HDK^{-1/2}
    #pragma unroll
    for (int i = 0; i < 8; i++) {
        int l = base + i;
        int sel = s_sel[l];
        int cnt;
        if (sel) { b1++; cnt = b1; } else { b0++; cnt = b0; }
        g_rsel[h * LL + l] = sel;
        g_coef[h * LL + l] = s_score[l] / (float)cnt * scale;
    }
}

// ---------------- stage 5: bf16 attention + fused LN/gate epilogue ---------
#define SU 36
#define AQH 0
#define AQL (AQH + 64*SU)
#define AKB (AQL + 64*SU)            // K: 2 stages x (hi, lo)
#define AKSTG (2*64*SU)
#define ASH (AKB + 2*AKSTG)
#define ASL (ASH + 64*SU)
#define AVH (ASL + 64*SU)            // V^T: 128 rows
#define AVL (AVH + 128*SU)
#define ACF (AVL + 128*SU)
#define ARR (ACF + 64)
#define ARC (ARR + 64)
#define ATTN4_WORDS (ARC + 64)
#define ATTN4_BYTES (ATTN4_WORDS * 4)   // ~108.8 KB -> 2 CTAs/SM

__global__ __launch_bounds__(256, 2) void attn_tc() {
    extern __shared__ unsigned smu[];
    unsigned* Qh = smu + AQH;  unsigned* Ql = smu + AQL;
    unsigned* Sh = smu + ASH;  unsigned* Sl = smu + ASL;
    unsigned* Vh = smu + AVH;  unsigned* Vl = smu + AVL;
    float* coef_r = (float*)(smu + ACF);
    int*   rsel_r = (int*)(smu + ARR);
    int*   rsel_c = (int*)(smu + ARC);

    int h   = blockIdx.y;
    int l0  = (gridDim.x - 1 - blockIdx.x) * 64;   // heavy tiles first
    int tid = threadIdx.x, lane = tid & 31, warp = tid >> 5;
    int g = lane >> 2, t = lane & 3;
    int wm  = (warp >> 1) * 16;
    int wns = (warp & 1) * 32;
    int wno = (warp & 1) * 64;

    const __nv_bfloat16* Kh_g  = g_kh  + (size_t)h * LL * HDKK;
    const __nv_bfloat16* Kl_g  = g_kl  + (size_t)h * LL * HDKK;
    const __nv_bfloat16* Vth_g = g_vth + (size_t)h * HDVV * LL;
    const __nv_bfloat16* Vtl_g = g_vtl + (size_t)h * HDVV * LL;

#define LOAD_K(s, m0) do {                                                  \
        unsigned* kh_ = smu + AKB + (s) * AKSTG;                            \
        unsigned* kl_ = kh_ + 64*SU;                                        \
        _Pragma("unroll")                                                   \
        for (int i_ = 0; i_ < 2; i_++) {                                    \
            int idx_ = tid + i_ * 256, r_ = idx_ >> 3, j_ = idx_ & 7;       \
            cp16b(kh_ + r_*SU + j_*4, Kh_g + (size_t)((m0)+r_)*HDKK + j_*8);\
            cp16b(kl_ + r_*SU + j_*4, Kl_g + (size_t)((m0)+r_)*HDKK + j_*8);\
        }                                                                   \
        asm volatile("cp.async.commit_group;\n" ::);                        \
    } while (0)

#define LOAD_V(m0) do {                                                     \
        _Pragma("unroll")                                                   \
        for (int i_ = 0; i_ < 4; i_++) {                                    \
            int idx_ = tid + i_ * 256, r_ = idx_ >> 3, j_ = idx_ & 7;       \
            cp16b(Vh + r_*SU + j_*4, Vth_g + (size_t)r_*LL + (m0) + j_*8);  \
            cp16b(Vl + r_*SU + j_*4, Vtl_g + (size_t)r_*LL + (m0) + j_*8);  \
        }                                                                   \
        asm volatile("cp.async.commit_group;\n" ::);                        \
    } while (0)

    // prologue: K(0) in flight, load Q + metadata
    LOAD_K(0, 0);
    {
        const __nv_bfloat16* Qh_g = g_qh + (size_t)h * LL * HDKK;
        const __nv_bfloat16* Ql_g = g_ql + (size_t)h * LL * HDKK;
        for (int i = tid; i < 64 * 8; i += 256) {
            int r = i >> 3, j = i & 7;
            *(uint4*)(Qh + r*SU + j*4) = *(const uint4*)(Qh_g + (size_t)(l0 + r)*HDKK + j*8);
            *(uint4*)(Ql + r*SU + j*4) = *(const uint4*)(Ql_g + (size_t)(l0 + r)*HDKK + j*8);
        }
    }
    if (tid < 64) {
        rsel_r[tid] = g_rsel[h * LL + l0 + tid];
        coef_r[tid] = g_coef[h * LL + l0 + tid];
    }

    float acc_o[8][4];
    #pragma unroll
    for (int fn = 0; fn < 8; fn++)
        #pragma unroll
        for (int r = 0; r < 4; r++) acc_o[fn][r] = 0.f;

    int ntiles = (l0 >> 6) + 1;
    for (int mt = 0; mt < ntiles; mt++) {
        int m0 = mt * 64;
        int s  = mt & 1;
        __syncthreads();                    // prev V/S reads done
        LOAD_V(m0);
        if (tid < 64) rsel_c[tid] = g_rsel[h * LL + m0 + tid];
        asm volatile("cp.async.wait_group 1;\n" ::);   // K(mt) done
        __syncthreads();

        const unsigned* Kts = smu + AKB + s * AKSTG;
        const unsigned* Kls = Kts + 64*SU;

        // ---- QK^T (bf16 3-term): warp tile 16x32, 4 k16 steps ----
        float acc_s[4][4];
        #pragma unroll
        for (int fn = 0; fn < 4; fn++)
            #pragma unroll
            for (int r = 0; r < 4; r++) acc_s[fn][r] = 0.f;

        #pragma unroll
        for (int kk = 0; kk < 4; kk++) {
            int p0 = kk * 8;
            int r0 = wm + g;
            unsigned ah0 = Qh[ r0      * SU + p0 + t];
            unsigned ah1 = Qh[(r0 + 8) * SU + p0 + t];
            unsigned ah2 = Qh[ r0      * SU + p0 + t + 4];
            unsigned ah3 = Qh[(r0 + 8) * SU + p0 + t + 4];
            unsigned al0 = Ql[ r0      * SU + p0 + t];
            unsigned al1 = Ql[(r0 + 8) * SU + p0 + t];
            unsigned al2 = Ql[ r0      * SU + p0 + t + 4];
            unsigned al3 = Ql[(r0 + 8) * SU + p0 + t + 4];
            #pragma unroll
            for (int fn = 0; fn < 4; fn++) {
                int c0 = wns + fn * 8 + g;
                unsigned bh0 = Kts[c0 * SU + p0 + t];
                unsigned bh1 = Kts[c0 * SU + p0 + t + 4];
                unsigned bl0 = Kls[c0 * SU + p0 + t];
                unsigned bl1 = Kls[c0 * SU + p0 + t + 4];
                mma16(acc_s[fn], ah0, ah1, ah2, ah3, bh0, bh1);
                mma16(acc_s[fn], ah0, ah1, ah2, ah3, bl0, bl1);
                mma16(acc_s[fn], al0, al1, al2, al3, bh0, bh1);
            }
        }

        // prefetch K(mt+1) — K(mt) reads are done
        if (mt + 1 < ntiles) LOAD_K(s ^ 1, m0 + 64);

        // ---- mask + coef, pack bf16 hi/lo pairs into S ----
        {
            int r0 = wm + g, r1 = r0 + 8;
            int gl0 = l0 + r0, gl1 = l0 + r1;
            int e0 = rsel_r[r0], e1 = rsel_r[r1];
            float cf0 = coef_r[r0], cf1 = coef_r[r1];
            #pragma unroll
            for (int fn = 0; fn < 4; fn++) {
                int c = wns + fn * 8 + 2 * t;
                int gm0 = m0 + c, gm1 = gm0 + 1;
                int ec0 = rsel_c[c], ec1 = rsel_c[c + 1];
                float s00 = (gm0 <= gl0 && ec0 == e0) ? acc_s[fn][0] * cf0 : 0.f;
                float s01 = (gm1 <= gl0 && ec1 == e0) ? acc_s[fn][1] * cf0 : 0.f;
                float s10 = (gm0 <= gl1 && ec0 == e1) ? acc_s[fn][2] * cf1 : 0.f;
                float s11 = (gm1 <= gl1 && ec1 == e1) ? acc_s[fn][3] * cf1 : 0.f;
                unsigned h00, l00, h01, l01, h10, l10, h11, l11;
                split_bf(s00, h00, l00); split_bf(s01, h01, l01);
                split_bf(s10, h10, l10); split_bf(s11, h11, l11);
                int pi = (wns >> 1) + fn * 4 + t;
                Sh[r0 * SU + pi] = h00 | (h01 << 16);
                Sl[r0 * SU + pi] = l00 | (l01 << 16);
                Sh[r1 * SU + pi] = h10 | (h11 << 16);
                Sl[r1 * SU + pi] = l10 | (l11 << 16);
            }
        }
        if (mt + 1 < ntiles)
            asm volatile("cp.async.wait_group 1;\n" ::);  // V(mt) done, K(mt+1) pending
        else
            asm volatile("cp.async.wait_group 0;\n" ::);  // last tile: V must be done
        __syncthreads();                                   // S + V visible

        // ---- O += S @ V (bf16 3-term): warp tile 16x64, 4 k16 steps ----
        #pragma unroll
        for (int kk = 0; kk < 4; kk++) {
            int p0 = kk * 8;
            int r0 = wm + g;
            unsigned ah0 = Sh[ r0      * SU + p0 + t];
            unsigned ah1 = Sh[(r0 + 8) * SU + p0 + t];
            unsigned ah2 = Sh[ r0      * SU + p0 + t + 4];
            unsigned ah3 = Sh[(r0 + 8) * SU + p0 + t + 4];
            unsigned al0 = Sl[ r0      * SU + p0 + t];
            unsigned al1 = Sl[(r0 + 8) * SU + p0 + t];
            unsigned al2 = Sl[ r0      * SU + p0 + t + 4];
            unsigned al3 = Sl[(r0 + 8) * SU + p0 + t + 4];
            #pragma unroll
            for (int fn = 0; fn < 8; fn++) {
                int c0 = wno + fn * 8 + g;
                unsigned bh0 = Vh[c0 * SU + p0 + t];
                unsigned bh1 = Vh[c0 * SU + p0 + t + 4];
                unsigned bl0 = Vl[c0 * SU + p0 + t];
                unsigned bl1 = Vl[c0 * SU + p0 + t + 4];
                mma16(acc_o[fn], ah0, ah1, ah2, ah3, bh0, bh1);
                mma16(acc_o[fn], ah0, ah1, ah2, ah3, bl0, bl1);
                mma16(acc_o[fn], al0, al1, al2, al3, bh0, bh1);
            }
        }
    }

    // ---- fused LayerNorm(128) * silu(gate) epilogue ----
    __syncthreads();                          // all smem reads done; reuse Sh region
    float* red_s = (float*)(smu + ASH);       // [128]: half*64 + row
    float* red_q = red_s + 128;               // [128]
    {
        int half = warp & 1;
        int r0 = wm + g, r1 = r0 + 8;
        float s0 = 0.f, q0 = 0.f, s1 = 0.f, q1 = 0.f;
        #pragma unroll
        for (int fn = 0; fn < 8; fn++) {
            float v0 = acc_o[fn][0], v1 = acc_o[fn][1];
            float v2 = acc_o[fn][2], v3 = acc_o[fn][3];
            s0 += v0 + v1;  q0 += v0*v0 + v1*v1;
            s1 += v2 + v3;  q1 += v2*v2 + v3*v3;
        }
        #pragma unroll
        for (int off = 1; off <= 2; off <<= 1) {
            s0 += __shfl_xor_sync(0xffffffffu, s0, off);
            q0 += __shfl_xor_sync(0xffffffffu, q0, off);
            s1 += __shfl_xor_sync(0xffffffffu, s1, off);
            q1 += __shfl_xor_sync(0xffffffffu, q1, off);
        }
        if (t == 0) {
            red_s[half*64 + r0] = s0;  red_q[half*64 + r0] = q0;
            red_s[half*64 + r1] = s1;  red_q[half*64 + r1] = q1;
        }
        __syncthreads();
        float S0 = red_s[r0] + red_s[64 + r0];
        float Q0 = red_q[r0] + red_q[64 + r0];
        float S1 = red_s[r1] + red_s[64 + r1];
        float Q1 = red_q[r1] + red_q[64 + r1];
        float mu0 = S0 * (1.f/128.f), mu1 = S1 * (1.f/128.f);
        float inv0 = rsqrtf(Q0 * (1.f/128.f) - mu0*mu0 + 1e-5f);
        float inv1 = rsqrtf(Q1 * (1.f/128.f) - mu1*mu1 + 1e-5f);
        size_t gbase0 = (size_t)(l0 + r0) * NCAT + 2*DKK + DVV + h * HDVV;
        size_t gbase1 = (size_t)(l0 + r1) * NCAT + 2*DKK + DVV + h * HDVV;
        size_t ybase0 = (size_t)(l0 + r0) * DVV + h * HDVV;
        size_t ybase1 = (size_t)(l0 + r1) * DVV + h * HDVV;
        #pragma unroll
        for (int fn = 0; fn < 8; fn++) {
            int c = wno + fn * 8 + 2 * t;
            float2 gt0 = *(const float2*)(g_qkvg + gbase0 + c);
            float2 gt1 = *(const float2*)(g_qkvg + gbase1 + c);
            float2 y0, y1;
            y0.x = tf32r(silu_f(gt0.x) * (acc_o[fn][0] - mu0) * inv0);
            y0.y = tf32r(silu_f(gt0.y) * (acc_o[fn][1] - mu0) * inv0);
            y1.x = tf32r(silu_f(gt1.x) * (acc_o[fn][2] - mu1) * inv1);
            y1.y = tf32r(silu_f(gt1.y) * (acc_o[fn][3] - mu1) * inv1);
            *(float2*)(g_y + ybase0 + c) = y0;
            *(float2*)(g_y + ybase1 + c) = y1;
        }
    }
}

// ---------------- launch ----------------------------------------------------
extern "C" void kernel_launch(void* const* d_in, const int* in_sizes, int n_in,
                              void* d_out, int out_size) {
    const float* x    = (const float*)d_in[0];
    const float* cw   = (const float*)d_in[1];
    const float* Wq   = (const float*)d_in[2];
    const float* Wk   = (const float*)d_in[3];
    const float* Wv   = (const float*)d_in[4];
    const float* Wg   = (const float*)d_in[5];
    const float* rw   = (const float*)d_in[6];
    const float* Wout = (const float*)d_in[7];
    float* out = (float*)d_out;

    float *p_xctf, *p_qkvg, *p_y;
    cudaGetSymbolAddress((void**)&p_xctf, g_xctf);
    cudaGetSymbolAddress((void**)&p_qkvg, g_qkvg);
    cudaGetSymbolAddress((void**)&p_y,    g_y);

    cudaFuncSetAttribute(attn_tc,
                         cudaFuncAttributeMaxDynamicSharedMemorySize, ATTN4_BYTES);
    cudaFuncSetAttribute(gemm_tc<true>,
                         cudaFuncAttributeMaxDynamicSharedMemorySize, SMEM_GEMM3);
    cudaFuncSetAttribute(gemm_tc<false>,
                         cudaFuncAttributeMaxDynamicSharedMemorySize, SMEM_GEMM3);

    conv_silu_kernel<<<(LL*DD)/256, 256>>>(x, cw);
    w2_kernel<<<DD/8, 256>>>(Wv, rw);

    // fused QKVG projection (silu on q columns), segmented B, B cvt in-loop
    gemm_tc<true><<<dim3(NCAT/128, LL/128), 256, SMEM_GEMM3>>>(
        p_xctf, Wq, Wk, Wv, Wg, p_qkvg, NCAT, DD, DKK);
    rlog_kernel<<<LL/8, 256>>>();

    rope_split_kernel<<<(LL*HH*32)/256, 256>>>();
    vsplit_t_kernel<<<dim3(LL/64, HDVV/32, HH), 256>>>();
    router_kernel<<<HH, 256>>>();

    attn_tc<<<dim3(LL/64, HH), 256, ATTN4_BYTES>>>();

    gemm_tc<false><<<dim3(DD/128, LL/128), 256, SMEM_GEMM3>>>(
        p_y, Wout, Wout, Wout, Wout, out, DD, DVV, 0);
}

// round 13
// speedup vs baseline: 5.0203x; 1.1922x over previous
#include <cuda_runtime.h>
#include <cuda_bf16.h>
#include <math.h>

#define LL   2048
#define DD   2048
#define HH   16
#define DKK  1024
#define DVV  2048
#define HDKK 64
#define HDVV 128
#define NCAT 6144              // q(1024) | k(1024) | v(2048) | g(2048)

// ---------------- scratch (device globals; no allocation allowed) ----------
__device__ float g_xc  [LL*DD];      // conv+silu output (fp32 exact, for router)
__device__ float g_xctf[LL*DD];      // conv+silu output, tf32-rounded (GEMM A)
__device__ float g_qkvg[LL*NCAT];    // fused projection output
__device__ float g_w2  [DD*32];      // Wv @ router_w  (fp32 exact)
__device__ float g_rlog[LL*32];      // router logits  (fp32 exact)
__device__ __nv_bfloat16 g_qh[LL*DKK];   // roped q hi, [h][l][64]
__device__ __nv_bfloat16 g_ql[LL*DKK];   // roped q lo
__device__ __nv_bfloat16 g_kh[LL*DKK];   // roped k hi
__device__ __nv_bfloat16 g_kl[LL*DKK];   // roped k lo
__device__ __nv_bfloat16 g_vth[HH*HDVV*LL]; // v hi, TRANSPOSED [h][c][l]
__device__ __nv_bfloat16 g_vtl[HH*HDVV*LL]; // v lo, transposed
__device__ float g_y   [LL*DVV];     // silu(g)*LN(o), tf32-rounded
__device__ float g_coef[HH*LL];      // score_max/count * HDK^-0.5
__device__ int   g_rsel[HH*LL];      // selected expert per (h,l)

__device__ __forceinline__ float silu_f(float z) { return z / (1.f + expf(-z)); }

__device__ __forceinline__ unsigned f2tf(float f) {
    unsigned r;
    asm("cvt.rna.tf32.f32 %0, %1;" : "=r"(r) : "f"(f));
    return r;
}
__device__ __forceinline__ float tf32r(float f) { return __uint_as_float(f2tf(f)); }

__device__ __forceinline__ unsigned f2bfu(float f) {
    return (unsigned)__bfloat16_as_ushort(__float2bfloat16_rn(f));
}
__device__ __forceinline__ float bfu2f(unsigned u) {
    return __bfloat162float(__ushort_as_bfloat16((unsigned short)u));
}
__device__ __forceinline__ void split_bf(float v, unsigned& hi, unsigned& lo) {
    hi = f2bfu(v);
    lo = f2bfu(v - bfu2f(hi));
}

__device__ __forceinline__ void mma8(float* c,
                                     unsigned a0, unsigned a1, unsigned a2, unsigned a3,
                                     unsigned b0, unsigned b1) {
    asm("mma.sync.aligned.m16n8k8.row.col.f32.tf32.tf32.f32 "
        "{%0,%1,%2,%3}, {%4,%5,%6,%7}, {%8,%9}, {%0,%1,%2,%3};"
        : "+f"(c[0]), "+f"(c[1]), "+f"(c[2]), "+f"(c[3])
        : "r"(a0), "r"(a1), "r"(a2), "r"(a3), "r"(b0), "r"(b1));
}

__device__ __forceinline__ void mma16(float* c,
                                      unsigned a0, unsigned a1, unsigned a2, unsigned a3,
                                      unsigned b0, unsigned b1) {
    asm("mma.sync.aligned.m16n8k16.row.col.f32.bf16.bf16.f32 "
        "{%0,%1,%2,%3}, {%4,%5,%6,%7}, {%8,%9}, {%0,%1,%2,%3};"
        : "+f"(c[0]), "+f"(c[1]), "+f"(c[2]), "+f"(c[3])
        : "r"(a0), "r"(a1), "r"(a2), "r"(a3), "r"(b0), "r"(b1));
}

__device__ __forceinline__ void cp16(float* smem_dst, const float* gsrc) {
    unsigned sa = (unsigned)__cvta_generic_to_shared(smem_dst);
    asm volatile("cp.async.cg.shared.global [%0], [%1], 16;\n"
                 :: "r"(sa), "l"(gsrc));
}
__device__ __forceinline__ void cp16b(unsigned* smem_dst, const __nv_bfloat16* gsrc) {
    unsigned sa = (unsigned)__cvta_generic_to_shared(smem_dst);
    asm volatile("cp.async.cg.shared.global [%0], [%1], 16;\n"
                 :: "r"(sa), "l"(gsrc));
}

// ---------------- stage 1: shifted conv + silu -----------------------------
__global__ void conv_silu_kernel(const float* __restrict__ x,
                                 const float* __restrict__ cw) {
    int idx = blockIdx.x * blockDim.x + threadIdx.x;  // over L*D
    if (idx >= LL*DD) return;
    int d = idx & (DD-1);
    int l = idx >> 11;
    float prev = (l == 0) ? 0.f : x[idx - DD];
    float z = prev * cw[2*d] + x[idx] * cw[2*d + 1];
    float v = silu_f(z);
    g_xc[idx]   = v;
    g_xctf[idx] = tf32r(v);
}

// ---------------- W2 = Wv @ router_w (fp32 exact, [2048][32]) --------------
__global__ void w2_kernel(const float* __restrict__ Wv,
                          const float* __restrict__ rw) {
    int tid = threadIdx.x;                 // 256 threads, 8 k-rows per block
    int k  = blockIdx.x * 8 + (tid >> 5);
    int t  = tid & 31;
    int h  = t >> 1, r = t & 1;
    const float* wrow = Wv + (size_t)k * DVV + h * HDVV;
    const float* rr   = rw + (h * HDVV) * 2 + r;
    float a0 = 0.f, a1 = 0.f, a2 = 0.f, a3 = 0.f;
    #pragma unroll 8
    for (int d = 0; d < HDVV; d += 4) {
        a0 += wrow[d]     * rr[2*d];
        a1 += wrow[d + 1] * rr[2*d + 2];
        a2 += wrow[d + 2] * rr[2*d + 4];
        a3 += wrow[d + 3] * rr[2*d + 6];
    }
    g_w2[k * 32 + t] = (a0 + a1) + (a2 + a3);
}

// ---------------- router logits = xc @ W2 (fp32 exact, [2048][32]) ---------
// 512 blocks x 256 threads; 4 l-rows per block, 64 threads (2 k-halves) per row.
__global__ void rlog_kernel() {
    int tid  = threadIdx.x;
    int lsub = tid >> 6;            // 0..3
    int u    = tid & 63;
    int hr   = u & 31;
    int kh   = u >> 5;              // k-half 0/1
    int l    = blockIdx.x * 4 + lsub;
    const float* xrow = g_xc + (size_t)l * DD + kh * 1024;
    const float* w2p  = g_w2 + (size_t)kh * 1024 * 32 + hr;
    float a0 = 0.f, a1 = 0.f, a2 = 0.f, a3 = 0.f;
    #pragma unroll 8
    for (int k = 0; k < 1024; k += 4) {
        a0 += xrow[k]     * w2p[(k    ) * 32];
        a1 += xrow[k + 1] * w2p[(k + 1) * 32];
        a2 += xrow[k + 2] * w2p[(k + 2) * 32];
        a3 += xrow[k + 3] * w2p[(k + 3) * 32];
    }
    __shared__ float part[256];
    part[tid] = (a0 + a1) + (a2 + a3);
    __syncthreads();
    if (kh == 0)
        g_rlog[l * 32 + hr] = part[tid] + part[tid + 32];
}

// ---------------- tensor-core GEMM (TF32, 3-stage cp.async) ----------------
// A pre-rounded tf32 in gmem. B raw fp32; fragments cvt'd in-loop.
// SEG: B segmented over {B0:q, B1:k, B2:v, B3:g} at 1024/2048/4096 col splits.
#define AP 36
#define BPAD 136
#define STGF (128*AP + 32*BPAD)       // floats per stage = 8960
#define SMEM_GEMM3 (3 * STGF * 4)     // 107520 bytes

template<bool SEG>
__global__ __launch_bounds__(256, 2) void gemm_tc(
        const float* __restrict__ A,
        const float* __restrict__ B0,
        const float* __restrict__ B1,
        const float* __restrict__ B2,
        const float* __restrict__ B3,
        float* __restrict__ C,
        int N, int K, int silu_ncols) {
    extern __shared__ float sm[];

    int tid = threadIdx.x, lane = tid & 31, warp = tid >> 5;
    int bm = blockIdx.y * 128, bn = blockIdx.x * 128;
    int wm = (warp >> 2) * 64, wn = (warp & 3) * 32;
    int g = lane >> 2, t = lane & 3;

    const float* Bseg; int ldb, bcol;
    if (SEG) {
        if (bn < 1024)      { Bseg = B0; ldb = 1024; bcol = bn; }
        else if (bn < 2048) { Bseg = B1; ldb = 1024; bcol = bn - 1024; }
        else if (bn < 4096) { Bseg = B2; ldb = 2048; bcol = bn - 2048; }
        else                { Bseg = B3; ldb = 2048; bcol = bn - 4096; }
    } else {
        Bseg = B0; ldb = N; bcol = bn;
    }

    float acc[4][4][4];
    #pragma unroll
    for (int i = 0; i < 4; i++)
        #pragma unroll
        for (int j = 0; j < 4; j++)
            #pragma unroll
            for (int r = 0; r < 4; r++) acc[i][j][r] = 0.f;

    const float* agp[4];
    const float* bgp[4];
    int asp[4], bsp[4];
    #pragma unroll
    for (int i = 0; i < 4; i++) {
        int idx = tid + i * 256;
        int ar = idx >> 3, ac = (idx & 7) * 4;
        int br = idx >> 5, bc = (idx & 31) * 4;
        agp[i] = A + (size_t)(bm + ar) * K + ac;
        bgp[i] = Bseg + (size_t)br * ldb + bcol + bc;
        asp[i] = ar * AP + ac;
        bsp[i] = 128 * AP + br * BPAD + bc;
    }

#define LOAD_STAGE(s, k0) do {                                          \
        float* base_ = sm + (s) * STGF;                                 \
        _Pragma("unroll")                                               \
        for (int i_ = 0; i_ < 4; i_++) {                                \
            cp16(base_ + asp[i_], agp[i_] + (k0));                      \
            cp16(base_ + bsp[i_], bgp[i_] + (size_t)(k0) * ldb);        \
        }                                                               \
        asm volatile("cp.async.commit_group;\n" ::);                    \
    } while (0)

    int nk = K >> 5;
    LOAD_STAGE(0, 0);
    LOAD_STAGE(1, 32);
    LOAD_STAGE(2, 64);

    int s = 0;
    for (int kt = 0; kt < nk; kt++) {
        asm volatile("cp.async.wait_group 2;\n" ::);
        __syncthreads();
        const float* Ah = sm + s * STGF;
        const float* Bh = Ah + 128 * AP;

        #pragma unroll
        for (int ko = 0; ko < 32; ko += 8) {
            unsigned af[4][4], bf[4][2];
            #pragma unroll
            for (int fm = 0; fm < 4; fm++) {
                int r0 = wm + fm * 16 + g;
                af[fm][0] = __float_as_uint(Ah[ r0      * AP + ko + t]);
                af[fm][1] = __float_as_uint(Ah[(r0 + 8) * AP + ko + t]);
                af[fm][2] = __float_as_uint(Ah[ r0      * AP + ko + t + 4]);
                af[fm][3] = __float_as_uint(Ah[(r0 + 8) * AP + ko + t + 4]);
            }
            #pragma unroll
            for (int fn = 0; fn < 4; fn++) {
                int c0 = wn + fn * 8 + g;
                bf[fn][0] = f2tf(Bh[(ko + t    ) * BPAD + c0]);
                bf[fn][1] = f2tf(Bh[(ko + t + 4) * BPAD + c0]);
            }
            #pragma unroll
            for (int fm = 0; fm < 4; fm++)
                #pragma unroll
                for (int fn = 0; fn < 4; fn++)
                    mma8(acc[fm][fn], af[fm][0], af[fm][1], af[fm][2], af[fm][3],
                         bf[fn][0], bf[fn][1]);
        }
        __syncthreads();
        if (kt + 3 < nk) LOAD_STAGE(s, (kt + 3) * 32);
        s = (s == 2) ? 0 : s + 1;
    }

    #pragma unroll
    for (int fm = 0; fm < 4; fm++) {
        int r0 = bm + wm + fm * 16 + g;
        #pragma unroll
        for (int fn = 0; fn < 4; fn++) {
            int c0 = bn + wn + fn * 8 + 2 * t;
            float v0 = acc[fm][fn][0], v1 = acc[fm][fn][1];
            float v2 = acc[fm][fn][2], v3 = acc[fm][fn][3];
            if (c0 < silu_ncols) {
                v0 = silu_f(v0); v1 = silu_f(v1);
                v2 = silu_f(v2); v3 = silu_f(v3);
            }
            *(float2*)(C + (size_t)r0 * N + c0)       = make_float2(v0, v1);
            *(float2*)(C + (size_t)(r0 + 8) * N + c0) = make_float2(v2, v3);
        }
    }
#undef LOAD_STAGE
}

// ---------------- stage 3: RoPE + bf16 hi/lo split, head-major -------------
__global__ void rope_split_kernel() {
    int idx = blockIdx.x * blockDim.x + threadIdx.x;   // L*H*32
    if (idx >= LL * HH * 32) return;
    int i  = idx & 31;
    int lh = idx >> 5;
    int h  = lh & (HH-1);
    int l  = lh >> 4;
    float invf = powf(10000.f, -(float)i / 32.f);
    float ang = (float)l * invf;
    float c = cosf(ang), s = sinf(ang);
    size_t qb = (size_t)l * NCAT + h * HDKK;
    size_t kb = qb + DKK;
    size_t ob = ((size_t)h * LL + l) * HDKK;
    float q1 = g_qkvg[qb + i], q2 = g_qkvg[qb + 32 + i];
    float k1 = g_qkvg[kb + i], k2 = g_qkvg[kb + 32 + i];
    float qa = q1 * c - q2 * s, qbv = q2 * c + q1 * s;
    float ka = k1 * c - k2 * s, kbv = k2 * c + k1 * s;
    __nv_bfloat16 hb;
    hb = __float2bfloat16_rn(qa);
    g_qh[ob + i] = hb;  g_ql[ob + i] = __float2bfloat16_rn(qa - __bfloat162float(hb));
    hb = __float2bfloat16_rn(qbv);
    g_qh[ob + 32 + i] = hb;  g_ql[ob + 32 + i] = __float2bfloat16_rn(qbv - __bfloat162float(hb));
    hb = __float2bfloat16_rn(ka);
    g_kh[ob + i] = hb;  g_kl[ob + i] = __float2bfloat16_rn(ka - __bfloat162float(hb));
    hb = __float2bfloat16_rn(kbv);
    g_kh[ob + 32 + i] = hb;  g_kl[ob + 32 + i] = __float2bfloat16_rn(kbv - __bfloat162float(hb));
}

// ---------------- v transpose + bf16 split: [h][c][l] ----------------------
__global__ void vsplit_t_kernel() {
    __shared__ float tile[64][33];
    int l0 = blockIdx.x * 64, c0 = blockIdx.y * 32, h = blockIdx.z;
    int tid = threadIdx.x;
    for (int i = tid; i < 64 * 32; i += 256) {
        int li = i >> 5, ci = i & 31;
        tile[li][ci] = g_qkvg[(size_t)(l0 + li) * NCAT + 2*DKK + h * HDVV + c0 + ci];
    }
    __syncthreads();
    for (int i = tid; i < 32 * 64; i += 256) {
        int ci = i >> 6, li = i & 63;
        float v = tile[li][ci];
        __nv_bfloat16 hb = __float2bfloat16_rn(v);
        size_t ob = ((size_t)h * HDVV + c0 + ci) * LL + l0 + li;
        g_vth[ob] = hb;
        g_vtl[ob] = __float2bfloat16_rn(v - __bfloat162float(hb));
    }
}

// ---------------- stage 4: router decision + parallel count scan -----------
__global__ void router_kernel() {
    int h = blockIdx.x;                    // 16 blocks, 256 threads
    int tid = threadIdx.x;
    __shared__ float s_score[LL];
    __shared__ unsigned char s_sel[LL];
    __shared__ int ps0[256], ps1[256];
    for (int l = tid; l < LL; l += 256) {
        float z0 = g_rlog[l * 32 + h * 2 + 0];
        float z1 = g_rlog[l * 32 + h * 2 + 1];
        int sel = (z1 > z0) ? 1 : 0;
        float m = fmaxf(z0, z1);
        float e0 = expf(z0 - m), e1 = expf(z1 - m);
        s_sel[l]   = (unsigned char)sel;
        s_score[l] = ((sel == 0) ? e0 : e1) / (e0 + e1);
    }
    __syncthreads();
    int base = tid * 8;
    int c0 = 0, c1 = 0;
    #pragma unroll
    for (int i = 0; i < 8; i++) {
        if (s_sel[base + i]) c1++; else c0++;
    }
    ps0[tid] = c0; ps1[tid] = c1;
    __syncthreads();
    for (int off = 1; off < 256; off <<= 1) {
        int v0 = (tid >= off) ? ps0[tid - off] : 0;
        int v1 = (tid >= off) ? ps1[tid - off] : 0;
        __syncthreads();
        ps0[tid] += v0; ps1[tid] += v1;
        __syncthreads();
    }
    int b0 = ps0[tid] - c0, b1 = ps1[tid] - c1;   // exclusive prefix
    const float scale = 0.125f;                   // HDK^{-1/2}
    #pragma unroll
    for (int i = 0; i < 8; i++) {
        int l = base + i;
        int sel = s_sel[l];
        int cnt;
        if (sel) { b1++; cnt = b1; } else { b0++; cnt = b0; }
        g_rsel[h * LL + l] = sel;
        g_coef[h * LL + l] = s_score[l] / (float)cnt * scale;
    }
}

// ---------------- stage 5: bf16 attention + fused LN/gate epilogue ---------
#define SU 36
#define AQH 0
#define AQL (AQH + 64*SU)
#define AKB (AQL + 64*SU)            // K: 2 stages x (hi, lo)
#define AKSTG (2*64*SU)
#define ASH (AKB + 2*AKSTG)
#define ASL (ASH + 64*SU)
#define AVH (ASL + 64*SU)            // V^T: 128 rows
#define AVL (AVH + 128*SU)
#define ACF (AVL + 128*SU)
#define ARR (ACF + 64)
#define ARC (ARR + 64)
#define ATTN4_WORDS (ARC + 64)
#define ATTN4_BYTES (ATTN4_WORDS * 4)   // ~108.8 KB -> 2 CTAs/SM

__global__ __launch_bounds__(256, 2) void attn_tc() {
    extern __shared__ unsigned smu[];
    unsigned* Qh = smu + AQH;  unsigned* Ql = smu + AQL;
    unsigned* Sh = smu + ASH;  unsigned* Sl = smu + ASL;
    unsigned* Vh = smu + AVH;  unsigned* Vl = smu + AVL;
    float* coef_r = (float*)(smu + ACF);
    int*   rsel_r = (int*)(smu + ARR);
    int*   rsel_c = (int*)(smu + ARC);

    int h   = blockIdx.y;
    int l0  = (gridDim.x - 1 - blockIdx.x) * 64;   // heavy tiles first
    int tid = threadIdx.x, lane = tid & 31, warp = tid >> 5;
    int g = lane >> 2, t = lane & 3;
    int wm  = (warp >> 1) * 16;
    int wns = (warp & 1) * 32;
    int wno = (warp & 1) * 64;

    const __nv_bfloat16* Kh_g  = g_kh  + (size_t)h * LL * HDKK;
    const __nv_bfloat16* Kl_g  = g_kl  + (size_t)h * LL * HDKK;
    const __nv_bfloat16* Vth_g = g_vth + (size_t)h * HDVV * LL;
    const __nv_bfloat16* Vtl_g = g_vtl + (size_t)h * HDVV * LL;

#define LOAD_K(s, m0) do {                                                  \
        unsigned* kh_ = smu + AKB + (s) * AKSTG;                            \
        unsigned* kl_ = kh_ + 64*SU;                                        \
        _Pragma("unroll")                                                   \
        for (int i_ = 0; i_ < 2; i_++) {                                    \
            int idx_ = tid + i_ * 256, r_ = idx_ >> 3, j_ = idx_ & 7;       \
            cp16b(kh_ + r_*SU + j_*4, Kh_g + (size_t)((m0)+r_)*HDKK + j_*8);\
            cp16b(kl_ + r_*SU + j_*4, Kl_g + (size_t)((m0)+r_)*HDKK + j_*8);\
        }                                                                   \
        asm volatile("cp.async.commit_group;\n" ::);                        \
    } while (0)

#define LOAD_V(m0) do {                                                     \
        _Pragma("unroll")                                                   \
        for (int i_ = 0; i_ < 4; i_++) {                                    \
            int idx_ = tid + i_ * 256, r_ = idx_ >> 3, j_ = idx_ & 7;       \
            cp16b(Vh + r_*SU + j_*4, Vth_g + (size_t)r_*LL + (m0) + j_*8);  \
            cp16b(Vl + r_*SU + j_*4, Vtl_g + (size_t)r_*LL + (m0) + j_*8);  \
        }                                                                   \
        asm volatile("cp.async.commit_group;\n" ::);                        \
    } while (0)

    // prologue: K(0) in flight, load Q + metadata
    LOAD_K(0, 0);
    {
        const __nv_bfloat16* Qh_g = g_qh + (size_t)h * LL * HDKK;
        const __nv_bfloat16* Ql_g = g_ql + (size_t)h * LL * HDKK;
        for (int i = tid; i < 64 * 8; i += 256) {
            int r = i >> 3, j = i & 7;
            *(uint4*)(Qh + r*SU + j*4) = *(const uint4*)(Qh_g + (size_t)(l0 + r)*HDKK + j*8);
            *(uint4*)(Ql + r*SU + j*4) = *(const uint4*)(Ql_g + (size_t)(l0 + r)*HDKK + j*8);
        }
    }
    if (tid < 64) {
        rsel_r[tid] = g_rsel[h * LL + l0 + tid];
        coef_r[tid] = g_coef[h * LL + l0 + tid];
    }

    float acc_o[8][4];
    #pragma unroll
    for (int fn = 0; fn < 8; fn++)
        #pragma unroll
        for (int r = 0; r < 4; r++) acc_o[fn][r] = 0.f;

    int ntiles = (l0 >> 6) + 1;
    for (int mt = 0; mt < ntiles; mt++) {
        int m0 = mt * 64;
        int s  = mt & 1;
        __syncthreads();                    // prev V/S reads done
        LOAD_V(m0);
        if (tid < 64) rsel_c[tid] = g_rsel[h * LL + m0 + tid];
        asm volatile("cp.async.wait_group 1;\n" ::);   // K(mt) done
        __syncthreads();

        const unsigned* Kts = smu + AKB + s * AKSTG;
        const unsigned* Kls = Kts + 64*SU;

        // ---- QK^T (bf16 3-term): warp tile 16x32, 4 k16 steps ----
        float acc_s[4][4];
        #pragma unroll
        for (int fn = 0; fn < 4; fn++)
            #pragma unroll
            for (int r = 0; r < 4; r++) acc_s[fn][r] = 0.f;

        #pragma unroll
        for (int kk = 0; kk < 4; kk++) {
            int p0 = kk * 8;
            int r0 = wm + g;
            unsigned ah0 = Qh[ r0      * SU + p0 + t];
            unsigned ah1 = Qh[(r0 + 8) * SU + p0 + t];
            unsigned ah2 = Qh[ r0      * SU + p0 + t + 4];
            unsigned ah3 = Qh[(r0 + 8) * SU + p0 + t + 4];
            unsigned al0 = Ql[ r0      * SU + p0 + t];
            unsigned al1 = Ql[(r0 + 8) * SU + p0 + t];
            unsigned al2 = Ql[ r0      * SU + p0 + t + 4];
            unsigned al3 = Ql[(r0 + 8) * SU + p0 + t + 4];
            #pragma unroll
            for (int fn = 0; fn < 4; fn++) {
                int c0 = wns + fn * 8 + g;
                unsigned bh0 = Kts[c0 * SU + p0 + t];
                unsigned bh1 = Kts[c0 * SU + p0 + t + 4];
                unsigned bl0 = Kls[c0 * SU + p0 + t];
                unsigned bl1 = Kls[c0 * SU + p0 + t + 4];
                mma16(acc_s[fn], ah0, ah1, ah2, ah3, bh0, bh1);
                mma16(acc_s[fn], ah0, ah1, ah2, ah3, bl0, bl1);
                mma16(acc_s[fn], al0, al1, al2, al3, bh0, bh1);
            }
        }

        // prefetch K(mt+1) — K(mt) reads are done
        if (mt + 1 < ntiles) LOAD_K(s ^ 1, m0 + 64);

        // ---- mask + coef, pack bf16 hi/lo pairs into S ----
        {
            int r0 = wm + g, r1 = r0 + 8;
            int gl0 = l0 + r0, gl1 = l0 + r1;
            int e0 = rsel_r[r0], e1 = rsel_r[r1];
            float cf0 = coef_r[r0], cf1 = coef_r[r1];
            #pragma unroll
            for (int fn = 0; fn < 4; fn++) {
                int c = wns + fn * 8 + 2 * t;
                int gm0 = m0 + c, gm1 = gm0 + 1;
                int ec0 = rsel_c[c], ec1 = rsel_c[c + 1];
                float s00 = (gm0 <= gl0 && ec0 == e0) ? acc_s[fn][0] * cf0 : 0.f;
                float s01 = (gm1 <= gl0 && ec1 == e0) ? acc_s[fn][1] * cf0 : 0.f;
                float s10 = (gm0 <= gl1 && ec0 == e1) ? acc_s[fn][2] * cf1 : 0.f;
                float s11 = (gm1 <= gl1 && ec1 == e1) ? acc_s[fn][3] * cf1 : 0.f;
                unsigned h00, l00, h01, l01, h10, l10, h11, l11;
                split_bf(s00, h00, l00); split_bf(s01, h01, l01);
                split_bf(s10, h10, l10); split_bf(s11, h11, l11);
                int pi = (wns >> 1) + fn * 4 + t;
                Sh[r0 * SU + pi] = h00 | (h01 << 16);
                Sl[r0 * SU + pi] = l00 | (l01 << 16);
                Sh[r1 * SU + pi] = h10 | (h11 << 16);
                Sl[r1 * SU + pi] = l10 | (l11 << 16);
            }
        }
        if (mt + 1 < ntiles)
            asm volatile("cp.async.wait_group 1;\n" ::);  // V(mt) done, K(mt+1) pending
        else
            asm volatile("cp.async.wait_group 0;\n" ::);  // last tile: V must be done
        __syncthreads();                                   // S + V visible

        // ---- O += S @ V (bf16 3-term): warp tile 16x64, 4 k16 steps ----
        #pragma unroll
        for (int kk = 0; kk < 4; kk++) {
            int p0 = kk * 8;
            int r0 = wm + g;
            unsigned ah0 = Sh[ r0      * SU + p0 + t];
            unsigned ah1 = Sh[(r0 + 8) * SU + p0 + t];
            unsigned ah2 = Sh[ r0      * SU + p0 + t + 4];
            unsigned ah3 = Sh[(r0 + 8) * SU + p0 + t + 4];
            unsigned al0 = Sl[ r0      * SU + p0 + t];
            unsigned al1 = Sl[(r0 + 8) * SU + p0 + t];
            unsigned al2 = Sl[ r0      * SU + p0 + t + 4];
            unsigned al3 = Sl[(r0 + 8) * SU + p0 + t + 4];
            #pragma unroll
            for (int fn = 0; fn < 8; fn++) {
                int c0 = wno + fn * 8 + g;
                unsigned bh0 = Vh[c0 * SU + p0 + t];
                unsigned bh1 = Vh[c0 * SU + p0 + t + 4];
                unsigned bl0 = Vl[c0 * SU + p0 + t];
                unsigned bl1 = Vl[c0 * SU + p0 + t + 4];
                mma16(acc_o[fn], ah0, ah1, ah2, ah3, bh0, bh1);
                mma16(acc_o[fn], ah0, ah1, ah2, ah3, bl0, bl1);
                mma16(acc_o[fn], al0, al1, al2, al3, bh0, bh1);
            }
        }
    }

    // ---- fused LayerNorm(128) * silu(gate) epilogue ----
    __syncthreads();                          // all smem reads done; reuse Sh region
    float* red_s = (float*)(smu + ASH);       // [128]: half*64 + row
    float* red_q = red_s + 128;               // [128]
    {
        int half = warp & 1;
        int r0 = wm + g, r1 = r0 + 8;
        float s0 = 0.f, q0 = 0.f, s1 = 0.f, q1 = 0.f;
        #pragma unroll
        for (int fn = 0; fn < 8; fn++) {
            float v0 = acc_o[fn][0], v1 = acc_o[fn][1];
            float v2 = acc_o[fn][2], v3 = acc_o[fn][3];
            s0 += v0 + v1;  q0 += v0*v0 + v1*v1;
            s1 += v2 + v3;  q1 += v2*v2 + v3*v3;
        }
        #pragma unroll
        for (int off = 1; off <= 2; off <<= 1) {
            s0 += __shfl_xor_sync(0xffffffffu, s0, off);
            q0 += __shfl_xor_sync(0xffffffffu, q0, off);
            s1 += __shfl_xor_sync(0xffffffffu, s1, off);
            q1 += __shfl_xor_sync(0xffffffffu, q1, off);
        }
        if (t == 0) {
            red_s[half*64 + r0] = s0;  red_q[half*64 + r0] = q0;
            red_s[half*64 + r1] = s1;  red_q[half*64 + r1] = q1;
        }
        __syncthreads();
        float S0 = red_s[r0] + red_s[64 + r0];
        float Q0 = red_q[r0] + red_q[64 + r0];
        float S1 = red_s[r1] + red_s[64 + r1];
        float Q1 = red_q[r1] + red_q[64 + r1];
        float mu0 = S0 * (1.f/128.f), mu1 = S1 * (1.f/128.f);
        float inv0 = rsqrtf(Q0 * (1.f/128.f) - mu0*mu0 + 1e-5f);
        float inv1 = rsqrtf(Q1 * (1.f/128.f) - mu1*mu1 + 1e-5f);
        size_t gbase0 = (size_t)(l0 + r0) * NCAT + 2*DKK + DVV + h * HDVV;
        size_t gbase1 = (size_t)(l0 + r1) * NCAT + 2*DKK + DVV + h * HDVV;
        size_t ybase0 = (size_t)(l0 + r0) * DVV + h * HDVV;
        size_t ybase1 = (size_t)(l0 + r1) * DVV + h * HDVV;
        #pragma unroll
        for (int fn = 0; fn < 8; fn++) {
            int c = wno + fn * 8 + 2 * t;
            float2 gt0 = *(const float2*)(g_qkvg + gbase0 + c);
            float2 gt1 = *(const float2*)(g_qkvg + gbase1 + c);
            float2 y0, y1;
            y0.x = tf32r(silu_f(gt0.x) * (acc_o[fn][0] - mu0) * inv0);
            y0.y = tf32r(silu_f(gt0.y) * (acc_o[fn][1] - mu0) * inv0);
            y1.x = tf32r(silu_f(gt1.x) * (acc_o[fn][2] - mu1) * inv1);
            y1.y = tf32r(silu_f(gt1.y) * (acc_o[fn][3] - mu1) * inv1);
            *(float2*)(g_y + ybase0 + c) = y0;
            *(float2*)(g_y + ybase1 + c) = y1;
        }
    }
}

// ---------------- launch ----------------------------------------------------
extern "C" void kernel_launch(void* const* d_in, const int* in_sizes, int n_in,
                              void* d_out, int out_size) {
    const float* x    = (const float*)d_in[0];
    const float* cw   = (const float*)d_in[1];
    const float* Wq   = (const float*)d_in[2];
    const float* Wk   = (const float*)d_in[3];
    const float* Wv   = (const float*)d_in[4];
    const float* Wg   = (const float*)d_in[5];
    const float* rw   = (const float*)d_in[6];
    const float* Wout = (const float*)d_in[7];
    float* out = (float*)d_out;

    float *p_xctf, *p_qkvg, *p_y;
    cudaGetSymbolAddress((void**)&p_xctf, g_xctf);
    cudaGetSymbolAddress((void**)&p_qkvg, g_qkvg);
    cudaGetSymbolAddress((void**)&p_y,    g_y);

    cudaFuncSetAttribute(attn_tc,
                         cudaFuncAttributeMaxDynamicSharedMemorySize, ATTN4_BYTES);
    cudaFuncSetAttribute(gemm_tc<true>,
                         cudaFuncAttributeMaxDynamicSharedMemorySize, SMEM_GEMM3);
    cudaFuncSetAttribute(gemm_tc<false>,
                         cudaFuncAttributeMaxDynamicSharedMemorySize, SMEM_GEMM3);

    conv_silu_kernel<<<(LL*DD)/256, 256>>>(x, cw);
    w2_kernel<<<DD/8, 256>>>(Wv, rw);
    rlog_kernel<<<LL/4, 256>>>();

    // fused QKVG projection (silu on q columns), segmented B, B cvt in-loop
    gemm_tc<true><<<dim3(NCAT/128, LL/128), 256, SMEM_GEMM3>>>(
        p_xctf, Wq, Wk, Wv, Wg, p_qkvg, NCAT, DD, DKK);

    rope_split_kernel<<<(LL*HH*32)/256, 256>>>();
    vsplit_t_kernel<<<dim3(LL/64, HDVV/32, HH), 256>>>();
    router_kernel<<<HH, 256>>>();

    attn_tc<<<dim3(LL/64, HH), 256, ATTN4_BYTES>>>();

    gemm_tc<false><<<dim3(DD/128, LL/128), 256, SMEM_GEMM3>>>(
        p_y, Wout, Wout, Wout, Wout, out, DD, DVV, 0);
}

// round 14
// speedup vs baseline: 5.1319x; 1.0222x over previous
#include <cuda_runtime.h>
#include <cuda_bf16.h>
#include <math.h>

#define LL   2048
#define DD   2048
#define HH   16
#define DKK  1024
#define DVV  2048
#define HDKK 64
#define HDVV 128
#define NCAT 6144              // q(1024) | k(1024) | v(2048) | g(2048)

// ---------------- scratch (device globals; no allocation allowed) ----------
__device__ float g_xc  [LL*DD];      // conv+silu output (fp32 exact, for router)
__device__ float g_xctf[LL*DD];      // conv+silu output, tf32-rounded (GEMM A)
__device__ float g_qkvg[LL*NCAT];    // fused projection output
__device__ float g_w2  [DD*32];      // Wv @ router_w  (fp32 exact)
__device__ float g_rlog[LL*32];      // router logits  (fp32 exact)
__device__ __nv_bfloat16 g_qh[LL*DKK];   // roped q hi, [h][l][64]
__device__ __nv_bfloat16 g_ql[LL*DKK];   // roped q lo
__device__ __nv_bfloat16 g_kh[LL*DKK];   // roped k hi
__device__ __nv_bfloat16 g_kl[LL*DKK];   // roped k lo
__device__ __nv_bfloat16 g_vth[HH*HDVV*LL]; // v hi, TRANSPOSED [h][c][l]
__device__ __nv_bfloat16 g_vtl[HH*HDVV*LL]; // v lo, transposed
__device__ float g_y   [LL*DVV];     // silu(g)*LN(o), tf32-rounded
__device__ float g_coef[HH*LL];      // score_max/count * HDK^-0.5
__device__ int   g_rsel[HH*LL];      // selected expert per (h,l)

__device__ __forceinline__ float silu_f(float z) { return z / (1.f + expf(-z)); }

__device__ __forceinline__ unsigned f2tf(float f) {
    unsigned r;
    asm("cvt.rna.tf32.f32 %0, %1;" : "=r"(r) : "f"(f));
    return r;
}
__device__ __forceinline__ float tf32r(float f) { return __uint_as_float(f2tf(f)); }

__device__ __forceinline__ unsigned f2bfu(float f) {
    return (unsigned)__bfloat16_as_ushort(__float2bfloat16_rn(f));
}
__device__ __forceinline__ float bfu2f(unsigned u) {
    return __bfloat162float(__ushort_as_bfloat16((unsigned short)u));
}
__device__ __forceinline__ void split_bf(float v, unsigned& hi, unsigned& lo) {
    hi = f2bfu(v);
    lo = f2bfu(v - bfu2f(hi));
}

__device__ __forceinline__ void mma8(float* c,
                                     unsigned a0, unsigned a1, unsigned a2, unsigned a3,
                                     unsigned b0, unsigned b1) {
    asm("mma.sync.aligned.m16n8k8.row.col.f32.tf32.tf32.f32 "
        "{%0,%1,%2,%3}, {%4,%5,%6,%7}, {%8,%9}, {%0,%1,%2,%3};"
        : "+f"(c[0]), "+f"(c[1]), "+f"(c[2]), "+f"(c[3])
        : "r"(a0), "r"(a1), "r"(a2), "r"(a3), "r"(b0), "r"(b1));
}

__device__ __forceinline__ void mma16(float* c,
                                      unsigned a0, unsigned a1, unsigned a2, unsigned a3,
                                      unsigned b0, unsigned b1) {
    asm("mma.sync.aligned.m16n8k16.row.col.f32.bf16.bf16.f32 "
        "{%0,%1,%2,%3}, {%4,%5,%6,%7}, {%8,%9}, {%0,%1,%2,%3};"
        : "+f"(c[0]), "+f"(c[1]), "+f"(c[2]), "+f"(c[3])
        : "r"(a0), "r"(a1), "r"(a2), "r"(a3), "r"(b0), "r"(b1));
}

__device__ __forceinline__ void cp16(float* smem_dst, const float* gsrc) {
    unsigned sa = (unsigned)__cvta_generic_to_shared(smem_dst);
    asm volatile("cp.async.cg.shared.global [%0], [%1], 16;\n"
                 :: "r"(sa), "l"(gsrc));
}
__device__ __forceinline__ void cp16b(unsigned* smem_dst, const __nv_bfloat16* gsrc) {
    unsigned sa = (unsigned)__cvta_generic_to_shared(smem_dst);
    asm volatile("cp.async.cg.shared.global [%0], [%1], 16;\n"
                 :: "r"(sa), "l"(gsrc));
}

// ---------------- stage 1: shifted conv + silu -----------------------------
__global__ void conv_silu_kernel(const float* __restrict__ x,
                                 const float* __restrict__ cw) {
    int idx = blockIdx.x * blockDim.x + threadIdx.x;  // over L*D
    if (idx >= LL*DD) return;
    int d = idx & (DD-1);
    int l = idx >> 11;
    float prev = (l == 0) ? 0.f : x[idx - DD];
    float z = prev * cw[2*d] + x[idx] * cw[2*d + 1];
    float v = silu_f(z);
    g_xc[idx]   = v;
    g_xctf[idx] = tf32r(v);
}

// ---------------- W2 = Wv @ router_w (fp32 exact, [2048][32]) --------------
__global__ void w2_kernel(const float* __restrict__ Wv,
                          const float* __restrict__ rw) {
    int tid = threadIdx.x;                 // 256 threads, 8 k-rows per block
    int k  = blockIdx.x * 8 + (tid >> 5);
    int t  = tid & 31;
    int h  = t >> 1, r = t & 1;
    const float* wrow = Wv + (size_t)k * DVV + h * HDVV;
    const float* rr   = rw + (h * HDVV) * 2 + r;
    float a0 = 0.f, a1 = 0.f, a2 = 0.f, a3 = 0.f;
    #pragma unroll 8
    for (int d = 0; d < HDVV; d += 4) {
        a0 += wrow[d]     * rr[2*d];
        a1 += wrow[d + 1] * rr[2*d + 2];
        a2 += wrow[d + 2] * rr[2*d + 4];
        a3 += wrow[d + 3] * rr[2*d + 6];
    }
    g_w2[k * 32 + t] = (a0 + a1) + (a2 + a3);
}

// ---------------- router logits = xc @ W2 (fp32 exact, [2048][32]) ---------
__global__ void rlog_kernel() {
    int tid  = threadIdx.x;
    int lsub = tid >> 6;            // 0..3
    int u    = tid & 63;
    int hr   = u & 31;
    int kh   = u >> 5;              // k-half 0/1
    int l    = blockIdx.x * 4 + lsub;
    const float* xrow = g_xc + (size_t)l * DD + kh * 1024;
    const float* w2p  = g_w2 + (size_t)kh * 1024 * 32 + hr;
    float a0 = 0.f, a1 = 0.f, a2 = 0.f, a3 = 0.f;
    #pragma unroll 8
    for (int k = 0; k < 1024; k += 4) {
        a0 += xrow[k]     * w2p[(k    ) * 32];
        a1 += xrow[k + 1] * w2p[(k + 1) * 32];
        a2 += xrow[k + 2] * w2p[(k + 2) * 32];
        a3 += xrow[k + 3] * w2p[(k + 3) * 32];
    }
    __shared__ float part[256];
    part[tid] = (a0 + a1) + (a2 + a3);
    __syncthreads();
    if (kh == 0)
        g_rlog[l * 32 + hr] = part[tid] + part[tid + 32];
}

// ---------------- tensor-core GEMM (TF32, 4-stage, 1 barrier/iter) ---------
// A pre-rounded tf32 in gmem. B raw fp32; fragments cvt'd in-loop.
// K-tile 16. SEG: B segmented over {q,k,v,g} at 1024/2048/4096 col splits.
#define AP4 20
#define BPAD 136
#define STGF4 (128*AP4 + 16*BPAD)     // floats per stage = 4736
#define SMEM_GEMM4 (4 * STGF4 * 4)    // 75776 bytes

template<bool SEG>
__global__ __launch_bounds__(256, 2) void gemm_tc(
        const float* __restrict__ A,
        const float* __restrict__ B0,
        const float* __restrict__ B1,
        const float* __restrict__ B2,
        const float* __restrict__ B3,
        float* __restrict__ C,
        int N, int K, int silu_ncols) {
    extern __shared__ float sm[];

    int tid = threadIdx.x, lane = tid & 31, warp = tid >> 5;
    int bm = blockIdx.y * 128, bn = blockIdx.x * 128;
    int wm = (warp >> 2) * 64, wn = (warp & 3) * 32;
    int g = lane >> 2, t = lane & 3;

    const float* Bseg; int ldb, bcol;
    if (SEG) {
        if (bn < 1024)      { Bseg = B0; ldb = 1024; bcol = bn; }
        else if (bn < 2048) { Bseg = B1; ldb = 1024; bcol = bn - 1024; }
        else if (bn < 4096) { Bseg = B2; ldb = 2048; bcol = bn - 2048; }
        else                { Bseg = B3; ldb = 2048; bcol = bn - 4096; }
    } else {
        Bseg = B0; ldb = N; bcol = bn;
    }

    float acc[4][4][4];
    #pragma unroll
    for (int i = 0; i < 4; i++)
        #pragma unroll
        for (int j = 0; j < 4; j++)
            #pragma unroll
            for (int r = 0; r < 4; r++) acc[i][j][r] = 0.f;

    // per-thread cp.async slots: A 2 chunks (128x16), B 2 chunks (16x128)
    const float* agp[2];
    const float* bgp[2];
    int asp[2], bsp[2];
    #pragma unroll
    for (int i = 0; i < 2; i++) {
        int idx = tid + i * 256;
        int ar = idx >> 2, ac = (idx & 3) * 4;    // A: 128 rows x 16 k
        int br = idx >> 5, bc = (idx & 31) * 4;   // B: 16 k x 128 cols
        agp[i] = A + (size_t)(bm + ar) * K + ac;
        bgp[i] = Bseg + (size_t)br * ldb + bcol + bc;
        asp[i] = ar * AP4 + ac;
        bsp[i] = 128 * AP4 + br * BPAD + bc;
    }

#define LOAD_STAGE(s, k0) do {                                          \
        float* base_ = sm + (s) * STGF4;                                \
        _Pragma("unroll")                                               \
        for (int i_ = 0; i_ < 2; i_++) {                                \
            cp16(base_ + asp[i_], agp[i_] + (k0));                      \
            cp16(base_ + bsp[i_], bgp[i_] + (size_t)(k0) * ldb);        \
        }                                                               \
        asm volatile("cp.async.commit_group;\n" ::);                    \
    } while (0)

    int nk = K >> 4;                  // K-tile 16
    LOAD_STAGE(0, 0);
    LOAD_STAGE(1, 16);
    LOAD_STAGE(2, 32);

    for (int kt = 0; kt < nk; kt++) {
        int s = kt & 3;
        asm volatile("cp.async.wait_group 2;\n" ::);
        __syncthreads();              // also guarantees kt-1 readers done
        const float* Ah = sm + s * STGF4;
        const float* Bh = Ah + 128 * AP4;

        #pragma unroll
        for (int ko = 0; ko < 16; ko += 8) {
            unsigned af[4][4], bf[4][2];
            #pragma unroll
            for (int fm = 0; fm < 4; fm++) {
                int r0 = wm + fm * 16 + g;
                af[fm][0] = __float_as_uint(Ah[ r0      * AP4 + ko + t]);
                af[fm][1] = __float_as_uint(Ah[(r0 + 8) * AP4 + ko + t]);
                af[fm][2] = __float_as_uint(Ah[ r0      * AP4 + ko + t + 4]);
                af[fm][3] = __float_as_uint(Ah[(r0 + 8) * AP4 + ko + t + 4]);
            }
            #pragma unroll
            for (int fn = 0; fn < 4; fn++) {
                int c0 = wn + fn * 8 + g;
                bf[fn][0] = f2tf(Bh[(ko + t    ) * BPAD + c0]);
                bf[fn][1] = f2tf(Bh[(ko + t + 4) * BPAD + c0]);
            }
            #pragma unroll
            for (int fm = 0; fm < 4; fm++)
                #pragma unroll
                for (int fn = 0; fn < 4; fn++)
                    mma8(acc[fm][fn], af[fm][0], af[fm][1], af[fm][2], af[fm][3],
                         bf[fn][0], bf[fn][1]);
        }
        // load stage (kt+3)%4 == (kt-1)%4: its readers finished before the
        // top-of-iteration barrier, so no second barrier is needed.
        if (kt + 3 < nk) LOAD_STAGE((kt + 3) & 3, (kt + 3) * 16);
    }

    #pragma unroll
    for (int fm = 0; fm < 4; fm++) {
        int r0 = bm + wm + fm * 16 + g;
        #pragma unroll
        for (int fn = 0; fn < 4; fn++) {
            int c0 = bn + wn + fn * 8 + 2 * t;
            float v0 = acc[fm][fn][0], v1 = acc[fm][fn][1];
            float v2 = acc[fm][fn][2], v3 = acc[fm][fn][3];
            if (c0 < silu_ncols) {
                v0 = silu_f(v0); v1 = silu_f(v1);
                v2 = silu_f(v2); v3 = silu_f(v3);
            }
            *(float2*)(C + (size_t)r0 * N + c0)       = make_float2(v0, v1);
            *(float2*)(C + (size_t)(r0 + 8) * N + c0) = make_float2(v2, v3);
        }
    }
#undef LOAD_STAGE
}

// ---------------- stage 3: RoPE + bf16 hi/lo split, head-major -------------
__global__ void rope_split_kernel() {
    int idx = blockIdx.x * blockDim.x + threadIdx.x;   // L*H*32
    if (idx >= LL * HH * 32) return;
    int i  = idx & 31;
    int lh = idx >> 5;
    int h  = lh & (HH-1);
    int l  = lh >> 4;
    float invf = powf(10000.f, -(float)i / 32.f);
    float ang = (float)l * invf;
    float c = cosf(ang), s = sinf(ang);
    size_t qb = (size_t)l * NCAT + h * HDKK;
    size_t kb = qb + DKK;
    size_t ob = ((size_t)h * LL + l) * HDKK;
    float q1 = g_qkvg[qb + i], q2 = g_qkvg[qb + 32 + i];
    float k1 = g_qkvg[kb + i], k2 = g_qkvg[kb + 32 + i];
    float qa = q1 * c - q2 * s, qbv = q2 * c + q1 * s;
    float ka = k1 * c - k2 * s, kbv = k2 * c + k1 * s;
    __nv_bfloat16 hb;
    hb = __float2bfloat16_rn(qa);
    g_qh[ob + i] = hb;  g_ql[ob + i] = __float2bfloat16_rn(qa - __bfloat162float(hb));
    hb = __float2bfloat16_rn(qbv);
    g_qh[ob + 32 + i] = hb;  g_ql[ob + 32 + i] = __float2bfloat16_rn(qbv - __bfloat162float(hb));
    hb = __float2bfloat16_rn(ka);
    g_kh[ob + i] = hb;  g_kl[ob + i] = __float2bfloat16_rn(ka - __bfloat162float(hb));
    hb = __float2bfloat16_rn(kbv);
    g_kh[ob + 32 + i] = hb;  g_kl[ob + 32 + i] = __float2bfloat16_rn(kbv - __bfloat162float(hb));
}

// ---------------- v transpose + bf16 split: [h][c][l] ----------------------
__global__ void vsplit_t_kernel() {
    __shared__ float tile[64][33];
    int l0 = blockIdx.x * 64, c0 = blockIdx.y * 32, h = blockIdx.z;
    int tid = threadIdx.x;
    for (int i = tid; i < 64 * 32; i += 256) {
        int li = i >> 5, ci = i & 31;
        tile[li][ci] = g_qkvg[(size_t)(l0 + li) * NCAT + 2*DKK + h * HDVV + c0 + ci];
    }
    __syncthreads();
    for (int i = tid; i < 32 * 64; i += 256) {
        int ci = i >> 6, li = i & 63;
        float v = tile[li][ci];
        __nv_bfloat16 hb = __float2bfloat16_rn(v);
        size_t ob = ((size_t)h * HDVV + c0 + ci) * LL + l0 + li;
        g_vth[ob] = hb;
        g_vtl[ob] = __float2bfloat16_rn(v - __bfloat162float(hb));
    }
}

// ---------------- stage 4: router decision + parallel count scan -----------
__global__ void router_kernel() {
    int h = blockIdx.x;                    // 16 blocks, 256 threads
    int tid = threadIdx.x;
    __shared__ float s_score[LL];
    __shared__ unsigned char s_sel[LL];
    __shared__ int ps0[256], ps1[256];
    for (int l = tid; l < LL; l += 256) {
        float z0 = g_rlog[l * 32 + h * 2 + 0];
        float z1 = g_rlog[l * 32 + h * 2 + 1];
        int sel = (z1 > z0) ? 1 : 0;
        float m = fmaxf(z0, z1);
        float e0 = expf(z0 - m), e1 = expf(z1 - m);
        s_sel[l]   = (unsigned char)sel;
        s_score[l] = ((sel == 0) ? e0 : e1) / (e0 + e1);
    }
    __syncthreads();
    int base = tid * 8;
    int c0 = 0, c1 = 0;
    #pragma unroll
    for (int i = 0; i < 8; i++) {
        if (s_sel[base + i]) c1++; else c0++;
    }
    ps0[tid] = c0; ps1[tid] = c1;
    __syncthreads();
    for (int off = 1; off < 256; off <<= 1) {
        int v0 = (tid >= off) ? ps0[tid - off] : 0;
        int v1 = (tid >= off) ? ps1[tid - off] : 0;
        __syncthreads();
        ps0[tid] += v0; ps1[tid] += v1;
        __syncthreads();
    }
    int b0 = ps0[tid] - c0, b1 = ps1[tid] - c1;   // exclusive prefix
    const float scale = 0.125f;                   // HDK^{-1/2}
    #pragma unroll
    for (int i = 0; i < 8; i++) {
        int l = base + i;
        int sel = s_sel[l];
        int cnt;
        if (sel) { b1++; cnt = b1; } else { b0++; cnt = b0; }
        g_rsel[h * LL + l] = sel;
        g_coef[h * LL + l] = s_score[l] / (float)cnt * scale;
    }
}

// ---------------- stage 5: bf16 attention + fused LN/gate epilogue ---------
#define SU 36
#define AQH 0
#define AQL (AQH + 64*SU)
#define AKB (AQL + 64*SU)            // K: 2 stages x (hi, lo)
#define AKSTG (2*64*SU)
#define ASH (AKB + 2*AKSTG)
#define ASL (ASH + 64*SU)
#define AVH (ASL + 64*SU)            // V^T: 128 rows
#define AVL (AVH + 128*SU)
#define ACF (AVL + 128*SU)
#define ARR (ACF + 64)
#define ARC (ARR + 64)
#define ATTN4_WORDS (ARC + 64)
#define ATTN4_BYTES (ATTN4_WORDS * 4)   // ~108.8 KB -> 2 CTAs/SM

__global__ __launch_bounds__(256, 2) void attn_tc() {
    extern __shared__ unsigned smu[];
    unsigned* Qh = smu + AQH;  unsigned* Ql = smu + AQL;
    unsigned* Sh = smu + ASH;  unsigned* Sl = smu + ASL;
    unsigned* Vh = smu + AVH;  unsigned* Vl = smu + AVL;
    float* coef_r = (float*)(smu + ACF);
    int*   rsel_r = (int*)(smu + ARR);
    int*   rsel_c = (int*)(smu + ARC);

    int h   = blockIdx.y;
    int l0  = (gridDim.x - 1 - blockIdx.x) * 64;   // heavy tiles first
    int tid = threadIdx.x, lane = tid & 31, warp = tid >> 5;
    int g = lane >> 2, t = lane & 3;
    int wm  = (warp >> 1) * 16;
    int wns = (warp & 1) * 32;
    int wno = (warp & 1) * 64;

    const __nv_bfloat16* Kh_g  = g_kh  + (size_t)h * LL * HDKK;
    const __nv_bfloat16* Kl_g  = g_kl  + (size_t)h * LL * HDKK;
    const __nv_bfloat16* Vth_g = g_vth + (size_t)h * HDVV * LL;
    const __nv_bfloat16* Vtl_g = g_vtl + (size_t)h * HDVV * LL;

#define LOAD_K(s, m0) do {                                                  \
        unsigned* kh_ = smu + AKB + (s) * AKSTG;                            \
        unsigned* kl_ = kh_ + 64*SU;                                        \
        _Pragma("unroll")                                                   \
        for (int i_ = 0; i_ < 2; i_++) {                                    \
            int idx_ = tid + i_ * 256, r_ = idx_ >> 3, j_ = idx_ & 7;       \
            cp16b(kh_ + r_*SU + j_*4, Kh_g + (size_t)((m0)+r_)*HDKK + j_*8);\
            cp16b(kl_ + r_*SU + j_*4, Kl_g + (size_t)((m0)+r_)*HDKK + j_*8);\
        }                                                                   \
        asm volatile("cp.async.commit_group;\n" ::);                        \
    } while (0)

#define LOAD_V(m0) do {                                                     \
        _Pragma("unroll")                                                   \
        for (int i_ = 0; i_ < 4; i_++) {                                    \
            int idx_ = tid + i_ * 256, r_ = idx_ >> 3, j_ = idx_ & 7;       \
            cp16b(Vh + r_*SU + j_*4, Vth_g + (size_t)r_*LL + (m0) + j_*8);  \
            cp16b(Vl + r_*SU + j_*4, Vtl_g + (size_t)r_*LL + (m0) + j_*8);  \
        }                                                                   \
        asm volatile("cp.async.commit_group;\n" ::);                        \
    } while (0)

    // prologue: K(0) in flight, load Q + metadata
    LOAD_K(0, 0);
    {
        const __nv_bfloat16* Qh_g = g_qh + (size_t)h * LL * HDKK;
        const __nv_bfloat16* Ql_g = g_ql + (size_t)h * LL * HDKK;
        for (int i = tid; i < 64 * 8; i += 256) {
            int r = i >> 3, j = i & 7;
            *(uint4*)(Qh + r*SU + j*4) = *(const uint4*)(Qh_g + (size_t)(l0 + r)*HDKK + j*8);
            *(uint4*)(Ql + r*SU + j*4) = *(const uint4*)(Ql_g + (size_t)(l0 + r)*HDKK + j*8);
        }
    }
    if (tid < 64) {
        rsel_r[tid] = g_rsel[h * LL + l0 + tid];
        coef_r[tid] = g_coef[h * LL + l0 + tid];
    }

    float acc_o[8][4];
    #pragma unroll
    for (int fn = 0; fn < 8; fn++)
        #pragma unroll
        for (int r = 0; r < 4; r++) acc_o[fn][r] = 0.f;

    int ntiles = (l0 >> 6) + 1;
    for (int mt = 0; mt < ntiles; mt++) {
        int m0 = mt * 64;
        int s  = mt & 1;
        __syncthreads();                    // prev V/S reads done
        LOAD_V(m0);
        if (tid < 64) rsel_c[tid] = g_rsel[h * LL + m0 + tid];
        asm volatile("cp.async.wait_group 1;\n" ::);   // K(mt) done
        __syncthreads();

        const unsigned* Kts = smu + AKB + s * AKSTG;
        const unsigned* Kls = Kts + 64*SU;

        // ---- QK^T (bf16 3-term): warp tile 16x32, 4 k16 steps ----
        float acc_s[4][4];
        #pragma unroll
        for (int fn = 0; fn < 4; fn++)
            #pragma unroll
            for (int r = 0; r < 4; r++) acc_s[fn][r] = 0.f;

        #pragma unroll
        for (int kk = 0; kk < 4; kk++) {
            int p0 = kk * 8;
            int r0 = wm + g;
            unsigned ah0 = Qh[ r0      * SU + p0 + t];
            unsigned ah1 = Qh[(r0 + 8) * SU + p0 + t];
            unsigned ah2 = Qh[ r0      * SU + p0 + t + 4];
            unsigned ah3 = Qh[(r0 + 8) * SU + p0 + t + 4];
            unsigned al0 = Ql[ r0      * SU + p0 + t];
            unsigned al1 = Ql[(r0 + 8) * SU + p0 + t];
            unsigned al2 = Ql[ r0      * SU + p0 + t + 4];
            unsigned al3 = Ql[(r0 + 8) * SU + p0 + t + 4];
            #pragma unroll
            for (int fn = 0; fn < 4; fn++) {
                int c0 = wns + fn * 8 + g;
                unsigned bh0 = Kts[c0 * SU + p0 + t];
                unsigned bh1 = Kts[c0 * SU + p0 + t + 4];
                unsigned bl0 = Kls[c0 * SU + p0 + t];
                unsigned bl1 = Kls[c0 * SU + p0 + t + 4];
                mma16(acc_s[fn], ah0, ah1, ah2, ah3, bh0, bh1);
                mma16(acc_s[fn], ah0, ah1, ah2, ah3, bl0, bl1);
                mma16(acc_s[fn], al0, al1, al2, al3, bh0, bh1);
            }
        }

        // prefetch K(mt+1) — K(mt) reads are done
        if (mt + 1 < ntiles) LOAD_K(s ^ 1, m0 + 64);

        // ---- mask + coef, pack bf16 hi/lo pairs into S ----
        {
            int r0 = wm + g, r1 = r0 + 8;
            int gl0 = l0 + r0, gl1 = l0 + r1;
            int e0 = rsel_r[r0], e1 = rsel_r[r1];
            float cf0 = coef_r[r0], cf1 = coef_r[r1];
            #pragma unroll
            for (int fn = 0; fn < 4; fn++) {
                int c = wns + fn * 8 + 2 * t;
                int gm0 = m0 + c, gm1 = gm0 + 1;
                int ec0 = rsel_c[c], ec1 = rsel_c[c + 1];
                float s00 = (gm0 <= gl0 && ec0 == e0) ? acc_s[fn][0] * cf0 : 0.f;
                float s01 = (gm1 <= gl0 && ec1 == e0) ? acc_s[fn][1] * cf0 : 0.f;
                float s10 = (gm0 <= gl1 && ec0 == e1) ? acc_s[fn][2] * cf1 : 0.f;
                float s11 = (gm1 <= gl1 && ec1 == e1) ? acc_s[fn][3] * cf1 : 0.f;
                unsigned h00, l00, h01, l01, h10, l10, h11, l11;
                split_bf(s00, h00, l00); split_bf(s01, h01, l01);
                split_bf(s10, h10, l10); split_bf(s11, h11, l11);
                int pi = (wns >> 1) + fn * 4 + t;
                Sh[r0 * SU + pi] = h00 | (h01 << 16);
                Sl[r0 * SU + pi] = l00 | (l01 << 16);
                Sh[r1 * SU + pi] = h10 | (h11 << 16);
                Sl[r1 * SU + pi] = l10 | (l11 << 16);
            }
        }
        if (mt + 1 < ntiles)
            asm volatile("cp.async.wait_group 1;\n" ::);  // V(mt) done, K(mt+1) pending
        else
            asm volatile("cp.async.wait_group 0;\n" ::);  // last tile: V must be done
        __syncthreads();                                   // S + V visible

        // ---- O += S @ V (bf16 3-term): warp tile 16x64, 4 k16 steps ----
        #pragma unroll
        for (int kk = 0; kk < 4; kk++) {
            int p0 = kk * 8;
            int r0 = wm + g;
            unsigned ah0 = Sh[ r0      * SU + p0 + t];
            unsigned ah1 = Sh[(r0 + 8) * SU + p0 + t];
            unsigned ah2 = Sh[ r0      * SU + p0 + t + 4];
            unsigned ah3 = Sh[(r0 + 8) * SU + p0 + t + 4];
            unsigned al0 = Sl[ r0      * SU + p0 + t];
            unsigned al1 = Sl[(r0 + 8) * SU + p0 + t];
            unsigned al2 = Sl[ r0      * SU + p0 + t + 4];
            unsigned al3 = Sl[(r0 + 8) * SU + p0 + t + 4];
            #pragma unroll
            for (int fn = 0; fn < 8; fn++) {
                int c0 = wno + fn * 8 + g;
                unsigned bh0 = Vh[c0 * SU + p0 + t];
                unsigned bh1 = Vh[c0 * SU + p0 + t + 4];
                unsigned bl0 = Vl[c0 * SU + p0 + t];
                unsigned bl1 = Vl[c0 * SU + p0 + t + 4];
                mma16(acc_o[fn], ah0, ah1, ah2, ah3, bh0, bh1);
                mma16(acc_o[fn], ah0, ah1, ah2, ah3, bl0, bl1);
                mma16(acc_o[fn], al0, al1, al2, al3, bh0, bh1);
            }
        }
    }

    // ---- fused LayerNorm(128) * silu(gate) epilogue ----
    __syncthreads();                          // all smem reads done; reuse Sh region
    float* red_s = (float*)(smu + ASH);       // [128]: half*64 + row
    float* red_q = red_s + 128;               // [128]
    {
        int half = warp & 1;
        int r0 = wm + g, r1 = r0 + 8;
        float s0 = 0.f, q0 = 0.f, s1 = 0.f, q1 = 0.f;
        #pragma unroll
        for (int fn = 0; fn < 8; fn++) {
            float v0 = acc_o[fn][0], v1 = acc_o[fn][1];
            float v2 = acc_o[fn][2], v3 = acc_o[fn][3];
            s0 += v0 + v1;  q0 += v0*v0 + v1*v1;
            s1 += v2 + v3;  q1 += v2*v2 + v3*v3;
        }
        #pragma unroll
        for (int off = 1; off <= 2; off <<= 1) {
            s0 += __shfl_xor_sync(0xffffffffu, s0, off);
            q0 += __shfl_xor_sync(0xffffffffu, q0, off);
            s1 += __shfl_xor_sync(0xffffffffu, s1, off);
            q1 += __shfl_xor_sync(0xffffffffu, q1, off);
        }
        if (t == 0) {
            red_s[half*64 + r0] = s0;  red_q[half*64 + r0] = q0;
            red_s[half*64 + r1] = s1;  red_q[half*64 + r1] = q1;
        }
        __syncthreads();
        float S0 = red_s[r0] + red_s[64 + r0];
        float Q0 = red_q[r0] + red_q[64 + r0];
        float S1 = red_s[r1] + red_s[64 + r1];
        float Q1 = red_q[r1] + red_q[64 + r1];
        float mu0 = S0 * (1.f/128.f), mu1 = S1 * (1.f/128.f);
        float inv0 = rsqrtf(Q0 * (1.f/128.f) - mu0*mu0 + 1e-5f);
        float inv1 = rsqrtf(Q1 * (1.f/128.f) - mu1*mu1 + 1e-5f);
        size_t gbase0 = (size_t)(l0 + r0) * NCAT + 2*DKK + DVV + h * HDVV;
        size_t gbase1 = (size_t)(l0 + r1) * NCAT + 2*DKK + DVV + h * HDVV;
        size_t ybase0 = (size_t)(l0 + r0) * DVV + h * HDVV;
        size_t ybase1 = (size_t)(l0 + r1) * DVV + h * HDVV;
        #pragma unroll
        for (int fn = 0; fn < 8; fn++) {
            int c = wno + fn * 8 + 2 * t;
            float2 gt0 = *(const float2*)(g_qkvg + gbase0 + c);
            float2 gt1 = *(const float2*)(g_qkvg + gbase1 + c);
            float2 y0, y1;
            y0.x = tf32r(silu_f(gt0.x) * (acc_o[fn][0] - mu0) * inv0);
            y0.y = tf32r(silu_f(gt0.y) * (acc_o[fn][1] - mu0) * inv0);
            y1.x = tf32r(silu_f(gt1.x) * (acc_o[fn][2] - mu1) * inv1);
            y1.y = tf32r(silu_f(gt1.y) * (acc_o[fn][3] - mu1) * inv1);
            *(float2*)(g_y + ybase0 + c) = y0;
            *(float2*)(g_y + ybase1 + c) = y1;
        }
    }
}

// ---------------- launch ----------------------------------------------------
extern "C" void kernel_launch(void* const* d_in, const int* in_sizes, int n_in,
                              void* d_out, int out_size) {
    const float* x    = (const float*)d_in[0];
    const float* cw   = (const float*)d_in[1];
    const float* Wq   = (const float*)d_in[2];
    const float* Wk   = (const float*)d_in[3];
    const float* Wv   = (const float*)d_in[4];
    const float* Wg   = (const float*)d_in[5];
    const float* rw   = (const float*)d_in[6];
    const float* Wout = (const float*)d_in[7];
    float* out = (float*)d_out;

    float *p_xctf, *p_qkvg, *p_y;
    cudaGetSymbolAddress((void**)&p_xctf, g_xctf);
    cudaGetSymbolAddress((void**)&p_qkvg, g_qkvg);
    cudaGetSymbolAddress((void**)&p_y,    g_y);

    cudaFuncSetAttribute(attn_tc,
                         cudaFuncAttributeMaxDynamicSharedMemorySize, ATTN4_BYTES);
    cudaFuncSetAttribute(gemm_tc<true>,
                         cudaFuncAttributeMaxDynamicSharedMemorySize, SMEM_GEMM4);
    cudaFuncSetAttribute(gemm_tc<false>,
                         cudaFuncAttributeMaxDynamicSharedMemorySize, SMEM_GEMM4);

    conv_silu_kernel<<<(LL*DD)/256, 256>>>(x, cw);
    w2_kernel<<<DD/8, 256>>>(Wv, rw);
    rlog_kernel<<<LL/4, 256>>>();

    // fused QKVG projection (silu on q columns), segmented B, B cvt in-loop
    gemm_tc<true><<<dim3(NCAT/128, LL/128), 256, SMEM_GEMM4>>>(
        p_xctf, Wq, Wk, Wv, Wg, p_qkvg, NCAT, DD, DKK);

    rope_split_kernel<<<(LL*HH*32)/256, 256>>>();
    vsplit_t_kernel<<<dim3(LL/64, HDVV/32, HH), 256>>>();
    router_kernel<<<HH, 256>>>();

    attn_tc<<<dim3(LL/64, HH), 256, ATTN4_BYTES>>>();

    gemm_tc<false><<<dim3(DD/128, LL/128), 256, SMEM_GEMM4>>>(
        p_y, Wout, Wout, Wout, Wout, out, DD, DVV, 0);
}

// round 15
// speedup vs baseline: 5.1959x; 1.0125x over previous
#include <cuda_runtime.h>
#include <cuda_bf16.h>
#include <math.h>

#define LL   2048
#define DD   2048
#define HH   16
#define DKK  1024
#define DVV  2048
#define HDKK 64
#define HDVV 128
#define NCAT 6144              // q(1024) | k(1024) | v(2048) | g(2048)

// ---------------- scratch (device globals; no allocation allowed) ----------
__device__ float g_xc  [LL*DD];      // conv+silu output (fp32 exact, for router)
__device__ float g_xctf[LL*DD];      // conv+silu output, tf32-rounded (GEMM A)
__device__ float g_qkvg[LL*NCAT];    // fused projection output
__device__ float g_w2  [DD*32];      // Wv @ router_w  (fp32 exact)
__device__ float g_rlog[LL*32];      // router logits  (fp32 exact)
__device__ __nv_bfloat16 g_qh[LL*DKK];   // roped q hi, [h][l][64]
__device__ __nv_bfloat16 g_ql[LL*DKK];   // roped q lo
__device__ __nv_bfloat16 g_kh[LL*DKK];   // roped k hi
__device__ __nv_bfloat16 g_kl[LL*DKK];   // roped k lo
__device__ __nv_bfloat16 g_vth[HH*HDVV*LL]; // v hi, TRANSPOSED [h][c][l]
__device__ __nv_bfloat16 g_vtl[HH*HDVV*LL]; // v lo, transposed
__device__ float g_y   [LL*DVV];     // silu(g)*LN(o), tf32-rounded
__device__ float g_coef[HH*LL];      // score_max/count * HDK^-0.5
__device__ int   g_rsel[HH*LL];      // selected expert per (h,l)

__device__ __forceinline__ float silu_f(float z) { return z / (1.f + expf(-z)); }

__device__ __forceinline__ unsigned f2tf(float f) {
    unsigned r;
    asm("cvt.rna.tf32.f32 %0, %1;" : "=r"(r) : "f"(f));
    return r;
}
__device__ __forceinline__ float tf32r(float f) { return __uint_as_float(f2tf(f)); }

__device__ __forceinline__ unsigned f2bfu(float f) {
    return (unsigned)__bfloat16_as_ushort(__float2bfloat16_rn(f));
}
__device__ __forceinline__ float bfu2f(unsigned u) {
    return __bfloat162float(__ushort_as_bfloat16((unsigned short)u));
}
__device__ __forceinline__ void split_bf(float v, unsigned& hi, unsigned& lo) {
    hi = f2bfu(v);
    lo = f2bfu(v - bfu2f(hi));
}

__device__ __forceinline__ void mma8(float* c,
                                     unsigned a0, unsigned a1, unsigned a2, unsigned a3,
                                     unsigned b0, unsigned b1) {
    asm("mma.sync.aligned.m16n8k8.row.col.f32.tf32.tf32.f32 "
        "{%0,%1,%2,%3}, {%4,%5,%6,%7}, {%8,%9}, {%0,%1,%2,%3};"
        : "+f"(c[0]), "+f"(c[1]), "+f"(c[2]), "+f"(c[3])
        : "r"(a0), "r"(a1), "r"(a2), "r"(a3), "r"(b0), "r"(b1));
}

__device__ __forceinline__ void mma16(float* c,
                                      unsigned a0, unsigned a1, unsigned a2, unsigned a3,
                                      unsigned b0, unsigned b1) {
    asm("mma.sync.aligned.m16n8k16.row.col.f32.bf16.bf16.f32 "
        "{%0,%1,%2,%3}, {%4,%5,%6,%7}, {%8,%9}, {%0,%1,%2,%3};"
        : "+f"(c[0]), "+f"(c[1]), "+f"(c[2]), "+f"(c[3])
        : "r"(a0), "r"(a1), "r"(a2), "r"(a3), "r"(b0), "r"(b1));
}

__device__ __forceinline__ void cp16(float* smem_dst, const float* gsrc) {
    unsigned sa = (unsigned)__cvta_generic_to_shared(smem_dst);
    asm volatile("cp.async.cg.shared.global [%0], [%1], 16;\n"
                 :: "r"(sa), "l"(gsrc));
}
__device__ __forceinline__ void cp16b(unsigned* smem_dst, const __nv_bfloat16* gsrc) {
    unsigned sa = (unsigned)__cvta_generic_to_shared(smem_dst);
    asm volatile("cp.async.cg.shared.global [%0], [%1], 16;\n"
                 :: "r"(sa), "l"(gsrc));
}

// ---------------- stage 1: shifted conv + silu -----------------------------
__global__ void conv_silu_kernel(const float* __restrict__ x,
                                 const float* __restrict__ cw) {
    int idx = blockIdx.x * blockDim.x + threadIdx.x;  // over L*D
    if (idx >= LL*DD) return;
    int d = idx & (DD-1);
    int l = idx >> 11;
    float prev = (l == 0) ? 0.f : x[idx - DD];
    float z = prev * cw[2*d] + x[idx] * cw[2*d + 1];
    float v = silu_f(z);
    g_xc[idx]   = v;
    g_xctf[idx] = tf32r(v);
}

// ---------------- W2 = Wv @ router_w (fp32 exact, [2048][32]) --------------
__global__ void w2_kernel(const float* __restrict__ Wv,
                          const float* __restrict__ rw) {
    int tid = threadIdx.x;                 // 256 threads, 8 k-rows per block
    int k  = blockIdx.x * 8 + (tid >> 5);
    int t  = tid & 31;
    int h  = t >> 1, r = t & 1;
    const float* wrow = Wv + (size_t)k * DVV + h * HDVV;
    const float* rr   = rw + (h * HDVV) * 2 + r;
    float a0 = 0.f, a1 = 0.f, a2 = 0.f, a3 = 0.f;
    #pragma unroll 8
    for (int d = 0; d < HDVV; d += 4) {
        a0 += wrow[d]     * rr[2*d];
        a1 += wrow[d + 1] * rr[2*d + 2];
        a2 += wrow[d + 2] * rr[2*d + 4];
        a3 += wrow[d + 3] * rr[2*d + 6];
    }
    g_w2[k * 32 + t] = (a0 + a1) + (a2 + a3);
}

// ---------------- router logits = xc @ W2 (fp32 exact, [2048][32]) ---------
__global__ void rlog_kernel() {
    int tid  = threadIdx.x;
    int lsub = tid >> 6;            // 0..3
    int u    = tid & 63;
    int hr   = u & 31;
    int kh   = u >> 5;              // k-half 0/1
    int l    = blockIdx.x * 4 + lsub;
    const float* xrow = g_xc + (size_t)l * DD + kh * 1024;
    const float* w2p  = g_w2 + (size_t)kh * 1024 * 32 + hr;
    float a0 = 0.f, a1 = 0.f, a2 = 0.f, a3 = 0.f;
    #pragma unroll 8
    for (int k = 0; k < 1024; k += 4) {
        a0 += xrow[k]     * w2p[(k    ) * 32];
        a1 += xrow[k + 1] * w2p[(k + 1) * 32];
        a2 += xrow[k + 2] * w2p[(k + 2) * 32];
        a3 += xrow[k + 3] * w2p[(k + 3) * 32];
    }
    __shared__ float part[256];
    part[tid] = (a0 + a1) + (a2 + a3);
    __syncthreads();
    if (kh == 0)
        g_rlog[l * 32 + hr] = part[tid] + part[tid + 32];
}

// ---------------- tensor-core GEMM (TF32, 5-stage, 1 barrier/iter) ---------
#define AP4 20
#define BPAD 136
#define STGF4 (128*AP4 + 16*BPAD)     // floats per stage = 4736
#define SMEM_GEMM5 (5 * STGF4 * 4)    // 94720 bytes

template<bool SEG>
__global__ __launch_bounds__(256, 2) void gemm_tc(
        const float* __restrict__ A,
        const float* __restrict__ B0,
        const float* __restrict__ B1,
        const float* __restrict__ B2,
        const float* __restrict__ B3,
        float* __restrict__ C,
        int N, int K, int silu_ncols) {
    extern __shared__ float sm[];

    int tid = threadIdx.x, lane = tid & 31, warp = tid >> 5;
    int bm = blockIdx.y * 128, bn = blockIdx.x * 128;
    int wm = (warp >> 2) * 64, wn = (warp & 3) * 32;
    int g = lane >> 2, t = lane & 3;

    const float* Bseg; int ldb, bcol;
    if (SEG) {
        if (bn < 1024)      { Bseg = B0; ldb = 1024; bcol = bn; }
        else if (bn < 2048) { Bseg = B1; ldb = 1024; bcol = bn - 1024; }
        else if (bn < 4096) { Bseg = B2; ldb = 2048; bcol = bn - 2048; }
        else                { Bseg = B3; ldb = 2048; bcol = bn - 4096; }
    } else {
        Bseg = B0; ldb = N; bcol = bn;
    }

    float acc[4][4][4];
    #pragma unroll
    for (int i = 0; i < 4; i++)
        #pragma unroll
        for (int j = 0; j < 4; j++)
            #pragma unroll
            for (int r = 0; r < 4; r++) acc[i][j][r] = 0.f;

    const float* agp[2];
    const float* bgp[2];
    int asp[2], bsp[2];
    #pragma unroll
    for (int i = 0; i < 2; i++) {
        int idx = tid + i * 256;
        int ar = idx >> 2, ac = (idx & 3) * 4;    // A: 128 rows x 16 k
        int br = idx >> 5, bc = (idx & 31) * 4;   // B: 16 k x 128 cols
        agp[i] = A + (size_t)(bm + ar) * K + ac;
        bgp[i] = Bseg + (size_t)br * ldb + bcol + bc;
        asp[i] = ar * AP4 + ac;
        bsp[i] = 128 * AP4 + br * BPAD + bc;
    }

#define LOAD_STAGE(s, k0) do {                                          \
        float* base_ = sm + (s) * STGF4;                                \
        _Pragma("unroll")                                               \
        for (int i_ = 0; i_ < 2; i_++) {                                \
            cp16(base_ + asp[i_], agp[i_] + (k0));                      \
            cp16(base_ + bsp[i_], bgp[i_] + (size_t)(k0) * ldb);        \
        }                                                               \
        asm volatile("cp.async.commit_group;\n" ::);                    \
    } while (0)

    int nk = K >> 4;                  // K-tile 16
    LOAD_STAGE(0, 0);
    LOAD_STAGE(1, 16);
    LOAD_STAGE(2, 32);
    LOAD_STAGE(3, 48);

    int s = 0;
    for (int kt = 0; kt < nk; kt++) {
        asm volatile("cp.async.wait_group 3;\n" ::);
        __syncthreads();              // also guarantees kt-1 readers done
        const float* Ah = sm + s * STGF4;
        const float* Bh = Ah + 128 * AP4;

        #pragma unroll
        for (int ko = 0; ko < 16; ko += 8) {
            unsigned af[4][4], bf[4][2];
            #pragma unroll
            for (int fm = 0; fm < 4; fm++) {
                int r0 = wm + fm * 16 + g;
                af[fm][0] = __float_as_uint(Ah[ r0      * AP4 + ko + t]);
                af[fm][1] = __float_as_uint(Ah[(r0 + 8) * AP4 + ko + t]);
                af[fm][2] = __float_as_uint(Ah[ r0      * AP4 + ko + t + 4]);
                af[fm][3] = __float_as_uint(Ah[(r0 + 8) * AP4 + ko + t + 4]);
            }
            #pragma unroll
            for (int fn = 0; fn < 4; fn++) {
                int c0 = wn + fn * 8 + g;
                bf[fn][0] = f2tf(Bh[(ko + t    ) * BPAD + c0]);
                bf[fn][1] = f2tf(Bh[(ko + t + 4) * BPAD + c0]);
            }
            #pragma unroll
            for (int fm = 0; fm < 4; fm++)
                #pragma unroll
                for (int fn = 0; fn < 4; fn++)
                    mma8(acc[fm][fn], af[fm][0], af[fm][1], af[fm][2], af[fm][3],
                         bf[fn][0], bf[fn][1]);
        }
        // load stage (kt+4)%5 == (kt-1)%5: its readers finished before the
        // top-of-iteration barrier, so no second barrier is needed.
        if (kt + 4 < nk) LOAD_STAGE((kt + 4) % 5, (kt + 4) * 16);
        s = (s == 4) ? 0 : s + 1;
    }

    #pragma unroll
    for (int fm = 0; fm < 4; fm++) {
        int r0 = bm + wm + fm * 16 + g;
        #pragma unroll
        for (int fn = 0; fn < 4; fn++) {
            int c0 = bn + wn + fn * 8 + 2 * t;
            float v0 = acc[fm][fn][0], v1 = acc[fm][fn][1];
            float v2 = acc[fm][fn][2], v3 = acc[fm][fn][3];
            if (c0 < silu_ncols) {
                v0 = silu_f(v0); v1 = silu_f(v1);
                v2 = silu_f(v2); v3 = silu_f(v3);
            }
            *(float2*)(C + (size_t)r0 * N + c0)       = make_float2(v0, v1);
            *(float2*)(C + (size_t)(r0 + 8) * N + c0) = make_float2(v2, v3);
        }
    }
#undef LOAD_STAGE
}

// ---------------- stage 3: RoPE + bf16 hi/lo split, head-major -------------
__global__ void rope_split_kernel() {
    int idx = blockIdx.x * blockDim.x + threadIdx.x;   // L*H*32
    if (idx >= LL * HH * 32) return;
    int i  = idx & 31;
    int lh = idx >> 5;
    int h  = lh & (HH-1);
    int l  = lh >> 4;
    float invf = powf(10000.f, -(float)i / 32.f);
    float ang = (float)l * invf;
    float c = cosf(ang), s = sinf(ang);
    size_t qb = (size_t)l * NCAT + h * HDKK;
    size_t kb = qb + DKK;
    size_t ob = ((size_t)h * LL + l) * HDKK;
    float q1 = g_qkvg[qb + i], q2 = g_qkvg[qb + 32 + i];
    float k1 = g_qkvg[kb + i], k2 = g_qkvg[kb + 32 + i];
    float qa = q1 * c - q2 * s, qbv = q2 * c + q1 * s;
    float ka = k1 * c - k2 * s, kbv = k2 * c + k1 * s;
    __nv_bfloat16 hb;
    hb = __float2bfloat16_rn(qa);
    g_qh[ob + i] = hb;  g_ql[ob + i] = __float2bfloat16_rn(qa - __bfloat162float(hb));
    hb = __float2bfloat16_rn(qbv);
    g_qh[ob + 32 + i] = hb;  g_ql[ob + 32 + i] = __float2bfloat16_rn(qbv - __bfloat162float(hb));
    hb = __float2bfloat16_rn(ka);
    g_kh[ob + i] = hb;  g_kl[ob + i] = __float2bfloat16_rn(ka - __bfloat162float(hb));
    hb = __float2bfloat16_rn(kbv);
    g_kh[ob + 32 + i] = hb;  g_kl[ob + 32 + i] = __float2bfloat16_rn(kbv - __bfloat162float(hb));
}

// ---------------- v transpose + bf16 split: [h][c][l] ----------------------
__global__ void vsplit_t_kernel() {
    __shared__ float tile[64][33];
    int l0 = blockIdx.x * 64, c0 = blockIdx.y * 32, h = blockIdx.z;
    int tid = threadIdx.x;
    for (int i = tid; i < 64 * 32; i += 256) {
        int li = i >> 5, ci = i & 31;
        tile[li][ci] = g_qkvg[(size_t)(l0 + li) * NCAT + 2*DKK + h * HDVV + c0 + ci];
    }
    __syncthreads();
    for (int i = tid; i < 32 * 64; i += 256) {
        int ci = i >> 6, li = i & 63;
        float v = tile[li][ci];
        __nv_bfloat16 hb = __float2bfloat16_rn(v);
        size_t ob = ((size_t)h * HDVV + c0 + ci) * LL + l0 + li;
        g_vth[ob] = hb;
        g_vtl[ob] = __float2bfloat16_rn(v - __bfloat162float(hb));
    }
}

// ---------------- stage 4: router decision + parallel count scan -----------
__global__ void router_kernel() {
    int h = blockIdx.x;                    // 16 blocks, 256 threads
    int tid = threadIdx.x;
    __shared__ float s_score[LL];
    __shared__ unsigned char s_sel[LL];
    __shared__ int ps0[256], ps1[256];
    for (int l = tid; l < LL; l += 256) {
        float z0 = g_rlog[l * 32 + h * 2 + 0];
        float z1 = g_rlog[l * 32 + h * 2 + 1];
        int sel = (z1 > z0) ? 1 : 0;
        float m = fmaxf(z0, z1);
        float e0 = expf(z0 - m), e1 = expf(z1 - m);
        s_sel[l]   = (unsigned char)sel;
        s_score[l] = ((sel == 0) ? e0 : e1) / (e0 + e1);
    }
    __syncthreads();
    int base = tid * 8;
    int c0 = 0, c1 = 0;
    #pragma unroll
    for (int i = 0; i < 8; i++) {
        if (s_sel[base + i]) c1++; else c0++;
    }
    ps0[tid] = c0; ps1[tid] = c1;
    __syncthreads();
    for (int off = 1; off < 256; off <<= 1) {
        int v0 = (tid >= off) ? ps0[tid - off] : 0;
        int v1 = (tid >= off) ? ps1[tid - off] : 0;
        __syncthreads();
        ps0[tid] += v0; ps1[tid] += v1;
        __syncthreads();
    }
    int b0 = ps0[tid] - c0, b1 = ps1[tid] - c1;   // exclusive prefix
    const float scale = 0.125f;                   // HDK^{-1/2}
    #pragma unroll
    for (int i = 0; i < 8; i++) {
        int l = base + i;
        int sel = s_sel[l];
        int cnt;
        if (sel) { b1++; cnt = b1; } else { b0++; cnt = b0; }
        g_rsel[h * LL + l] = sel;
        g_coef[h * LL + l] = s_score[l] / (float)cnt * scale;
    }
}

// ---------------- stage 5: bf16 attention, Q in registers ------------------
#define SU 36
#define AKB 0
#define AKSTG (2*64*SU)              // one K stage = hi + lo
#define ASH (AKB + 2*AKSTG)
#define ASL (ASH + 64*SU)
#define AVH (ASL + 64*SU)            // V^T: 128 rows
#define AVL (AVH + 128*SU)
#define ACF (AVL + 128*SU)
#define ARR (ACF + 64)
#define ARC (ARR + 64)
#define ATTN5_WORDS (ARC + 64)
#define ATTN5_BYTES (ATTN5_WORDS * 4)   // ~93 KB -> 2 CTAs/SM

__global__ __launch_bounds__(256, 2) void attn_tc() {
    extern __shared__ unsigned smu[];
    unsigned* Sh = smu + ASH;  unsigned* Sl = smu + ASL;
    unsigned* Vh = smu + AVH;  unsigned* Vl = smu + AVL;
    float* coef_r = (float*)(smu + ACF);
    int*   rsel_r = (int*)(smu + ARR);
    int*   rsel_c = (int*)(smu + ARC);

    int h   = blockIdx.y;
    int l0  = (gridDim.x - 1 - blockIdx.x) * 64;   // heavy tiles first
    int tid = threadIdx.x, lane = tid & 31, warp = tid >> 5;
    int g = lane >> 2, t = lane & 3;
    int wm  = (warp >> 1) * 16;
    int wns = (warp & 1) * 32;
    int wno = (warp & 1) * 64;

    const __nv_bfloat16* Kh_g  = g_kh  + (size_t)h * LL * HDKK;
    const __nv_bfloat16* Kl_g  = g_kl  + (size_t)h * LL * HDKK;
    const __nv_bfloat16* Vth_g = g_vth + (size_t)h * HDVV * LL;
    const __nv_bfloat16* Vtl_g = g_vtl + (size_t)h * HDVV * LL;

#define LOAD_K(s, m0) do {                                                  \
        unsigned* kh_ = smu + AKB + (s) * AKSTG;                            \
        unsigned* kl_ = kh_ + 64*SU;                                        \
        _Pragma("unroll")                                                   \
        for (int i_ = 0; i_ < 2; i_++) {                                    \
            int idx_ = tid + i_ * 256, r_ = idx_ >> 3, j_ = idx_ & 7;       \
            cp16b(kh_ + r_*SU + j_*4, Kh_g + (size_t)((m0)+r_)*HDKK + j_*8);\
            cp16b(kl_ + r_*SU + j_*4, Kl_g + (size_t)((m0)+r_)*HDKK + j_*8);\
        }                                                                   \
        asm volatile("cp.async.commit_group;\n" ::);                        \
    } while (0)

#define LOAD_V(m0) do {                                                     \
        _Pragma("unroll")                                                   \
        for (int i_ = 0; i_ < 4; i_++) {                                    \
            int idx_ = tid + i_ * 256, r_ = idx_ >> 3, j_ = idx_ & 7;       \
            cp16b(Vh + r_*SU + j_*4, Vth_g + (size_t)r_*LL + (m0) + j_*8);  \
            cp16b(Vl + r_*SU + j_*4, Vtl_g + (size_t)r_*LL + (m0) + j_*8);  \
        }                                                                   \
        asm volatile("cp.async.commit_group;\n" ::);                        \
    } while (0)

    // prologue: K(0) in flight; Q fragments -> registers (reused all tiles)
    LOAD_K(0, 0);
    unsigned qh_r[4][4], ql_r[4][4];
    {
        const unsigned* Qg_h = (const unsigned*)g_qh + ((size_t)h * LL + l0) * 32;
        const unsigned* Qg_l = (const unsigned*)g_ql + ((size_t)h * LL + l0) * 32;
        int r0 = wm + g;
        #pragma unroll
        for (int kk = 0; kk < 4; kk++) {
            int w0 = kk * 8 + t, w1 = w0 + 4;
            qh_r[kk][0] = Qg_h[ r0      * 32 + w0];
            qh_r[kk][1] = Qg_h[(r0 + 8) * 32 + w0];
            qh_r[kk][2] = Qg_h[ r0      * 32 + w1];
            qh_r[kk][3] = Qg_h[(r0 + 8) * 32 + w1];
            ql_r[kk][0] = Qg_l[ r0      * 32 + w0];
            ql_r[kk][1] = Qg_l[(r0 + 8) * 32 + w0];
            ql_r[kk][2] = Qg_l[ r0      * 32 + w1];
            ql_r[kk][3] = Qg_l[(r0 + 8) * 32 + w1];
        }
    }
    if (tid < 64) {
        rsel_r[tid] = g_rsel[h * LL + l0 + tid];
        coef_r[tid] = g_coef[h * LL + l0 + tid];
    }

    float acc_o[8][4];
    #pragma unroll
    for (int fn = 0; fn < 8; fn++)
        #pragma unroll
        for (int r = 0; r < 4; r++) acc_o[fn][r] = 0.f;

    int ntiles = (l0 >> 6) + 1;
    for (int mt = 0; mt < ntiles; mt++) {
        int m0 = mt * 64;
        int s  = mt & 1;
        __syncthreads();                    // prev V/S reads done
        LOAD_V(m0);
        if (tid < 64) rsel_c[tid] = g_rsel[h * LL + m0 + tid];
        asm volatile("cp.async.wait_group 1;\n" ::);   // K(mt) done
        __syncthreads();

        const unsigned* Kts = smu + AKB + s * AKSTG;
        const unsigned* Kls = Kts + 64*SU;

        // ---- QK^T (bf16 3-term): warp tile 16x32, 4 k16 steps ----
        float acc_s[4][4];
        #pragma unroll
        for (int fn = 0; fn < 4; fn++)
            #pragma unroll
            for (int r = 0; r < 4; r++) acc_s[fn][r] = 0.f;

        #pragma unroll
        for (int kk = 0; kk < 4; kk++) {
            int p0 = kk * 8;
            #pragma unroll
            for (int fn = 0; fn < 4; fn++) {
                int c0 = wns + fn * 8 + g;
                unsigned bh0 = Kts[c0 * SU + p0 + t];
                unsigned bh1 = Kts[c0 * SU + p0 + t + 4];
                unsigned bl0 = Kls[c0 * SU + p0 + t];
                unsigned bl1 = Kls[c0 * SU + p0 + t + 4];
                mma16(acc_s[fn], qh_r[kk][0], qh_r[kk][1], qh_r[kk][2], qh_r[kk][3], bh0, bh1);
                mma16(acc_s[fn], qh_r[kk][0], qh_r[kk][1], qh_r[kk][2], qh_r[kk][3], bl0, bl1);
                mma16(acc_s[fn], ql_r[kk][0], ql_r[kk][1], ql_r[kk][2], ql_r[kk][3], bh0, bh1);
            }
        }

        // prefetch K(mt+1) — K(mt) reads are done
        if (mt + 1 < ntiles) LOAD_K(s ^ 1, m0 + 64);

        // ---- mask + coef, pack bf16 hi/lo pairs into S ----
        {
            int r0 = wm + g, r1 = r0 + 8;
            int gl0 = l0 + r0, gl1 = l0 + r1;
            int e0 = rsel_r[r0], e1 = rsel_r[r1];
            float cf0 = coef_r[r0], cf1 = coef_r[r1];
            #pragma unroll
            for (int fn = 0; fn < 4; fn++) {
                int c = wns + fn * 8 + 2 * t;
                int gm0 = m0 + c, gm1 = gm0 + 1;
                int ec0 = rsel_c[c], ec1 = rsel_c[c + 1];
                float s00 = (gm0 <= gl0 && ec0 == e0) ? acc_s[fn][0] * cf0 : 0.f;
                float s01 = (gm1 <= gl0 && ec1 == e0) ? acc_s[fn][1] * cf0 : 0.f;
                float s10 = (gm0 <= gl1 && ec0 == e1) ? acc_s[fn][2] * cf1 : 0.f;
                float s11 = (gm1 <= gl1 && ec1 == e1) ? acc_s[fn][3] * cf1 : 0.f;
                unsigned h00, l00, h01, l01, h10, l10, h11, l11;
                split_bf(s00, h00, l00); split_bf(s01, h01, l01);
                split_bf(s10, h10, l10); split_bf(s11, h11, l11);
                int pi = (wns >> 1) + fn * 4 + t;
                Sh[r0 * SU + pi] = h00 | (h01 << 16);
                Sl[r0 * SU + pi] = l00 | (l01 << 16);
                Sh[r1 * SU + pi] = h10 | (h11 << 16);
                Sl[r1 * SU + pi] = l10 | (l11 << 16);
            }
        }
        if (mt + 1 < ntiles)
            asm volatile("cp.async.wait_group 1;\n" ::);  // V(mt) done, K(mt+1) pending
        else
            asm volatile("cp.async.wait_group 0;\n" ::);  // last tile: V must be done
        __syncthreads();                                   // S + V visible

        // ---- O += S @ V (bf16 3-term): warp tile 16x64, 4 k16 steps ----
        #pragma unroll
        for (int kk = 0; kk < 4; kk++) {
            int p0 = kk * 8;
            int r0 = wm + g;
            unsigned ah0 = Sh[ r0      * SU + p0 + t];
            unsigned ah1 = Sh[(r0 + 8) * SU + p0 + t];
            unsigned ah2 = Sh[ r0      * SU + p0 + t + 4];
            unsigned ah3 = Sh[(r0 + 8) * SU + p0 + t + 4];
            unsigned al0 = Sl[ r0      * SU + p0 + t];
            unsigned al1 = Sl[(r0 + 8) * SU + p0 + t];
            unsigned al2 = Sl[ r0      * SU + p0 + t + 4];
            unsigned al3 = Sl[(r0 + 8) * SU + p0 + t + 4];
            #pragma unroll
            for (int fn = 0; fn < 8; fn++) {
                int c0 = wno + fn * 8 + g;
                unsigned bh0 = Vh[c0 * SU + p0 + t];
                unsigned bh1 = Vh[c0 * SU + p0 + t + 4];
                unsigned bl0 = Vl[c0 * SU + p0 + t];
                unsigned bl1 = Vl[c0 * SU + p0 + t + 4];
                mma16(acc_o[fn], ah0, ah1, ah2, ah3, bh0, bh1);
                mma16(acc_o[fn], ah0, ah1, ah2, ah3, bl0, bl1);
                mma16(acc_o[fn], al0, al1, al2, al3, bh0, bh1);
            }
        }
    }

    // ---- fused LayerNorm(128) * silu(gate) epilogue ----
    __syncthreads();                          // all smem reads done; reuse Sh region
    float* red_s = (float*)(smu + ASH);       // [128]: half*64 + row
    float* red_q = red_s + 128;               // [128]
    {
        int half = warp & 1;
        int r0 = wm + g, r1 = r0 + 8;
        float s0 = 0.f, q0 = 0.f, s1 = 0.f, q1 = 0.f;
        #pragma unroll
        for (int fn = 0; fn < 8; fn++) {
            float v0 = acc_o[fn][0], v1 = acc_o[fn][1];
            float v2 = acc_o[fn][2], v3 = acc_o[fn][3];
            s0 += v0 + v1;  q0 += v0*v0 + v1*v1;
            s1 += v2 + v3;  q1 += v2*v2 + v3*v3;
        }
        #pragma unroll
        for (int off = 1; off <= 2; off <<= 1) {
            s0 += __shfl_xor_sync(0xffffffffu, s0, off);
            q0 += __shfl_xor_sync(0xffffffffu, q0, off);
            s1 += __shfl_xor_sync(0xffffffffu, s1, off);
            q1 += __shfl_xor_sync(0xffffffffu, q1, off);
        }
        if (t == 0) {
            red_s[half*64 + r0] = s0;  red_q[half*64 + r0] = q0;
            red_s[half*64 + r1] = s1;  red_q[half*64 + r1] = q1;
        }
        __syncthreads();
        float S0 = red_s[r0] + red_s[64 + r0];
        float Q0 = red_q[r0] + red_q[64 + r0];
        float S1 = red_s[r1] + red_s[64 + r1];
        float Q1 = red_q[r1] + red_q[64 + r1];
        float mu0 = S0 * (1.f/128.f), mu1 = S1 * (1.f/128.f);
        float inv0 = rsqrtf(Q0 * (1.f/128.f) - mu0*mu0 + 1e-5f);
        float inv1 = rsqrtf(Q1 * (1.f/128.f) - mu1*mu1 + 1e-5f);
        size_t gbase0 = (size_t)(l0 + r0) * NCAT + 2*DKK + DVV + h * HDVV;
        size_t gbase1 = (size_t)(l0 + r1) * NCAT + 2*DKK + DVV + h * HDVV;
        size_t ybase0 = (size_t)(l0 + r0) * DVV + h * HDVV;
        size_t ybase1 = (size_t)(l0 + r1) * DVV + h * HDVV;
        #pragma unroll
        for (int fn = 0; fn < 8; fn++) {
            int c = wno + fn * 8 + 2 * t;
            float2 gt0 = *(const float2*)(g_qkvg + gbase0 + c);
            float2 gt1 = *(const float2*)(g_qkvg + gbase1 + c);
            float2 y0, y1;
            y0.x = tf32r(silu_f(gt0.x) * (acc_o[fn][0] - mu0) * inv0);
            y0.y = tf32r(silu_f(gt0.y) * (acc_o[fn][1] - mu0) * inv0);
            y1.x = tf32r(silu_f(gt1.x) * (acc_o[fn][2] - mu1) * inv1);
            y1.y = tf32r(silu_f(gt1.y) * (acc_o[fn][3] - mu1) * inv1);
            *(float2*)(g_y + ybase0 + c) = y0;
            *(float2*)(g_y + ybase1 + c) = y1;
        }
    }
}

// ---------------- launch ----------------------------------------------------
extern "C" void kernel_launch(void* const* d_in, const int* in_sizes, int n_in,
                              void* d_out, int out_size) {
    const float* x    = (const float*)d_in[0];
    const float* cw   = (const float*)d_in[1];
    const float* Wq   = (const float*)d_in[2];
    const float* Wk   = (const float*)d_in[3];
    const float* Wv   = (const float*)d_in[4];
    const float* Wg   = (const float*)d_in[5];
    const float* rw   = (const float*)d_in[6];
    const float* Wout = (const float*)d_in[7];
    float* out = (float*)d_out;

    float *p_xctf, *p_qkvg, *p_y;
    cudaGetSymbolAddress((void**)&p_xctf, g_xctf);
    cudaGetSymbolAddress((void**)&p_qkvg, g_qkvg);
    cudaGetSymbolAddress((void**)&p_y,    g_y);

    cudaFuncSetAttribute(attn_tc,
                         cudaFuncAttributeMaxDynamicSharedMemorySize, ATTN5_BYTES);
    cudaFuncSetAttribute(gemm_tc<true>,
                         cudaFuncAttributeMaxDynamicSharedMemorySize, SMEM_GEMM5);
    cudaFuncSetAttribute(gemm_tc<false>,
                         cudaFuncAttributeMaxDynamicSharedMemorySize, SMEM_GEMM5);

    conv_silu_kernel<<<(LL*DD)/256, 256>>>(x, cw);
    w2_kernel<<<DD/8, 256>>>(Wv, rw);
    rlog_kernel<<<LL/4, 256>>>();

    // fused QKVG projection (silu on q columns), segmented B, B cvt in-loop
    gemm_tc<true><<<dim3(NCAT/128, LL/128), 256, SMEM_GEMM5>>>(
        p_xctf, Wq, Wk, Wv, Wg, p_qkvg, NCAT, DD, DKK);

    rope_split_kernel<<<(LL*HH*32)/256, 256>>>();
    vsplit_t_kernel<<<dim3(LL/64, HDVV/32, HH), 256>>>();
    router_kernel<<<HH, 256>>>();

    attn_tc<<<dim3(LL/64, HH), 256, ATTN5_BYTES>>>();

    gemm_tc<false><<<dim3(DD/128, LL/128), 256, SMEM_GEMM5>>>(
        p_y, Wout, Wout, Wout, Wout, out, DD, DVV, 0);
}

// round 16
// speedup vs baseline: 5.2524x; 1.0109x over previous
#include <cuda_runtime.h>
#include <cuda_bf16.h>
#include <math.h>

#define LL   2048
#define DD   2048
#define HH   16
#define DKK  1024
#define DVV  2048
#define HDKK 64
#define HDVV 128
#define NCAT 6144              // q(1024) | k(1024) | v(2048) | g(2048)

// ---------------- scratch (device globals; no allocation allowed) ----------
__device__ float g_xc  [LL*DD];      // conv+silu output (fp32 exact, for router)
__device__ float g_xctf[LL*DD];      // conv+silu output, tf32-rounded (GEMM A)
__device__ float g_qkvg[LL*NCAT];    // projection output (only g block written)
__device__ float g_w2  [DD*32];      // Wv @ router_w  (fp32 exact)
__device__ float g_rlog[LL*32];      // router logits  (fp32 exact)
__device__ __nv_bfloat16 g_qh[LL*DKK];   // roped q hi, [h][l][64]
__device__ __nv_bfloat16 g_ql[LL*DKK];   // roped q lo
__device__ __nv_bfloat16 g_kh[LL*DKK];   // roped k hi
__device__ __nv_bfloat16 g_kl[LL*DKK];   // roped k lo
__device__ __nv_bfloat16 g_vth[HH*HDVV*LL]; // v hi, TRANSPOSED [h][c][l]
__device__ __nv_bfloat16 g_vtl[HH*HDVV*LL]; // v lo, transposed
__device__ float g_y   [LL*DVV];     // silu(g)*LN(o), tf32-rounded
__device__ float g_coef[HH*LL];      // score_max/count * HDK^-0.5
__device__ int   g_rsel[HH*LL];      // selected expert per (h,l)

__device__ __forceinline__ float silu_f(float z) { return z / (1.f + expf(-z)); }

__device__ __forceinline__ unsigned f2tf(float f) {
    unsigned r;
    asm("cvt.rna.tf32.f32 %0, %1;" : "=r"(r) : "f"(f));
    return r;
}
__device__ __forceinline__ float tf32r(float f) { return __uint_as_float(f2tf(f)); }

__device__ __forceinline__ unsigned f2bfu(float f) {
    return (unsigned)__bfloat16_as_ushort(__float2bfloat16_rn(f));
}
__device__ __forceinline__ float bfu2f(unsigned u) {
    return __bfloat162float(__ushort_as_bfloat16((unsigned short)u));
}
__device__ __forceinline__ void split_bf(float v, unsigned& hi, unsigned& lo) {
    hi = f2bfu(v);
    lo = f2bfu(v - bfu2f(hi));
}

__device__ __forceinline__ void mma8(float* c,
                                     unsigned a0, unsigned a1, unsigned a2, unsigned a3,
                                     unsigned b0, unsigned b1) {
    asm("mma.sync.aligned.m16n8k8.row.col.f32.tf32.tf32.f32 "
        "{%0,%1,%2,%3}, {%4,%5,%6,%7}, {%8,%9}, {%0,%1,%2,%3};"
        : "+f"(c[0]), "+f"(c[1]), "+f"(c[2]), "+f"(c[3])
        : "r"(a0), "r"(a1), "r"(a2), "r"(a3), "r"(b0), "r"(b1));
}

__device__ __forceinline__ void mma16(float* c,
                                      unsigned a0, unsigned a1, unsigned a2, unsigned a3,
                                      unsigned b0, unsigned b1) {
    asm("mma.sync.aligned.m16n8k16.row.col.f32.bf16.bf16.f32 "
        "{%0,%1,%2,%3}, {%4,%5,%6,%7}, {%8,%9}, {%0,%1,%2,%3};"
        : "+f"(c[0]), "+f"(c[1]), "+f"(c[2]), "+f"(c[3])
        : "r"(a0), "r"(a1), "r"(a2), "r"(a3), "r"(b0), "r"(b1));
}

__device__ __forceinline__ void cp16(float* smem_dst, const float* gsrc) {
    unsigned sa = (unsigned)__cvta_generic_to_shared(smem_dst);
    asm volatile("cp.async.cg.shared.global [%0], [%1], 16;\n"
                 :: "r"(sa), "l"(gsrc));
}
__device__ __forceinline__ void cp16b(unsigned* smem_dst, const __nv_bfloat16* gsrc) {
    unsigned sa = (unsigned)__cvta_generic_to_shared(smem_dst);
    asm volatile("cp.async.cg.shared.global [%0], [%1], 16;\n"
                 :: "r"(sa), "l"(gsrc));
}

// ---------------- stage 1: shifted conv + silu -----------------------------
__global__ void conv_silu_kernel(const float* __restrict__ x,
                                 const float* __restrict__ cw) {
    int idx = blockIdx.x * blockDim.x + threadIdx.x;  // over L*D
    if (idx >= LL*DD) return;
    int d = idx & (DD-1);
    int l = idx >> 11;
    float prev = (l == 0) ? 0.f : x[idx - DD];
    float z = prev * cw[2*d] + x[idx] * cw[2*d + 1];
    float v = silu_f(z);
    g_xc[idx]   = v;
    g_xctf[idx] = tf32r(v);
}

// ---------------- W2 = Wv @ router_w (fp32 exact, [2048][32]) --------------
__global__ void w2_kernel(const float* __restrict__ Wv,
                          const float* __restrict__ rw) {
    int tid = threadIdx.x;                 // 256 threads, 8 k-rows per block
    int k  = blockIdx.x * 8 + (tid >> 5);
    int t  = tid & 31;
    int h  = t >> 1, r = t & 1;
    const float* wrow = Wv + (size_t)k * DVV + h * HDVV;
    const float* rr   = rw + (h * HDVV) * 2 + r;
    float a0 = 0.f, a1 = 0.f, a2 = 0.f, a3 = 0.f;
    #pragma unroll 8
    for (int d = 0; d < HDVV; d += 4) {
        a0 += wrow[d]     * rr[2*d];
        a1 += wrow[d + 1] * rr[2*d + 2];
        a2 += wrow[d + 2] * rr[2*d + 4];
        a3 += wrow[d + 3] * rr[2*d + 6];
    }
    g_w2[k * 32 + t] = (a0 + a1) + (a2 + a3);
}

// ---------------- router logits = xc @ W2 (fp32 exact, [2048][32]) ---------
__global__ void rlog_kernel() {
    int tid  = threadIdx.x;
    int lsub = tid >> 6;            // 0..3
    int u    = tid & 63;
    int hr   = u & 31;
    int kh   = u >> 5;              // k-half 0/1
    int l    = blockIdx.x * 4 + lsub;
    const float* xrow = g_xc + (size_t)l * DD + kh * 1024;
    const float* w2p  = g_w2 + (size_t)kh * 1024 * 32 + hr;
    float a0 = 0.f, a1 = 0.f, a2 = 0.f, a3 = 0.f;
    #pragma unroll 8
    for (int k = 0; k < 1024; k += 4) {
        a0 += xrow[k]     * w2p[(k    ) * 32];
        a1 += xrow[k + 1] * w2p[(k + 1) * 32];
        a2 += xrow[k + 2] * w2p[(k + 2) * 32];
        a3 += xrow[k + 3] * w2p[(k + 3) * 32];
    }
    __shared__ float part[256];
    part[tid] = (a0 + a1) + (a2 + a3);
    __syncthreads();
    if (kh == 0)
        g_rlog[l * 32 + hr] = part[tid] + part[tid + 32];
}

// ---------------- tensor-core GEMM (TF32, 5-stage, fused epilogue) ---------
// A pre-rounded tf32 in gmem. B raw fp32; fragments cvt'd in-loop.
// SEG: B segmented over {q,k,v,g}; q/k tiles get SiLU(q)+RoPE+bf16-split to
// head-major buffers; v tiles get transpose+split; g tiles write qkvg.
#define AP4 20
#define BPAD 136
#define STGF4 (128*AP4 + 16*BPAD)     // floats per stage = 4736
#define SMEM_GEMM5 (5 * STGF4 * 4)    // 94720 bytes (also >= 128*129*4 staging)

template<bool SEG>
__global__ __launch_bounds__(256, 2) void gemm_tc(
        const float* __restrict__ A,
        const float* __restrict__ B0,
        const float* __restrict__ B1,
        const float* __restrict__ B2,
        const float* __restrict__ B3,
        float* __restrict__ C,
        int N, int K, int silu_ncols) {
    extern __shared__ float sm[];

    int tid = threadIdx.x, lane = tid & 31, warp = tid >> 5;
    int bm = blockIdx.y * 128, bn = blockIdx.x * 128;
    int wm = (warp >> 2) * 64, wn = (warp & 3) * 32;
    int g = lane >> 2, t = lane & 3;

    const float* Bseg; int ldb, bcol;
    if (SEG) {
        if (bn < 1024)      { Bseg = B0; ldb = 1024; bcol = bn; }
        else if (bn < 2048) { Bseg = B1; ldb = 1024; bcol = bn - 1024; }
        else if (bn < 4096) { Bseg = B2; ldb = 2048; bcol = bn - 2048; }
        else                { Bseg = B3; ldb = 2048; bcol = bn - 4096; }
    } else {
        Bseg = B0; ldb = N; bcol = bn;
    }

    float acc[4][4][4];
    #pragma unroll
    for (int i = 0; i < 4; i++)
        #pragma unroll
        for (int j = 0; j < 4; j++)
            #pragma unroll
            for (int r = 0; r < 4; r++) acc[i][j][r] = 0.f;

    const float* agp[2];
    const float* bgp[2];
    int asp[2], bsp[2];
    #pragma unroll
    for (int i = 0; i < 2; i++) {
        int idx = tid + i * 256;
        int ar = idx >> 2, ac = (idx & 3) * 4;    // A: 128 rows x 16 k
        int br = idx >> 5, bc = (idx & 31) * 4;   // B: 16 k x 128 cols
        agp[i] = A + (size_t)(bm + ar) * K + ac;
        bgp[i] = Bseg + (size_t)br * ldb + bcol + bc;
        asp[i] = ar * AP4 + ac;
        bsp[i] = 128 * AP4 + br * BPAD + bc;
    }

#define LOAD_STAGE(s, k0) do {                                          \
        float* base_ = sm + (s) * STGF4;                                \
        _Pragma("unroll")                                               \
        for (int i_ = 0; i_ < 2; i_++) {                                \
            cp16(base_ + asp[i_], agp[i_] + (k0));                      \
            cp16(base_ + bsp[i_], bgp[i_] + (size_t)(k0) * ldb);        \
        }                                                               \
        asm volatile("cp.async.commit_group;\n" ::);                    \
    } while (0)

    int nk = K >> 4;                  // K-tile 16
    LOAD_STAGE(0, 0);
    LOAD_STAGE(1, 16);
    LOAD_STAGE(2, 32);
    LOAD_STAGE(3, 48);

    int s = 0;
    for (int kt = 0; kt < nk; kt++) {
        // sound tail handling: the stage read at kt was committed as group kt+1;
        // allowed outstanding = (groups committed) - (kt+1).
        int rem = nk - 1 - kt;
        if (rem >= 3)      asm volatile("cp.async.wait_group 3;\n" ::);
        else if (rem == 2) asm volatile("cp.async.wait_group 2;\n" ::);
        else if (rem == 1) asm volatile("cp.async.wait_group 1;\n" ::);
        else               asm volatile("cp.async.wait_group 0;\n" ::);
        __syncthreads();              // also guarantees kt-1 readers done
        const float* Ah = sm + s * STGF4;
        const float* Bh = Ah + 128 * AP4;

        #pragma unroll
        for (int ko = 0; ko < 16; ko += 8) {
            unsigned af[4][4], bf[4][2];
            #pragma unroll
            for (int fm = 0; fm < 4; fm++) {
                int r0 = wm + fm * 16 + g;
                af[fm][0] = __float_as_uint(Ah[ r0      * AP4 + ko + t]);
                af[fm][1] = __float_as_uint(Ah[(r0 + 8) * AP4 + ko + t]);
                af[fm][2] = __float_as_uint(Ah[ r0      * AP4 + ko + t + 4]);
                af[fm][3] = __float_as_uint(Ah[(r0 + 8) * AP4 + ko + t + 4]);
            }
            #pragma unroll
            for (int fn = 0; fn < 4; fn++) {
                int c0 = wn + fn * 8 + g;
                bf[fn][0] = f2tf(Bh[(ko + t    ) * BPAD + c0]);
                bf[fn][1] = f2tf(Bh[(ko + t + 4) * BPAD + c0]);
            }
            #pragma unroll
            for (int fm = 0; fm < 4; fm++)
                #pragma unroll
                for (int fn = 0; fn < 4; fn++)
                    mma8(acc[fm][fn], af[fm][0], af[fm][1], af[fm][2], af[fm][3],
                         bf[fn][0], bf[fn][1]);
        }
        if (kt + 4 < nk) LOAD_STAGE((kt + 4) % 5, (kt + 4) * 16);
        s = (s == 4) ? 0 : s + 1;
    }

    if (SEG && bn < 4096) {
        // -------- fused epilogue: stage tile, then RoPE/split or transpose --
        __syncthreads();              // all smem reads done; 0 cp.async pending
        float* st = sm;               // [128][129]
        #pragma unroll
        for (int fm = 0; fm < 4; fm++) {
            int r0 = wm + fm * 16 + g;
            #pragma unroll
            for (int fn = 0; fn < 4; fn++) {
                int c0 = wn + fn * 8 + 2 * t;
                float v0 = acc[fm][fn][0], v1 = acc[fm][fn][1];
                float v2 = acc[fm][fn][2], v3 = acc[fm][fn][3];
                if (bn < silu_ncols) {            // whole tile is q
                    v0 = silu_f(v0); v1 = silu_f(v1);
                    v2 = silu_f(v2); v3 = silu_f(v3);
                }
                st[ r0      * 129 + c0] = v0;  st[ r0      * 129 + c0 + 1] = v1;
                st[(r0 + 8) * 129 + c0] = v2;  st[(r0 + 8) * 129 + c0 + 1] = v3;
            }
        }
        __syncthreads();

        if (bn < 2048) {
            // ---- q/k tile: RoPE + bf16 hi/lo split, head-major ----
            bool isq = bn < 1024;
            int h0 = (isq ? bn : bn - 1024) >> 6;
            __nv_bfloat16* Oh = isq ? g_qh : g_kh;
            __nv_bfloat16* Ol = isq ? g_ql : g_kl;
            int u  = tid & 63, hh = u >> 5, i = u & 31;
            int lb = tid >> 6;        // 0..3
            float invf = powf(10000.f, -(float)i / 32.f);
            for (int pass = 0; pass < 32; pass++) {
                int l = lb + pass * 4;
                float x1 = st[l * 129 + hh * 64 + i];
                float x2 = st[l * 129 + hh * 64 + 32 + i];
                float ang = (float)(bm + l) * invf;
                float cc = cosf(ang), ss = sinf(ang);
                float ra = x1 * cc - x2 * ss;
                float rb = x2 * cc + x1 * ss;
                size_t ob = ((size_t)(h0 + hh) * LL + bm + l) * HDKK;
                __nv_bfloat16 hb;
                hb = __float2bfloat16_rn(ra);
                Oh[ob + i] = hb;
                Ol[ob + i] = __float2bfloat16_rn(ra - __bfloat162float(hb));
                hb = __float2bfloat16_rn(rb);
                Oh[ob + 32 + i] = hb;
                Ol[ob + 32 + i] = __float2bfloat16_rn(rb - __bfloat162float(hb));
            }
        } else {
            // ---- v tile (one full head): transpose + bf16 split, [h][c][l] --
            int h = (bn - 2048) >> 7;
            int c = tid >> 1;
            int l0off = (tid & 1) * 64;
            size_t ob = ((size_t)h * HDVV + c) * LL + bm + l0off;
            #pragma unroll
            for (int j = 0; j < 8; j++) {
                unsigned hw[4], lw[4];
                #pragma unroll
                for (int e = 0; e < 4; e++) {
                    int l = l0off + j * 8 + e * 2;
                    float v0 = st[ l      * 129 + c];
                    float v1 = st[(l + 1) * 129 + c];
                    unsigned h0b, l0b, h1b, l1b;
                    split_bf(v0, h0b, l0b);
                    split_bf(v1, h1b, l1b);
                    hw[e] = h0b | (h1b << 16);
                    lw[e] = l0b | (l1b << 16);
                }
                *(uint4*)(g_vth + ob + j * 8) = make_uint4(hw[0], hw[1], hw[2], hw[3]);
                *(uint4*)(g_vtl + ob + j * 8) = make_uint4(lw[0], lw[1], lw[2], lw[3]);
            }
        }
    } else {
        // -------- plain epilogue (g tiles, and gemm2) --------
        #pragma unroll
        for (int fm = 0; fm < 4; fm++) {
            int r0 = bm + wm + fm * 16 + g;
            #pragma unroll
            for (int fn = 0; fn < 4; fn++) {
                int c0 = bn + wn + fn * 8 + 2 * t;
                float v0 = acc[fm][fn][0], v1 = acc[fm][fn][1];
                float v2 = acc[fm][fn][2], v3 = acc[fm][fn][3];
                if (c0 < silu_ncols) {
                    v0 = silu_f(v0); v1 = silu_f(v1);
                    v2 = silu_f(v2); v3 = silu_f(v3);
                }
                *(float2*)(C + (size_t)r0 * N + c0)       = make_float2(v0, v1);
                *(float2*)(C + (size_t)(r0 + 8) * N + c0) = make_float2(v2, v3);
            }
        }
    }
#undef LOAD_STAGE
}

// ---------------- stage 4: router decision + parallel count scan -----------
__global__ void router_kernel() {
    int h = blockIdx.x;                    // 16 blocks, 256 threads
    int tid = threadIdx.x;
    __shared__ float s_score[LL];
    __shared__ unsigned char s_sel[LL];
    __shared__ int ps0[256], ps1[256];
    for (int l = tid; l < LL; l += 256) {
        float z0 = g_rlog[l * 32 + h * 2 + 0];
        float z1 = g_rlog[l * 32 + h * 2 + 1];
        int sel = (z1 > z0) ? 1 : 0;
        float m = fmaxf(z0, z1);
        float e0 = expf(z0 - m), e1 = expf(z1 - m);
        s_sel[l]   = (unsigned char)sel;
        s_score[l] = ((sel == 0) ? e0 : e1) / (e0 + e1);
    }
    __syncthreads();
    int base = tid * 8;
    int c0 = 0, c1 = 0;
    #pragma unroll
    for (int i = 0; i < 8; i++) {
        if (s_sel[base + i]) c1++; else c0++;
    }
    ps0[tid] = c0; ps1[tid] = c1;
    __syncthreads();
    for (int off = 1; off < 256; off <<= 1) {
        int v0 = (tid >= off) ? ps0[tid - off] : 0;
        int v1 = (tid >= off) ? ps1[tid - off] : 0;
        __syncthreads();
        ps0[tid] += v0; ps1[tid] += v1;
        __syncthreads();
    }
    int b0 = ps0[tid] - c0, b1 = ps1[tid] - c1;   // exclusive prefix
    const float scale = 0.125f;                   // HDK^{-1/2}
    #pragma unroll
    for (int i = 0; i < 8; i++) {
        int l = base + i;
        int sel = s_sel[l];
        int cnt;
        if (sel) { b1++; cnt = b1; } else { b0++; cnt = b0; }
        g_rsel[h * LL + l] = sel;
        g_coef[h * LL + l] = s_score[l] / (float)cnt * scale;
    }
}

// ---------------- stage 5: bf16 attention, Q in registers ------------------
#define SU 36
#define AKB 0
#define AKSTG (2*64*SU)              // one K stage = hi + lo
#define ASH (AKB + 2*AKSTG)
#define ASL (ASH + 64*SU)
#define AVH (ASL + 64*SU)            // V^T: 128 rows
#define AVL (AVH + 128*SU)
#define ACF (AVL + 128*SU)
#define ARR (ACF + 64)
#define ARC (ARR + 64)
#define ATTN5_WORDS (ARC + 64)
#define ATTN5_BYTES (ATTN5_WORDS * 4)   // ~93 KB -> 2 CTAs/SM

__global__ __launch_bounds__(256, 2) void attn_tc() {
    extern __shared__ unsigned smu[];
    unsigned* Sh = smu + ASH;  unsigned* Sl = smu + ASL;
    unsigned* Vh = smu + AVH;  unsigned* Vl = smu + AVL;
    float* coef_r = (float*)(smu + ACF);
    int*   rsel_r = (int*)(smu + ARR);
    int*   rsel_c = (int*)(smu + ARC);

    int h   = blockIdx.y;
    int l0  = (gridDim.x - 1 - blockIdx.x) * 64;   // heavy tiles first
    int tid = threadIdx.x, lane = tid & 31, warp = tid >> 5;
    int g = lane >> 2, t = lane & 3;
    int wm  = (warp >> 1) * 16;
    int wns = (warp & 1) * 32;
    int wno = (warp & 1) * 64;

    const __nv_bfloat16* Kh_g  = g_kh  + (size_t)h * LL * HDKK;
    const __nv_bfloat16* Kl_g  = g_kl  + (size_t)h * LL * HDKK;
    const __nv_bfloat16* Vth_g = g_vth + (size_t)h * HDVV * LL;
    const __nv_bfloat16* Vtl_g = g_vtl + (size_t)h * HDVV * LL;

#define LOAD_K(s, m0) do {                                                  \
        unsigned* kh_ = smu + AKB + (s) * AKSTG;                            \
        unsigned* kl_ = kh_ + 64*SU;                                        \
        _Pragma("unroll")                                                   \
        for (int i_ = 0; i_ < 2; i_++) {                                    \
            int idx_ = tid + i_ * 256, r_ = idx_ >> 3, j_ = idx_ & 7;       \
            cp16b(kh_ + r_*SU + j_*4, Kh_g + (size_t)((m0)+r_)*HDKK + j_*8);\
            cp16b(kl_ + r_*SU + j_*4, Kl_g + (size_t)((m0)+r_)*HDKK + j_*8);\
        }                                                                   \
        asm volatile("cp.async.commit_group;\n" ::);                        \
    } while (0)

#define LOAD_V(m0) do {                                                     \
        _Pragma("unroll")                                                   \
        for (int i_ = 0; i_ < 4; i_++) {                                    \
            int idx_ = tid + i_ * 256, r_ = idx_ >> 3, j_ = idx_ & 7;       \
            cp16b(Vh + r_*SU + j_*4, Vth_g + (size_t)r_*LL + (m0) + j_*8);  \
            cp16b(Vl + r_*SU + j_*4, Vtl_g + (size_t)r_*LL + (m0) + j_*8);  \
        }                                                                   \
        asm volatile("cp.async.commit_group;\n" ::);                        \
    } while (0)

    // prologue: K(0) in flight; Q fragments -> registers (reused all tiles)
    LOAD_K(0, 0);
    unsigned qh_r[4][4], ql_r[4][4];
    {
        const unsigned* Qg_h = (const unsigned*)g_qh + ((size_t)h * LL + l0) * 32;
        const unsigned* Qg_l = (const unsigned*)g_ql + ((size_t)h * LL + l0) * 32;
        int r0 = wm + g;
        #pragma unroll
        for (int kk = 0; kk < 4; kk++) {
            int w0 = kk * 8 + t, w1 = w0 + 4;
            qh_r[kk][0] = Qg_h[ r0      * 32 + w0];
            qh_r[kk][1] = Qg_h[(r0 + 8) * 32 + w0];
            qh_r[kk][2] = Qg_h[ r0      * 32 + w1];
            qh_r[kk][3] = Qg_h[(r0 + 8) * 32 + w1];
            ql_r[kk][0] = Qg_l[ r0      * 32 + w0];
            ql_r[kk][1] = Qg_l[(r0 + 8) * 32 + w0];
            ql_r[kk][2] = Qg_l[ r0      * 32 + w1];
            ql_r[kk][3] = Qg_l[(r0 + 8) * 32 + w1];
        }
    }
    if (tid < 64) {
        rsel_r[tid] = g_rsel[h * LL + l0 + tid];
        coef_r[tid] = g_coef[h * LL + l0 + tid];
    }

    float acc_o[8][4];
    #pragma unroll
    for (int fn = 0; fn < 8; fn++)
        #pragma unroll
        for (int r = 0; r < 4; r++) acc_o[fn][r] = 0.f;

    int ntiles = (l0 >> 6) + 1;
    for (int mt = 0; mt < ntiles; mt++) {
        int m0 = mt * 64;
        int s  = mt & 1;
        __syncthreads();                    // prev V/S reads done
        LOAD_V(m0);
        if (tid < 64) rsel_c[tid] = g_rsel[h * LL + m0 + tid];
        asm volatile("cp.async.wait_group 1;\n" ::);   // K(mt) done
        __syncthreads();

        const unsigned* Kts = smu + AKB + s * AKSTG;
        const unsigned* Kls = Kts + 64*SU;

        // ---- QK^T (bf16 3-term): warp tile 16x32, 4 k16 steps ----
        float acc_s[4][4];
        #pragma unroll
        for (int fn = 0; fn < 4; fn++)
            #pragma unroll
            for (int r = 0; r < 4; r++) acc_s[fn][r] = 0.f;

        #pragma unroll
        for (int kk = 0; kk < 4; kk++) {
            int p0 = kk * 8;
            #pragma unroll
            for (int fn = 0; fn < 4; fn++) {
                int c0 = wns + fn * 8 + g;
                unsigned bh0 = Kts[c0 * SU + p0 + t];
                unsigned bh1 = Kts[c0 * SU + p0 + t + 4];
                unsigned bl0 = Kls[c0 * SU + p0 + t];
                unsigned bl1 = Kls[c0 * SU + p0 + t + 4];
                mma16(acc_s[fn], qh_r[kk][0], qh_r[kk][1], qh_r[kk][2], qh_r[kk][3], bh0, bh1);
                mma16(acc_s[fn], qh_r[kk][0], qh_r[kk][1], qh_r[kk][2], qh_r[kk][3], bl0, bl1);
                mma16(acc_s[fn], ql_r[kk][0], ql_r[kk][1], ql_r[kk][2], ql_r[kk][3], bh0, bh1);
            }
        }

        // prefetch K(mt+1) — K(mt) reads are done
        if (mt + 1 < ntiles) LOAD_K(s ^ 1, m0 + 64);

        // ---- mask + coef, pack bf16 hi/lo pairs into S ----
        {
            int r0 = wm + g, r1 = r0 + 8;
            int gl0 = l0 + r0, gl1 = l0 + r1;
            int e0 = rsel_r[r0], e1 = rsel_r[r1];
            float cf0 = coef_r[r0], cf1 = coef_r[r1];
            #pragma unroll
            for (int fn = 0; fn < 4; fn++) {
                int c = wns + fn * 8 + 2 * t;
                int gm0 = m0 + c, gm1 = gm0 + 1;
                int ec0 = rsel_c[c], ec1 = rsel_c[c + 1];
                float s00 = (gm0 <= gl0 && ec0 == e0) ? acc_s[fn][0] * cf0 : 0.f;
                float s01 = (gm1 <= gl0 && ec1 == e0) ? acc_s[fn][1] * cf0 : 0.f;
                float s10 = (gm0 <= gl1 && ec0 == e1) ? acc_s[fn][2] * cf1 : 0.f;
                float s11 = (gm1 <= gl1 && ec1 == e1) ? acc_s[fn][3] * cf1 : 0.f;
                unsigned h00, l00, h01, l01, h10, l10, h11, l11;
                split_bf(s00, h00, l00); split_bf(s01, h01, l01);
                split_bf(s10, h10, l10); split_bf(s11, h11, l11);
                int pi = (wns >> 1) + fn * 4 + t;
                Sh[r0 * SU + pi] = h00 | (h01 << 16);
                Sl[r0 * SU + pi] = l00 | (l01 << 16);
                Sh[r1 * SU + pi] = h10 | (h11 << 16);
                Sl[r1 * SU + pi] = l10 | (l11 << 16);
            }
        }
        if (mt + 1 < ntiles)
            asm volatile("cp.async.wait_group 1;\n" ::);  // V(mt) done, K(mt+1) pending
        else
            asm volatile("cp.async.wait_group 0;\n" ::);  // last tile: V must be done
        __syncthreads();                                   // S + V visible

        // ---- O += S @ V (bf16 3-term): warp tile 16x64, 4 k16 steps ----
        #pragma unroll
        for (int kk = 0; kk < 4; kk++) {
            int p0 = kk * 8;
            int r0 = wm + g;
            unsigned ah0 = Sh[ r0      * SU + p0 + t];
            unsigned ah1 = Sh[(r0 + 8) * SU + p0 + t];
            unsigned ah2 = Sh[ r0      * SU + p0 + t + 4];
            unsigned ah3 = Sh[(r0 + 8) * SU + p0 + t + 4];
            unsigned al0 = Sl[ r0      * SU + p0 + t];
            unsigned al1 = Sl[(r0 + 8) * SU + p0 + t];
            unsigned al2 = Sl[ r0      * SU + p0 + t + 4];
            unsigned al3 = Sl[(r0 + 8) * SU + p0 + t + 4];
            #pragma unroll
            for (int fn = 0; fn < 8; fn++) {
                int c0 = wno + fn * 8 + g;
                unsigned bh0 = Vh[c0 * SU + p0 + t];
                unsigned bh1 = Vh[c0 * SU + p0 + t + 4];
                unsigned bl0 = Vl[c0 * SU + p0 + t];
                unsigned bl1 = Vl[c0 * SU + p0 + t + 4];
                mma16(acc_o[fn], ah0, ah1, ah2, ah3, bh0, bh1);
                mma16(acc_o[fn], ah0, ah1, ah2, ah3, bl0, bl1);
                mma16(acc_o[fn], al0, al1, al2, al3, bh0, bh1);
            }
        }
    }

    // ---- fused LayerNorm(128) * silu(gate) epilogue ----
    __syncthreads();                          // all smem reads done; reuse Sh region
    float* red_s = (float*)(smu + ASH);       // [128]: half*64 + row
    float* red_q = red_s + 128;               // [128]
    {
        int half = warp & 1;
        int r0 = wm + g, r1 = r0 + 8;
        float s0 = 0.f, q0 = 0.f, s1 = 0.f, q1 = 0.f;
        #pragma unroll
        for (int fn = 0; fn < 8; fn++) {
            float v0 = acc_o[fn][0], v1 = acc_o[fn][1];
            float v2 = acc_o[fn][2], v3 = acc_o[fn][3];
            s0 += v0 + v1;  q0 += v0*v0 + v1*v1;
            s1 += v2 + v3;  q1 += v2*v2 + v3*v3;
        }
        #pragma unroll
        for (int off = 1; off <= 2; off <<= 1) {
            s0 += __shfl_xor_sync(0xffffffffu, s0, off);
            q0 += __shfl_xor_sync(0xffffffffu, q0, off);
            s1 += __shfl_xor_sync(0xffffffffu, s1, off);
            q1 += __shfl_xor_sync(0xffffffffu, q1, off);
        }
        if (t == 0) {
            red_s[half*64 + r0] = s0;  red_q[half*64 + r0] = q0;
            red_s[half*64 + r1] = s1;  red_q[half*64 + r1] = q1;
        }
        __syncthreads();
        float S0 = red_s[r0] + red_s[64 + r0];
        float Q0 = red_q[r0] + red_q[64 + r0];
        float S1 = red_s[r1] + red_s[64 + r1];
        float Q1 = red_q[r1] + red_q[64 + r1];
        float mu0 = S0 * (1.f/128.f), mu1 = S1 * (1.f/128.f);
        float inv0 = rsqrtf(Q0 * (1.f/128.f) - mu0*mu0 + 1e-5f);
        float inv1 = rsqrtf(Q1 * (1.f/128.f) - mu1*mu1 + 1e-5f);
        size_t gbase0 = (size_t)(l0 + r0) * NCAT + 2*DKK + DVV + h * HDVV;
        size_t gbase1 = (size_t)(l0 + r1) * NCAT + 2*DKK + DVV + h * HDVV;
        size_t ybase0 = (size_t)(l0 + r0) * DVV + h * HDVV;
        size_t ybase1 = (size_t)(l0 + r1) * DVV + h * HDVV;
        #pragma unroll
        for (int fn = 0; fn < 8; fn++) {
            int c = wno + fn * 8 + 2 * t;
            float2 gt0 = *(const float2*)(g_qkvg + gbase0 + c);
            float2 gt1 = *(const float2*)(g_qkvg + gbase1 + c);
            float2 y0, y1;
            y0.x = tf32r(silu_f(gt0.x) * (acc_o[fn][0] - mu0) * inv0);
            y0.y = tf32r(silu_f(gt0.y) * (acc_o[fn][1] - mu0) * inv0);
            y1.x = tf32r(silu_f(gt1.x) * (acc_o[fn][2] - mu1) * inv1);
            y1.y = tf32r(silu_f(gt1.y) * (acc_o[fn][3] - mu1) * inv1);
            *(float2*)(g_y + ybase0 + c) = y0;
            *(float2*)(g_y + ybase1 + c) = y1;
        }
    }
}

// ---------------- launch ----------------------------------------------------
extern "C" void kernel_launch(void* const* d_in, const int* in_sizes, int n_in,
                              void* d_out, int out_size) {
    const float* x    = (const float*)d_in[0];
    const float* cw   = (const float*)d_in[1];
    const float* Wq   = (const float*)d_in[2];
    const float* Wk   = (const float*)d_in[3];
    const float* Wv   = (const float*)d_in[4];
    const float* Wg   = (const float*)d_in[5];
    const float* rw   = (const float*)d_in[6];
    const float* Wout = (const float*)d_in[7];
    float* out = (float*)d_out;

    float *p_xctf, *p_qkvg, *p_y;
    cudaGetSymbolAddress((void**)&p_xctf, g_xctf);
    cudaGetSymbolAddress((void**)&p_qkvg, g_qkvg);
    cudaGetSymbolAddress((void**)&p_y,    g_y);

    cudaFuncSetAttribute(attn_tc,
                         cudaFuncAttributeMaxDynamicSharedMemorySize, ATTN5_BYTES);
    cudaFuncSetAttribute(gemm_tc<true>,
                         cudaFuncAttributeMaxDynamicSharedMemorySize, SMEM_GEMM5);
    cudaFuncSetAttribute(gemm_tc<false>,
                         cudaFuncAttributeMaxDynamicSharedMemorySize, SMEM_GEMM5);

    conv_silu_kernel<<<(LL*DD)/256, 256>>>(x, cw);
    w2_kernel<<<DD/8, 256>>>(Wv, rw);
    rlog_kernel<<<LL/4, 256>>>();

    // fused QKVG projection: silu(q)+RoPE+split and v transpose+split are
    // performed inside the GEMM epilogue; only g block lands in qkvg.
    gemm_tc<true><<<dim3(NCAT/128, LL/128), 256, SMEM_GEMM5>>>(
        p_xctf, Wq, Wk, Wv, Wg, p_qkvg, NCAT, DD, DKK);

    router_kernel<<<HH, 256>>>();

    attn_tc<<<dim3(LL/64, HH), 256, ATTN5_BYTES>>>();

    gemm_tc<false><<<dim3(DD/128, LL/128), 256, SMEM_GEMM5>>>(
        p_y, Wout, Wout, Wout, Wout, out, DD, DVV, 0);
}